// round 3
// baseline (speedup 1.0000x reference)
#include <cuda_runtime.h>
#include <math.h>

// ---------------------------------------------------------------------------
// Problem constants
// ---------------------------------------------------------------------------
#define NB_GRAPHS 512          // B
#define M_NODES   64           // nodes per graph
#define EPG       512          // edges per graph

// ---------------------------------------------------------------------------
// Scratch layout (single __device__ array, no allocations)
// ---------------------------------------------------------------------------
#define SZ_F0 (32768*64)
#define SZ_F1 (32768*32)
#define SZ_F2 (32768*16)
#define SZ_H  (512*12288)
#define SZ_Y1 (512*256)

#define OFF_FQ0 0
#define OFF_FC0 (OFF_FQ0 + SZ_F0)
#define OFF_FQ1 (OFF_FC0 + SZ_F0)
#define OFF_FC1 (OFF_FQ1 + SZ_F1)
#define OFF_FQ2 (OFF_FC1 + SZ_F1)
#define OFF_FC2 (OFF_FQ2 + SZ_F2)
#define OFF_H   (OFF_FC2 + SZ_F2)
#define OFF_Y1  (OFF_H + SZ_H)
#define SCRATCH_TOTAL (OFF_Y1 + SZ_Y1)

__device__ float g_scratch[SCRATCH_TOTAL];

// ---------------------------------------------------------------------------
// GCN layer: one block per graph (1024 blocks = 512 q + 512 c).
// Does: h1 = (relu?)x @ W   (smem GEMM, W column cached in registers)
//       deg via smem atomics, dinv = rsqrt(deg)
//       out[d] += h1[s]*dinv[s]*dinv[d]  (smem atomics) + selfloop + bias
// Stores PRE-relu feats (reference appends feats before relu).
// ---------------------------------------------------------------------------
template<int FIN, int FOUT, bool RELU_IN, int OINQ, int OINC, int OOUTQ, int OOUTC>
__global__ void __launch_bounds__(256) gcn_layer(
    const float* __restrict__ xq_ext, const float* __restrict__ xc_ext,
    const float* __restrict__ W, const float* __restrict__ bias,
    const int* __restrict__ srcq, const int* __restrict__ dstq,
    const int* __restrict__ srcc, const int* __restrict__ dstc)
{
    extern __shared__ float sm[];
    float* sx   = sm;                       // 64*FIN
    float* sA   = sx + 64*FIN;              // 64*FOUT
    float* sout = sA + 64*FOUT;             // 64*FOUT
    float* sdeg = sout + 64*FOUT;           // 64 (deg, then dinv)

    const int g   = blockIdx.x;
    const bool isC = (g >= NB_GRAPHS);
    const int gg  = isC ? g - NB_GRAPHS : g;

    const float* x;
    if (isC) { if constexpr (OINC >= 0) x = g_scratch + OINC; else x = xc_ext; }
    else     { if constexpr (OINQ >= 0) x = g_scratch + OINQ; else x = xq_ext; }
    const int* src = isC ? srcc : srcq;
    const int* dst = isC ? dstc : dstq;
    float* out = g_scratch + (isC ? OOUTC : OOUTQ);

    const int nb = gg * M_NODES;
    const int eb = gg * EPG;
    const int t  = threadIdx.x;

    // load input features (apply relu from previous layer if needed)
    for (int i = t; i < 64*FIN; i += 256) {
        float v = x[(long)nb*FIN + i];
        sx[i] = RELU_IN ? fmaxf(v, 0.f) : v;
    }
    if (t < 64) sdeg[t] = 1.0f;   // self loop
    __syncthreads();

    // degree accumulation (overlapped with GEMM below; resolved at next barrier)
    for (int e = t; e < EPG; e += 256) {
        int d = dst[eb + e] - nb;
        atomicAdd(&sdeg[d], 1.0f);
    }

    // GEMM: sA[n][j] = sum_k sx[n][k] * W[k][j]; j fixed per thread
    {
        const int j = t % FOUT;
        float wcol[FIN];
        #pragma unroll
        for (int k = 0; k < FIN; ++k) wcol[k] = __ldg(&W[k*FOUT + j]);
        for (int i = t; i < 64*FOUT; i += 256) {
            int n = i / FOUT;
            float acc = 0.f;
            #pragma unroll
            for (int k = 0; k < FIN; ++k) acc += sx[n*FIN + k] * wcol[k];
            sA[i] = acc;
        }
    }
    __syncthreads();

    if (t < 64) sdeg[t] = rsqrtf(sdeg[t]);   // now sdeg holds dinv
    __syncthreads();

    // self loop + bias
    for (int i = t; i < 64*FOUT; i += 256) {
        int n = i / FOUT, j = i - n*FOUT;
        float di = sdeg[n];
        sout[i] = sA[i]*di*di + __ldg(&bias[j]);
    }
    __syncthreads();

    // edge scatter with symmetric normalization
    {
        const int lane = t & 31, wp = t >> 5;
        for (int e = wp; e < EPG; e += 8) {
            int s = src[eb + e] - nb;
            int d = dst[eb + e] - nb;
            float nrm = sdeg[s] * sdeg[d];
            for (int j = lane; j < FOUT; j += 32)
                atomicAdd(&sout[d*FOUT + j], sA[s*FOUT + j] * nrm);
        }
    }
    __syncthreads();

    for (int i = t; i < 64*FOUT; i += 256)
        out[(long)nb*FOUT + i] = sout[i];
}

// ---------------------------------------------------------------------------
// Fused pair kernel: per (sim index i [fixed per launch], graph pair b):
//   sim = qf @ cf^T (64x64)  -> conv0(1->8,5x5)+relu+pool -> 8x32x32
//   -> conv1(8->16,5x5)+relu+pool -> 16x16x16 -> write into MLP input layout
// SMEM: sA (32KB): qf + swizzled cf^T, later reused for pooled conv0 output
//       sB (16KB): sim matrix, later reused for conv1 weights
// ---------------------------------------------------------------------------
template<int F, int OQ, int OC>
__global__ void __launch_bounds__(256, 2) pair_kernel(
    const float* __restrict__ cw0, const float* __restrict__ cb0,
    const float* __restrict__ cw1, const float* __restrict__ cb1,
    int h_col_off)
{
    __shared__ float sA[8192];   // 32 KB
    __shared__ float sB[4096];   // 16 KB

    const int bk = blockIdx.x;
    const int t  = threadIdx.x;
    const float* fq = g_scratch + OQ + (long)bk * 64 * F;
    const float* fc = g_scratch + OC + (long)bk * 64 * F;

    float* sq  = sA;          // [64][F]
    float* scT = sA + 4096;   // [F][64] xor-swizzled

    for (int i = t; i < 64*F; i += 256) sq[i] = fq[i];
    for (int i = t; i < 64*F; i += 256) {
        int n = i / F, k = i - n*F;
        scT[k*64 + (n ^ (k & 31))] = fc[i];
    }
    __syncthreads();

    // ---- similarity GEMM: 4x4 register tile per thread -> sB[m][n] ----
    {
        const int m0 = (t >> 4) << 2;
        const int n0 = (t & 15) << 2;
        float acc[4][4] = {};
        #pragma unroll
        for (int k = 0; k < F; ++k) {
            float a[4], b[4];
            #pragma unroll
            for (int u = 0; u < 4; ++u) a[u] = sq[(m0+u)*F + k];
            #pragma unroll
            for (int v = 0; v < 4; ++v) b[v] = scT[k*64 + ((n0+v) ^ (k & 31))];
            #pragma unroll
            for (int u = 0; u < 4; ++u)
                #pragma unroll
                for (int v = 0; v < 4; ++v)
                    acc[u][v] += a[u] * b[v];
        }
        #pragma unroll
        for (int u = 0; u < 4; ++u)
            #pragma unroll
            for (int v = 0; v < 4; ++v)
                sB[(m0+u)*64 + (n0+v)] = acc[u][v];
    }
    __syncthreads();   // sim done; sq/scT dead -> sA reusable for p0

    // ---- conv0 (1->8, 5x5, same) + relu + 2x2 maxpool -> sA[o][32][32] ----
    {
        const int ty = t >> 4, tx = t & 15;       // 4x4 conv tile -> 2x2 pooled
        const int y0 = 4*ty - 2, x0 = 4*tx - 2;
        float p[8][8];
        #pragma unroll
        for (int dy = 0; dy < 8; ++dy) {
            int yy = y0 + dy;
            #pragma unroll
            for (int dx = 0; dx < 8; ++dx) {
                int xx = x0 + dx;
                p[dy][dx] = (yy >= 0 && yy < 64 && xx >= 0 && xx < 64)
                            ? sB[yy*64 + xx] : 0.f;
            }
        }
        for (int o = 0; o < 8; ++o) {
            float b0 = __ldg(&cb0[o]);
            float acc[4][4];
            #pragma unroll
            for (int u = 0; u < 4; ++u)
                #pragma unroll
                for (int v = 0; v < 4; ++v) acc[u][v] = b0;
            #pragma unroll
            for (int ky = 0; ky < 5; ++ky)
                #pragma unroll
                for (int kx = 0; kx < 5; ++kx) {
                    float w = __ldg(&cw0[o*25 + ky*5 + kx]);
                    #pragma unroll
                    for (int u = 0; u < 4; ++u)
                        #pragma unroll
                        for (int v = 0; v < 4; ++v)
                            acc[u][v] += p[u+ky][v+kx] * w;
                }
            #pragma unroll
            for (int a = 0; a < 2; ++a)
                #pragma unroll
                for (int b = 0; b < 2; ++b) {
                    float m = fmaxf(fmaxf(acc[2*a][2*b],   acc[2*a][2*b+1]),
                                    fmaxf(acc[2*a+1][2*b], acc[2*a+1][2*b+1]));
                    sA[o*1024 + (2*ty + a)*32 + (2*tx + b)] = fmaxf(m, 0.f);
                }
        }
    }
    __syncthreads();   // all conv0 reads of sB done -> sB reusable for weights

    // load conv1 weights (16*8*25 = 3200 floats) into sB
    for (int i = t; i < 16*8*25; i += 256) sB[i] = cw1[i];
    __syncthreads();

    // ---- conv1 (8->16, 5x5, same) + relu + pool -> global h ----
    {
        float* hout = g_scratch + OFF_H + h_col_off + (long)bk * 12288;
        for (int it = 0; it < 4; ++it) {
            int item = it*256 + t;
            int o    = item >> 6;          // 0..15 (uniform per warp)
            int tile = item & 63;
            int ty = tile >> 3, tx = tile & 7;
            int y0 = 4*ty - 2, x0 = 4*tx - 2;

            float b1 = __ldg(&cb1[o]);
            float acc[4][4];
            #pragma unroll
            for (int u = 0; u < 4; ++u)
                #pragma unroll
                for (int v = 0; v < 4; ++v) acc[u][v] = b1;

            for (int c = 0; c < 8; ++c) {
                float p[8][8];
                #pragma unroll
                for (int dy = 0; dy < 8; ++dy) {
                    int yy = y0 + dy;
                    #pragma unroll
                    for (int dx = 0; dx < 8; ++dx) {
                        int xx = x0 + dx;
                        p[dy][dx] = (yy >= 0 && yy < 32 && xx >= 0 && xx < 32)
                                    ? sA[c*1024 + yy*32 + xx] : 0.f;
                    }
                }
                const float* wc = &sB[(o*8 + c) * 25];
                #pragma unroll
                for (int ky = 0; ky < 5; ++ky)
                    #pragma unroll
                    for (int kx = 0; kx < 5; ++kx) {
                        float w = wc[ky*5 + kx];
                        #pragma unroll
                        for (int u = 0; u < 4; ++u)
                            #pragma unroll
                            for (int v = 0; v < 4; ++v)
                                acc[u][v] += p[u+ky][v+kx] * w;
                    }
            }
            #pragma unroll
            for (int a = 0; a < 2; ++a)
                #pragma unroll
                for (int b = 0; b < 2; ++b) {
                    float m = fmaxf(fmaxf(acc[2*a][2*b],   acc[2*a][2*b+1]),
                                    fmaxf(acc[2*a+1][2*b], acc[2*a+1][2*b+1]));
                    hout[(o*16 + 2*ty + a)*16 + (2*tx + b)] = fmaxf(m, 0.f);
                }
        }
    }
}

// ---------------------------------------------------------------------------
// MLP layer 0: y1 = h @ Wl0 (+ bl0 via init kernel). Split-K GEMM + atomics.
// ---------------------------------------------------------------------------
__global__ void init_y1(const float* __restrict__ bl0)
{
    int i = blockIdx.x * 256 + threadIdx.x;
    if (i < 512*256) g_scratch[OFF_Y1 + i] = __ldg(&bl0[i & 255]);
}

#define KSPLIT 8
#define KCH (12288 / KSPLIT)

__global__ void __launch_bounds__(256) gemm1_kernel(const float* __restrict__ Bw)
{
    const float* A = g_scratch + OFF_H;
    float* C = g_scratch + OFF_Y1;

    const int r0 = blockIdx.x * 64;
    const int c0 = blockIdx.y * 64;
    const int k0 = blockIdx.z * KCH;

    __shared__ float As[64*16];
    __shared__ float Bs[16*64];

    const int t  = threadIdx.x;
    const int tr = t >> 4, tc = t & 15;
    float acc[4][4] = {};

    for (int kt = 0; kt < KCH; kt += 16) {
        #pragma unroll
        for (int j = 0; j < 4; ++j) {
            int i = t + j*256;
            int r = i >> 4, kk = i & 15;
            As[i] = A[(long)(r0 + r)*12288 + k0 + kt + kk];
            int kk2 = i >> 6, c = i & 63;
            Bs[i] = Bw[(long)(k0 + kt + kk2)*256 + c0 + c];
        }
        __syncthreads();
        #pragma unroll
        for (int kk = 0; kk < 16; ++kk) {
            float a[4];
            #pragma unroll
            for (int u = 0; u < 4; ++u) a[u] = As[(tr*4 + u)*16 + kk];
            float4 b4 = *(const float4*)&Bs[kk*64 + tc*4];
            float b[4] = {b4.x, b4.y, b4.z, b4.w};
            #pragma unroll
            for (int u = 0; u < 4; ++u)
                #pragma unroll
                for (int v = 0; v < 4; ++v)
                    acc[u][v] += a[u] * b[v];
        }
        __syncthreads();
    }
    #pragma unroll
    for (int u = 0; u < 4; ++u)
        #pragma unroll
        for (int v = 0; v < 4; ++v)
            atomicAdd(&C[(r0 + tr*4 + u)*256 + c0 + tc*4 + v], acc[u][v]);
}

// ---------------------------------------------------------------------------
// Head: relu(y1) @ Wl1 + bl1 -> relu -> @ Wsc + bsc -> sigmoid. One block/row.
// ---------------------------------------------------------------------------
__global__ void head_kernel(const float* __restrict__ Wl1, const float* __restrict__ bl1,
                            const float* __restrict__ Wsc, const float* __restrict__ bsc,
                            float* __restrict__ out)
{
    const int r = blockIdx.x;
    const int j = threadIdx.x;   // 64 threads
    __shared__ float sy[256];
    __shared__ float red[2];

    const float* y1 = g_scratch + OFF_Y1 + (long)r * 256;
    for (int k = j; k < 256; k += 64) sy[k] = fmaxf(y1[k], 0.f);
    __syncthreads();

    float acc = __ldg(&bl1[j]);
    #pragma unroll 8
    for (int k = 0; k < 256; ++k) acc += sy[k] * __ldg(&Wl1[k*64 + j]);

    float v = fmaxf(acc, 0.f) * __ldg(&Wsc[j]);
    #pragma unroll
    for (int off = 16; off > 0; off >>= 1)
        v += __shfl_down_sync(0xffffffffu, v, off);
    if ((j & 31) == 0) red[j >> 5] = v;
    __syncthreads();
    if (j == 0) {
        float s = red[0] + red[1] + __ldg(&bsc[0]);
        out[r] = 1.f / (1.f + expf(-s));
    }
}

// ---------------------------------------------------------------------------
// Launch
// ---------------------------------------------------------------------------
extern "C" void kernel_launch(void* const* d_in, const int* in_sizes, int n_in,
                              void* d_out, int out_size)
{
    (void)in_sizes; (void)n_in; (void)out_size;
    const float* x_q  = (const float*)d_in[0];
    const float* x_c  = (const float*)d_in[1];
    const int*   src_q = (const int*)d_in[2];
    const int*   dst_q = (const int*)d_in[3];
    const int*   src_c = (const int*)d_in[4];
    const int*   dst_c = (const int*)d_in[5];
    const float* Wg0 = (const float*)d_in[6];
    const float* bg0 = (const float*)d_in[7];
    const float* Wg1 = (const float*)d_in[8];
    const float* bg1 = (const float*)d_in[9];
    const float* Wg2 = (const float*)d_in[10];
    const float* bg2 = (const float*)d_in[11];
    const float* cw0 = (const float*)d_in[12];
    const float* cb0 = (const float*)d_in[13];
    const float* cw1 = (const float*)d_in[14];
    const float* cb1 = (const float*)d_in[15];
    const float* Wl0 = (const float*)d_in[16];
    const float* bl0 = (const float*)d_in[17];
    const float* Wl1 = (const float*)d_in[18];
    const float* bl1 = (const float*)d_in[19];
    const float* Wsc = (const float*)d_in[20];
    const float* bsc = (const float*)d_in[21];
    float* out = (float*)d_out;

    // GCN layers (q + c in one grid)
    size_t sm0 = (size_t)(64*32 + 2*64*64 + 64) * sizeof(float);
    gcn_layer<32,64,false,-1,-1,OFF_FQ0,OFF_FC0>
        <<<2*NB_GRAPHS, 256, sm0>>>(x_q, x_c, Wg0, bg0, src_q, dst_q, src_c, dst_c);
    size_t sm1 = (size_t)(64*64 + 2*64*32 + 64) * sizeof(float);
    gcn_layer<64,32,true,OFF_FQ0,OFF_FC0,OFF_FQ1,OFF_FC1>
        <<<2*NB_GRAPHS, 256, sm1>>>(nullptr, nullptr, Wg1, bg1, src_q, dst_q, src_c, dst_c);
    size_t sm2 = (size_t)(64*32 + 2*64*16 + 64) * sizeof(float);
    gcn_layer<32,16,true,OFF_FQ1,OFF_FC1,OFF_FQ2,OFF_FC2>
        <<<2*NB_GRAPHS, 256, sm2>>>(nullptr, nullptr, Wg2, bg2, src_q, dst_q, src_c, dst_c);

    // Fused sim + conv stacks (one launch per sim index)
    pair_kernel<64,OFF_FQ0,OFF_FC0><<<NB_GRAPHS, 256>>>(cw0,       cb0,      cw1,        cb1,       0);
    pair_kernel<32,OFF_FQ1,OFF_FC1><<<NB_GRAPHS, 256>>>(cw0 + 200, cb0 + 8,  cw1 + 3200, cb1 + 16,  4096);
    pair_kernel<16,OFF_FQ2,OFF_FC2><<<NB_GRAPHS, 256>>>(cw0 + 400, cb0 + 16, cw1 + 6400, cb1 + 32,  8192);

    // MLP
    init_y1<<<512, 256>>>(bl0);
    gemm1_kernel<<<dim3(8, 4, KSPLIT), 256>>>(Wl0);
    head_kernel<<<512, 64>>>(Wl1, bl1, Wsc, bsc, out);
}

// round 4
// speedup vs baseline: 1.3821x; 1.3821x over previous
#include <cuda_runtime.h>
#include <math.h>

// ---------------------------------------------------------------------------
// Problem constants
// ---------------------------------------------------------------------------
#define NB_GRAPHS 512          // B
#define M_NODES   64           // nodes per graph
#define EPG       512          // edges per graph

// ---------------------------------------------------------------------------
// Scratch layout (single __device__ array, no allocations)
// ---------------------------------------------------------------------------
#define SZ_F0 (32768*64)
#define SZ_F1 (32768*32)
#define SZ_F2 (32768*16)
#define SZ_H  (512*12288)
#define SZ_Y1 (512*256)

#define OFF_FQ0 0
#define OFF_FC0 (OFF_FQ0 + SZ_F0)
#define OFF_FQ1 (OFF_FC0 + SZ_F0)
#define OFF_FC1 (OFF_FQ1 + SZ_F1)
#define OFF_FQ2 (OFF_FC1 + SZ_F1)
#define OFF_FC2 (OFF_FQ2 + SZ_F2)
#define OFF_H   (OFF_FC2 + SZ_F2)
#define OFF_Y1  (OFF_H + SZ_H)
#define SCRATCH_TOTAL (OFF_Y1 + SZ_Y1)

__device__ float g_scratch[SCRATCH_TOTAL];

// ---------------------------------------------------------------------------
// Packed fp32x2 helpers (Blackwell dual-FP32 path; ptxas never emits FFMA2
// from scalar C++ — only via PTX fma.rn.f32x2)
// ---------------------------------------------------------------------------
typedef unsigned long long u64;

__device__ __forceinline__ u64 pack2(float lo, float hi) {
    u64 r; asm("mov.b64 %0, {%1,%2};" : "=l"(r) : "f"(lo), "f"(hi)); return r;
}
__device__ __forceinline__ u64 fma2(u64 a, u64 b, u64 c) {
    u64 d; asm("fma.rn.f32x2 %0, %1, %2, %3;" : "=l"(d) : "l"(a), "l"(b), "l"(c));
    return d;
}
__device__ __forceinline__ float2 unpack2(u64 v) {
    float lo, hi; asm("mov.b64 {%0,%1}, %2;" : "=f"(lo), "=f"(hi) : "l"(v));
    return make_float2(lo, hi);
}

// ---------------------------------------------------------------------------
// Fused 3-layer GCN: one block per graph (1024 blocks = 512 q + 512 c).
// Edges/degrees/norms computed once, all layers run out of a shared-mem pool.
// Stores PRE-relu feats of each layer to g_scratch.
// ---------------------------------------------------------------------------
template<int FIN, int FOUT>
__device__ __forceinline__ void gcn_layer_body(
    const float* __restrict__ sx, float* __restrict__ sA, float* __restrict__ sout,
    const float* __restrict__ sdinv,
    const int* __restrict__ ses, const int* __restrict__ sed,
    const float* __restrict__ sen,
    const float* __restrict__ W, const float* __restrict__ bias,
    float* __restrict__ outg, int t)
{
    // GEMM: sA[n][j] = sum_k sx[n][k] * W[k][j]
    {
        const int j = t % FOUT;
        float wcol[FIN];
        #pragma unroll
        for (int k = 0; k < FIN; ++k) wcol[k] = __ldg(&W[k*FOUT + j]);
        for (int i = t; i < 64*FOUT; i += 256) {
            int n = i / FOUT;
            float acc = 0.f;
            #pragma unroll
            for (int k = 0; k < FIN; ++k) acc += sx[n*FIN + k] * wcol[k];
            sA[i] = acc;
        }
    }
    __syncthreads();

    // self loop + bias
    for (int i = t; i < 64*FOUT; i += 256) {
        int n = i / FOUT, j = i - n*FOUT;
        float di = sdinv[n];
        sout[i] = sA[i]*di*di + __ldg(&bias[j]);
    }
    __syncthreads();

    // edge scatter with symmetric normalization
    {
        const int lane = t & 31, wp = t >> 5;
        for (int e = wp; e < EPG; e += 8) {
            int s = ses[e], d = sed[e];
            float nrm = sen[e];
            #pragma unroll
            for (int j = lane; j < FOUT; j += 32)
                atomicAdd(&sout[d*FOUT + j], sA[s*FOUT + j] * nrm);
        }
    }
    __syncthreads();

    for (int i = t; i < 64*FOUT; i += 256)
        outg[i] = sout[i];
}

__global__ void __launch_bounds__(256) gcn_all(
    const float* __restrict__ xq, const float* __restrict__ xc,
    const float* __restrict__ Wg0, const float* __restrict__ bg0,
    const float* __restrict__ Wg1, const float* __restrict__ bg1,
    const float* __restrict__ Wg2, const float* __restrict__ bg2,
    const int* __restrict__ srcq, const int* __restrict__ dstq,
    const int* __restrict__ srcc, const int* __restrict__ dstc)
{
    __shared__ float pool[10240];
    __shared__ int   ses[EPG], sed[EPG];
    __shared__ float sen[EPG];
    __shared__ float sdinv[64];

    const int g   = blockIdx.x;
    const bool isC = (g >= NB_GRAPHS);
    const int gg  = isC ? g - NB_GRAPHS : g;
    const float* x = isC ? xc : xq;
    const int* src = isC ? srcc : srcq;
    const int* dst = isC ? dstc : dstq;

    const int nb = gg * M_NODES;
    const int eb = gg * EPG;
    const int t  = threadIdx.x;

    if (t < 64) sdinv[t] = 1.0f;   // self loop
    __syncthreads();

    for (int e = t; e < EPG; e += 256) {
        int s = src[eb + e] - nb;
        int d = dst[eb + e] - nb;
        ses[e] = s; sed[e] = d;
        atomicAdd(&sdinv[d], 1.0f);
    }
    // load layer-0 input features into pool[0:2048]
    for (int i = t; i < 64*32; i += 256) pool[i] = x[(long)nb*32 + i];
    __syncthreads();

    if (t < 64) sdinv[t] = rsqrtf(sdinv[t]);
    __syncthreads();

    for (int e = t; e < EPG; e += 256) sen[e] = sdinv[ses[e]] * sdinv[sed[e]];
    __syncthreads();

    // Layer 0: 32 -> 64   sx=pool[0:2048] sA=pool[2048:6144] sout=pool[6144:10240]
    gcn_layer_body<32,64>(pool, pool+2048, pool+6144, sdinv, ses, sed, sen,
                          Wg0, bg0, g_scratch + (isC?OFF_FC0:OFF_FQ0) + (long)nb*64, t);
    for (int i = t; i < 64*64; i += 256) pool[i] = fmaxf(pool[6144 + i], 0.f);
    __syncthreads();

    // Layer 1: 64 -> 32   sx=pool[0:4096] sA=pool[4096:6144] sout=pool[6144:8192]
    gcn_layer_body<64,32>(pool, pool+4096, pool+6144, sdinv, ses, sed, sen,
                          Wg1, bg1, g_scratch + (isC?OFF_FC1:OFF_FQ1) + (long)nb*32, t);
    for (int i = t; i < 64*32; i += 256) pool[i] = fmaxf(pool[6144 + i], 0.f);
    __syncthreads();

    // Layer 2: 32 -> 16   sx=pool[0:2048] sA=pool[2048:3072] sout=pool[3072:4096]
    gcn_layer_body<32,16>(pool, pool+2048, pool+3072, sdinv, ses, sed, sen,
                          Wg2, bg2, g_scratch + (isC?OFF_FC2:OFF_FQ2) + (long)nb*16, t);
}

// ---------------------------------------------------------------------------
// Row-streaming 5x5 conv contribution of one input channel into packed
// accumulators (4 rows x 2 column-pairs). Input rows loaded as float2 pairs
// (x0 is even; pairs never straddle the [0,Wd) boundary), overlapping pairs
// built with mov.b64 packs (ALU pipe), MACs on fma.rn.f32x2.
// ---------------------------------------------------------------------------
template<int Wd>
__device__ __forceinline__ void conv5x5_rowstream(
    const float* __restrict__ plane, const u64* __restrict__ wq,
    u64 accp[4][2], int y0, int x0)
{
    #pragma unroll
    for (int dy = 0; dy < 8; ++dy) {
        const int yy = y0 + dy;
        const bool rowok = ((unsigned)yy < (unsigned)Wd);
        float r[8];
        #pragma unroll
        for (int j = 0; j < 4; ++j) {
            int xx = x0 + 2*j;
            float2 v = make_float2(0.f, 0.f);
            if (rowok && (unsigned)xx < (unsigned)Wd)
                v = *(const float2*)(plane + yy*Wd + xx);
            r[2*j] = v.x; r[2*j+1] = v.y;
        }
        u64 q[7];
        #pragma unroll
        for (int j = 0; j < 7; ++j) q[j] = pack2(r[j], r[j+1]);
        #pragma unroll
        for (int u = 0; u < 4; ++u) {
            const int ky = dy - u;
            if (ky >= 0 && ky < 5) {
                #pragma unroll
                for (int kx = 0; kx < 5; ++kx) {
                    u64 w = wq[ky*5 + kx];
                    accp[u][0] = fma2(q[kx],     w, accp[u][0]);
                    accp[u][1] = fma2(q[kx + 2], w, accp[u][1]);
                }
            }
        }
    }
}

__device__ __forceinline__ void pool_store(const u64 accp[4][2], float* dst, int stride)
{
    #pragma unroll
    for (int a = 0; a < 2; ++a)
        #pragma unroll
        for (int b = 0; b < 2; ++b) {
            float2 p0 = unpack2(accp[2*a][b]);
            float2 p1 = unpack2(accp[2*a+1][b]);
            float m = fmaxf(fmaxf(p0.x, p0.y), fmaxf(p1.x, p1.y));
            dst[a*stride + b] = fmaxf(m, 0.f);
        }
}

// ---------------------------------------------------------------------------
// Fused pair kernel, all 3 sims in one launch (grid = 1536, sim interleaved):
//   sim = qf @ cf^T (64x64) -> conv0(1->8)+relu+pool -> conv1(8->16)+relu+pool
//   -> write into MLP input layout.
// ---------------------------------------------------------------------------
__global__ void __launch_bounds__(256, 2) pair_all(
    const float* __restrict__ cw0, const float* __restrict__ cb0,
    const float* __restrict__ cw1, const float* __restrict__ cb1)
{
    __shared__ float sA[8192];   // 32 KB
    __shared__ float sB[4096];   // 16 KB

    const int sim = blockIdx.x % 3;
    const int bk  = blockIdx.x / 3;
    const int lf  = 6 - sim;                 // log2(F)
    const int F   = 1 << lf;                 // 64, 32, 16
    const int offq = (sim == 0) ? OFF_FQ0 : (sim == 1) ? OFF_FQ1 : OFF_FQ2;
    const int offc = (sim == 0) ? OFF_FC0 : (sim == 1) ? OFF_FC1 : OFF_FC2;
    const float* cw0p = cw0 + sim*200;
    const float* cb0p = cb0 + sim*8;
    const float* cw1p = cw1 + sim*3200;
    const float* cb1p = cb1 + sim*16;

    const int t = threadIdx.x;
    const float* fq = g_scratch + offq + ((long)bk << (6 + lf));
    const float* fc = g_scratch + offc + ((long)bk << (6 + lf));

    float* sq  = sA;          // [64][F]
    float* scT = sA + 4096;   // [F][64] xor-swizzled

    for (int i = t; i < (64 << lf); i += 256) sq[i] = fq[i];
    for (int i = t; i < (64 << lf); i += 256) {
        int n = i >> lf, k = i & (F - 1);
        scT[k*64 + (n ^ (k & 31))] = fc[i];
    }
    __syncthreads();

    // ---- similarity GEMM: 4x4 register tile per thread -> sB[m][n] ----
    {
        const int m0 = (t >> 4) << 2;
        const int n0 = (t & 15) << 2;
        float acc[4][4] = {};
        #pragma unroll 16
        for (int k = 0; k < F; ++k) {
            float a[4], b[4];
            #pragma unroll
            for (int u = 0; u < 4; ++u) a[u] = sq[((m0+u) << lf) + k];
            #pragma unroll
            for (int v = 0; v < 4; ++v) b[v] = scT[k*64 + ((n0+v) ^ (k & 31))];
            #pragma unroll
            for (int u = 0; u < 4; ++u)
                #pragma unroll
                for (int v = 0; v < 4; ++v)
                    acc[u][v] += a[u] * b[v];
        }
        #pragma unroll
        for (int u = 0; u < 4; ++u)
            #pragma unroll
            for (int v = 0; v < 4; ++v)
                sB[(m0+u)*64 + (n0+v)] = acc[u][v];
    }
    __syncthreads();   // sim done; sA reusable for pooled conv0 output

    // ---- conv0 (1->8, 5x5, same) + relu + 2x2 maxpool -> sA[o][32][32] ----
    {
        const int ty = t >> 4, tx = t & 15;
        const int y0 = 4*ty - 2, x0 = 4*tx - 2;
        for (int o = 0; o < 8; ++o) {
            u64 wq[25];
            #pragma unroll
            for (int i = 0; i < 25; ++i) {
                float w = __ldg(&cw0p[o*25 + i]);
                wq[i] = pack2(w, w);
            }
            float b0 = __ldg(&cb0p[o]);
            u64 accp[4][2];
            #pragma unroll
            for (int u = 0; u < 4; ++u) { accp[u][0] = pack2(b0,b0); accp[u][1] = pack2(b0,b0); }
            conv5x5_rowstream<64>(sB, wq, accp, y0, x0);
            pool_store(accp, &sA[o*1024 + (2*ty)*32 + 2*tx], 32);
        }
    }
    __syncthreads();   // conv0 reads of sB done -> sB reusable for weights

    // load conv1 weights (16*8*25 = 3200 floats) into sB
    for (int i = t; i < 16*8*25; i += 256) sB[i] = cw1p[i];
    __syncthreads();

    // ---- conv1 (8->16, 5x5, same) + relu + pool -> global h ----
    {
        float* hout = g_scratch + OFF_H + sim*4096 + (long)bk * 12288;
        #pragma unroll
        for (int it = 0; it < 4; ++it) {
            const int item = it*256 + t;
            const int o    = item >> 6;          // 0..15 (uniform per warp)
            const int tile = item & 63;
            const int ty = tile >> 3, tx = tile & 7;
            const int y0 = 4*ty - 2, x0 = 4*tx - 2;

            float b1 = __ldg(&cb1p[o]);
            u64 accp[4][2];
            #pragma unroll
            for (int u = 0; u < 4; ++u) { accp[u][0] = pack2(b1,b1); accp[u][1] = pack2(b1,b1); }

            for (int c = 0; c < 8; ++c) {
                u64 wq[25];
                const float* ws = &sB[(o*8 + c) * 25];
                #pragma unroll
                for (int i = 0; i < 25; ++i) { float w = ws[i]; wq[i] = pack2(w, w); }
                conv5x5_rowstream<32>(&sA[c*1024], wq, accp, y0, x0);
            }
            pool_store(accp, &hout[(o*16 + 2*ty)*16 + 2*tx], 16);
        }
    }
}

// ---------------------------------------------------------------------------
// MLP layer 0: y1 = h @ Wl0 (+ bl0 via init kernel). Split-K GEMM + atomics.
// A tile stored k-major for float4 fragment loads; MACs on fma.rn.f32x2.
// ---------------------------------------------------------------------------
__global__ void init_y1(const float* __restrict__ bl0)
{
    int i = blockIdx.x * 256 + threadIdx.x;
    if (i < 512*256) g_scratch[OFF_Y1 + i] = __ldg(&bl0[i & 255]);
}

#define KSPLIT 8
#define KCH (12288 / KSPLIT)
#define ASTRIDE 68   // padded k-major row stride (16B-aligned, 2-way bank max)

__global__ void __launch_bounds__(256) gemm1_kernel(const float* __restrict__ Bw)
{
    const float* A = g_scratch + OFF_H;
    float* C = g_scratch + OFF_Y1;

    const int r0 = blockIdx.x * 64;
    const int c0 = blockIdx.y * 64;
    const int k0 = blockIdx.z * KCH;

    __shared__ float As[16 * ASTRIDE];   // [kk][r]
    __shared__ float Bs[16 * 64];        // [kk][c]

    const int t  = threadIdx.x;
    const int tr = t >> 4, tc = t & 15;
    u64 accp[4][2] = {};

    for (int kt = 0; kt < KCH; kt += 16) {
        #pragma unroll
        for (int j = 0; j < 4; ++j) {
            int i = t + j*256;
            int r = i >> 4, kk = i & 15;
            As[kk*ASTRIDE + r] = A[(long)(r0 + r)*12288 + k0 + kt + kk];
            int kk2 = i >> 6, c = i & 63;
            Bs[kk2*64 + c] = Bw[(long)(k0 + kt + kk2)*256 + c0 + c];
        }
        __syncthreads();
        #pragma unroll
        for (int kk = 0; kk < 16; ++kk) {
            float4 a4 = *(const float4*)&As[kk*ASTRIDE + tr*4];
            float4 b4 = *(const float4*)&Bs[kk*64 + tc*4];
            u64 bp0 = pack2(b4.x, b4.y);
            u64 bp1 = pack2(b4.z, b4.w);
            u64 ap[4] = { pack2(a4.x,a4.x), pack2(a4.y,a4.y),
                          pack2(a4.z,a4.z), pack2(a4.w,a4.w) };
            #pragma unroll
            for (int u = 0; u < 4; ++u) {
                accp[u][0] = fma2(bp0, ap[u], accp[u][0]);
                accp[u][1] = fma2(bp1, ap[u], accp[u][1]);
            }
        }
        __syncthreads();
    }
    #pragma unroll
    for (int u = 0; u < 4; ++u)
        #pragma unroll
        for (int vp = 0; vp < 2; ++vp) {
            float2 v = unpack2(accp[u][vp]);
            atomicAdd(&C[(r0 + tr*4 + u)*256 + c0 + tc*4 + 2*vp],     v.x);
            atomicAdd(&C[(r0 + tr*4 + u)*256 + c0 + tc*4 + 2*vp + 1], v.y);
        }
}

// ---------------------------------------------------------------------------
// Head: relu(y1) @ Wl1 + bl1 -> relu -> @ Wsc + bsc -> sigmoid. One block/row.
// ---------------------------------------------------------------------------
__global__ void head_kernel(const float* __restrict__ Wl1, const float* __restrict__ bl1,
                            const float* __restrict__ Wsc, const float* __restrict__ bsc,
                            float* __restrict__ out)
{
    const int r = blockIdx.x;
    const int j = threadIdx.x;   // 64 threads
    __shared__ float sy[256];
    __shared__ float red[2];

    const float* y1 = g_scratch + OFF_Y1 + (long)r * 256;
    for (int k = j; k < 256; k += 64) sy[k] = fmaxf(y1[k], 0.f);
    __syncthreads();

    float acc = __ldg(&bl1[j]);
    #pragma unroll 8
    for (int k = 0; k < 256; ++k) acc += sy[k] * __ldg(&Wl1[k*64 + j]);

    float v = fmaxf(acc, 0.f) * __ldg(&Wsc[j]);
    #pragma unroll
    for (int off = 16; off > 0; off >>= 1)
        v += __shfl_down_sync(0xffffffffu, v, off);
    if ((j & 31) == 0) red[j >> 5] = v;
    __syncthreads();
    if (j == 0) {
        float s = red[0] + red[1] + __ldg(&bsc[0]);
        out[r] = 1.f / (1.f + expf(-s));
    }
}

// ---------------------------------------------------------------------------
// Launch
// ---------------------------------------------------------------------------
extern "C" void kernel_launch(void* const* d_in, const int* in_sizes, int n_in,
                              void* d_out, int out_size)
{
    (void)in_sizes; (void)n_in; (void)out_size;
    const float* x_q  = (const float*)d_in[0];
    const float* x_c  = (const float*)d_in[1];
    const int*   src_q = (const int*)d_in[2];
    const int*   dst_q = (const int*)d_in[3];
    const int*   src_c = (const int*)d_in[4];
    const int*   dst_c = (const int*)d_in[5];
    const float* Wg0 = (const float*)d_in[6];
    const float* bg0 = (const float*)d_in[7];
    const float* Wg1 = (const float*)d_in[8];
    const float* bg1 = (const float*)d_in[9];
    const float* Wg2 = (const float*)d_in[10];
    const float* bg2 = (const float*)d_in[11];
    const float* cw0 = (const float*)d_in[12];
    const float* cb0 = (const float*)d_in[13];
    const float* cw1 = (const float*)d_in[14];
    const float* cb1 = (const float*)d_in[15];
    const float* Wl0 = (const float*)d_in[16];
    const float* bl0 = (const float*)d_in[17];
    const float* Wl1 = (const float*)d_in[18];
    const float* bl1 = (const float*)d_in[19];
    const float* Wsc = (const float*)d_in[20];
    const float* bsc = (const float*)d_in[21];
    float* out = (float*)d_out;

    // Fused 3-layer GCN (q + c in one grid)
    gcn_all<<<2*NB_GRAPHS, 256>>>(x_q, x_c, Wg0, bg0, Wg1, bg1, Wg2, bg2,
                                  src_q, dst_q, src_c, dst_c);

    // Fused sim + conv stacks: all 3 sims, one launch (interleaved)
    pair_all<<<3*NB_GRAPHS, 256>>>(cw0, cb0, cw1, cb1);

    // MLP
    init_y1<<<512, 256>>>(bl0);
    gemm1_kernel<<<dim3(8, 4, KSPLIT), 256>>>(Wl0);
    head_kernel<<<512, 64>>>(Wl1, bl1, Wsc, bsc, out);
}

// round 5
// speedup vs baseline: 1.9162x; 1.3864x over previous
#include <cuda_runtime.h>
#include <math.h>

// ---------------------------------------------------------------------------
// Problem constants
// ---------------------------------------------------------------------------
#define NB_GRAPHS 512          // B
#define M_NODES   64           // nodes per graph
#define EPG       512          // edges per graph

// ---------------------------------------------------------------------------
// Scratch layout (single __device__ array, no allocations)
// ---------------------------------------------------------------------------
#define SZ_F0 (32768*64)
#define SZ_F1 (32768*32)
#define SZ_F2 (32768*16)
#define SZ_H  (512*12288)
#define SZ_Y1 (512*256)

#define OFF_FQ0 0
#define OFF_FC0 (OFF_FQ0 + SZ_F0)
#define OFF_FQ1 (OFF_FC0 + SZ_F0)
#define OFF_FC1 (OFF_FQ1 + SZ_F1)
#define OFF_FQ2 (OFF_FC1 + SZ_F1)
#define OFF_FC2 (OFF_FQ2 + SZ_F2)
#define OFF_H   (OFF_FC2 + SZ_F2)
#define OFF_Y1  (OFF_H + SZ_H)
#define SCRATCH_TOTAL (OFF_Y1 + SZ_Y1)

__device__ float g_scratch[SCRATCH_TOTAL];

// ---------------------------------------------------------------------------
// Packed fp32x2 helpers
// ---------------------------------------------------------------------------
typedef unsigned long long u64;

__device__ __forceinline__ u64 pack2(float lo, float hi) {
    u64 r; asm("mov.b64 %0, {%1,%2};" : "=l"(r) : "f"(lo), "f"(hi)); return r;
}
__device__ __forceinline__ u64 fma2(u64 a, u64 b, u64 c) {
    u64 d; asm("fma.rn.f32x2 %0, %1, %2, %3;" : "=l"(d) : "l"(a), "l"(b), "l"(c));
    return d;
}
__device__ __forceinline__ float2 unpack2(u64 v) {
    float lo, hi; asm("mov.b64 {%0,%1}, %2;" : "=f"(lo), "=f"(hi) : "l"(v));
    return make_float2(lo, hi);
}
__device__ __forceinline__ unsigned f2tf32(float f) {
    unsigned u; asm("cvt.rna.tf32.f32 %0, %1;" : "=r"(u) : "f"(f)); return u;
}

// ---------------------------------------------------------------------------
// Fused 3-layer GCN with sort+gather aggregation (no per-feature atomics).
// One block per graph (1024 blocks = 512 q + 512 c).
// sA holds dinv[n] * (x @ W)[n];  out[d] = bias + dinv[d]*(sA[d] + sum sA[src])
// ---------------------------------------------------------------------------
template<int FIN, int FOUT>
__device__ __forceinline__ void gcn_layer_body(
    const float* __restrict__ sx, float* __restrict__ sA, float* __restrict__ sout,
    const float* __restrict__ sdinv,
    const int* __restrict__ sstart, const int* __restrict__ ssrc,
    const float* __restrict__ W, const float* __restrict__ bias,
    float* __restrict__ outg, int t)
{
    // GEMM with dinv pre-scale: sA[n][j] = dinv[n] * sum_k sx[n][k] * W[k][j]
    {
        const int j = t % FOUT;
        float wcol[FIN];
        #pragma unroll
        for (int k = 0; k < FIN; ++k) wcol[k] = __ldg(&W[k*FOUT + j]);
        for (int i = t; i < 64*FOUT; i += 256) {
            int n = i / FOUT;
            float acc = 0.f;
            #pragma unroll
            for (int k = 0; k < FIN; ++k) acc += sx[n*FIN + k] * wcol[k];
            sA[i] = acc * sdinv[n];
        }
    }
    __syncthreads();

    // gather: one warp per node (8 warps sweep 64 nodes)
    {
        const int wp = t >> 5, lane = t & 31;
        constexpr int CH = (FOUT + 31) / 32;
        for (int d = wp; d < 64; d += 8) {
            const int e0 = sstart[d], e1 = sstart[d + 1];
            const float dv = sdinv[d];
            float a[CH];
            #pragma unroll
            for (int c = 0; c < CH; ++c) {
                int j = lane + 32*c;
                a[c] = (j < FOUT) ? sA[d*FOUT + j] : 0.f;
            }
            for (int e = e0; e < e1; ++e) {
                int s = ssrc[e];
                #pragma unroll
                for (int c = 0; c < CH; ++c) {
                    int j = lane + 32*c;
                    if (j < FOUT) a[c] += sA[s*FOUT + j];
                }
            }
            #pragma unroll
            for (int c = 0; c < CH; ++c) {
                int j = lane + 32*c;
                if (j < FOUT) sout[d*FOUT + j] = dv*a[c] + __ldg(&bias[j]);
            }
        }
    }
    __syncthreads();

    for (int i = t; i < 64*FOUT; i += 256)
        outg[i] = sout[i];
}

__global__ void __launch_bounds__(256) gcn_all(
    const float* __restrict__ xq, const float* __restrict__ xc,
    const float* __restrict__ Wg0, const float* __restrict__ bg0,
    const float* __restrict__ Wg1, const float* __restrict__ bg1,
    const float* __restrict__ Wg2, const float* __restrict__ bg2,
    const int* __restrict__ srcq, const int* __restrict__ dstq,
    const int* __restrict__ srcc, const int* __restrict__ dstc)
{
    __shared__ float pool[10240];
    __shared__ int   ssrc[EPG];
    __shared__ int   sstart[65];
    __shared__ int   scnt[64];
    __shared__ float sdinv[64];

    const int g   = blockIdx.x;
    const bool isC = (g >= NB_GRAPHS);
    const int gg  = isC ? g - NB_GRAPHS : g;
    const float* x = isC ? xc : xq;
    const int* src = isC ? srcc : srcq;
    const int* dst = isC ? dstc : dstq;

    const int nb = gg * M_NODES;
    const int eb = gg * EPG;
    const int t  = threadIdx.x;

    if (t < 64) scnt[t] = 0;
    __syncthreads();

    // pass 1: degree histogram (+ load layer-0 features)
    for (int e = t; e < EPG; e += 256)
        atomicAdd(&scnt[dst[eb + e] - nb], 1);
    for (int i = t; i < 64*32; i += 256) pool[i] = x[(long)nb*32 + i];
    __syncthreads();

    if (t == 0) {
        int a = 0;
        for (int i = 0; i < 64; ++i) { sstart[i] = a; a += scnt[i]; }
        sstart[64] = a;
    }
    __syncthreads();
    if (t < 64) {
        scnt[t] = sstart[t];   // cursor
        sdinv[t] = rsqrtf(1.0f + (float)(sstart[t + 1] - sstart[t]));
    }
    __syncthreads();

    // pass 2: bucket sources by destination
    for (int e = t; e < EPG; e += 256) {
        int d = dst[eb + e] - nb;
        int s = src[eb + e] - nb;
        int p = atomicAdd(&scnt[d], 1);
        ssrc[p] = s;
    }
    __syncthreads();

    // Layer 0: 32 -> 64
    gcn_layer_body<32,64>(pool, pool+2048, pool+6144, sdinv, sstart, ssrc,
                          Wg0, bg0, g_scratch + (isC?OFF_FC0:OFF_FQ0) + (long)nb*64, t);
    for (int i = t; i < 64*64; i += 256) pool[i] = fmaxf(pool[6144 + i], 0.f);
    __syncthreads();

    // Layer 1: 64 -> 32
    gcn_layer_body<64,32>(pool, pool+4096, pool+6144, sdinv, sstart, ssrc,
                          Wg1, bg1, g_scratch + (isC?OFF_FC1:OFF_FQ1) + (long)nb*32, t);
    for (int i = t; i < 64*32; i += 256) pool[i] = fmaxf(pool[6144 + i], 0.f);
    __syncthreads();

    // Layer 2: 32 -> 16
    gcn_layer_body<32,16>(pool, pool+2048, pool+3072, sdinv, sstart, ssrc,
                          Wg2, bg2, g_scratch + (isC?OFF_FC2:OFF_FQ2) + (long)nb*16, t);
}

// ---------------------------------------------------------------------------
// conv helpers
// ---------------------------------------------------------------------------
// Spatial-paired (conv0): accumulators = 4 rows x 2 col-pairs for ONE channel
template<int Wd>
__device__ __forceinline__ void conv5x5_rowstream(
    const float* __restrict__ plane, const u64* __restrict__ wq,
    u64 accp[4][2], int y0, int x0)
{
    #pragma unroll
    for (int dy = 0; dy < 8; ++dy) {
        const int yy = y0 + dy;
        const bool rowok = ((unsigned)yy < (unsigned)Wd);
        float r[8];
        #pragma unroll
        for (int j = 0; j < 4; ++j) {
            int xx = x0 + 2*j;
            float2 v = make_float2(0.f, 0.f);
            if (rowok && (unsigned)xx < (unsigned)Wd)
                v = *(const float2*)(plane + yy*Wd + xx);
            r[2*j] = v.x; r[2*j+1] = v.y;
        }
        u64 q[7];
        #pragma unroll
        for (int j = 0; j < 7; ++j) q[j] = pack2(r[j], r[j+1]);
        #pragma unroll
        for (int u = 0; u < 4; ++u) {
            const int ky = dy - u;
            if (ky >= 0 && ky < 5) {
                #pragma unroll
                for (int kx = 0; kx < 5; ++kx) {
                    u64 w = wq[ky*5 + kx];
                    accp[u][0] = fma2(q[kx],     w, accp[u][0]);
                    accp[u][1] = fma2(q[kx + 2], w, accp[u][1]);
                }
            }
        }
    }
}

__device__ __forceinline__ void pool_store(const u64 accp[4][2], float* dst, int stride)
{
    #pragma unroll
    for (int a = 0; a < 2; ++a)
        #pragma unroll
        for (int b = 0; b < 2; ++b) {
            float2 p0 = unpack2(accp[2*a][b]);
            float2 p1 = unpack2(accp[2*a+1][b]);
            float m = fmaxf(fmaxf(p0.x, p0.y), fmaxf(p1.x, p1.y));
            dst[a*stride + b] = fmaxf(m, 0.f);
        }
}

// Output-channel-paired (conv1): accumulators = 4x4 spatial, each u64 = (o, o+1)
template<int Wd>
__device__ __forceinline__ void conv5x5_opair(
    const float* __restrict__ plane, const u64* __restrict__ wq,
    u64 acc[4][4], int y0, int x0)
{
    #pragma unroll
    for (int dy = 0; dy < 8; ++dy) {
        const int yy = y0 + dy;
        const bool rowok = ((unsigned)yy < (unsigned)Wd);
        u64 sp[8];
        #pragma unroll
        for (int j = 0; j < 4; ++j) {
            int xx = x0 + 2*j;
            float2 v = make_float2(0.f, 0.f);
            if (rowok && (unsigned)xx < (unsigned)Wd)
                v = *(const float2*)(plane + yy*Wd + xx);
            sp[2*j]   = pack2(v.x, v.x);
            sp[2*j+1] = pack2(v.y, v.y);
        }
        #pragma unroll
        for (int u = 0; u < 4; ++u) {
            const int ky = dy - u;
            if (ky >= 0 && ky < 5) {
                #pragma unroll
                for (int kx = 0; kx < 5; ++kx) {
                    u64 w = wq[ky*5 + kx];
                    #pragma unroll
                    for (int v = 0; v < 4; ++v)
                        acc[u][v] = fma2(sp[v + kx], w, acc[u][v]);
                }
            }
        }
    }
}

// ---------------------------------------------------------------------------
// Fused pair kernel (sim GEMM + conv0 + conv1), all 3 sims, grid = 1536
// ---------------------------------------------------------------------------
__global__ void __launch_bounds__(256, 2) pair_all(
    const float* __restrict__ cw0, const float* __restrict__ cb0,
    const float* __restrict__ cw1, const float* __restrict__ cb1)
{
    __shared__ __align__(16) float sA[8192];   // 32 KB
    __shared__ __align__(16) float sB[4096];   // 16 KB

    const int sim = blockIdx.x % 3;
    const int bk  = blockIdx.x / 3;
    const int lf  = 6 - sim;                 // log2(F)
    const int F   = 1 << lf;                 // 64, 32, 16
    const int offq = (sim == 0) ? OFF_FQ0 : (sim == 1) ? OFF_FQ1 : OFF_FQ2;
    const int offc = (sim == 0) ? OFF_FC0 : (sim == 1) ? OFF_FC1 : OFF_FC2;
    const float* cw0p = cw0 + sim*200;
    const float* cb0p = cb0 + sim*8;
    const float* cw1p = cw1 + sim*3200;
    const float* cb1p = cb1 + sim*16;

    const int t = threadIdx.x;
    const float* fq = g_scratch + offq + ((long)bk << (6 + lf));
    const float* fc = g_scratch + offc + ((long)bk << (6 + lf));

    float* sq  = sA;          // [64][F]
    float* scT = sA + 4096;   // [F][64] 4-granular xor-swizzled

    for (int i = t; i < (64 << lf); i += 256) sq[i] = fq[i];
    for (int i = t; i < (64 << lf); i += 256) {
        int n = i >> lf, k = i & (F - 1);
        scT[k*64 + (n ^ (k & 28))] = fc[i];
    }
    __syncthreads();

    // ---- similarity GEMM (f32x2): 4x4 tile per thread -> sB[m][n] ----
    {
        const int m0 = (t >> 4) << 2;
        const int n0 = (t & 15) << 2;
        u64 acc[4][2] = {};
        #pragma unroll 16
        for (int k = 0; k < F; ++k) {
            const int s = k & 28;
            u64 bp[2];
            bp[0] = *(const u64*)&scT[k*64 + ((n0    ) ^ s)];
            bp[1] = *(const u64*)&scT[k*64 + ((n0 + 2) ^ s)];
            #pragma unroll
            for (int u = 0; u < 4; ++u) {
                float av = sq[((m0+u) << lf) + k];
                u64 ap = pack2(av, av);
                acc[u][0] = fma2(bp[0], ap, acc[u][0]);
                acc[u][1] = fma2(bp[1], ap, acc[u][1]);
            }
        }
        #pragma unroll
        for (int u = 0; u < 4; ++u)
            #pragma unroll
            for (int vp = 0; vp < 2; ++vp)
                *(float2*)&sB[(m0+u)*64 + n0 + 2*vp] = unpack2(acc[u][vp]);
    }
    __syncthreads();   // sim done; sA reusable for pooled conv0 output

    // ---- conv0 (1->8, 5x5, same) + relu + 2x2 maxpool -> sA[o][32][32] ----
    {
        const int ty = t >> 4, tx = t & 15;
        const int y0 = 4*ty - 2, x0 = 4*tx - 2;
        for (int o = 0; o < 8; ++o) {
            u64 wq[25];
            #pragma unroll
            for (int i = 0; i < 25; ++i) {
                float w = __ldg(&cw0p[o*25 + i]);
                wq[i] = pack2(w, w);
            }
            float b0 = __ldg(&cb0p[o]);
            u64 accp[4][2];
            #pragma unroll
            for (int u = 0; u < 4; ++u) { accp[u][0] = pack2(b0,b0); accp[u][1] = pack2(b0,b0); }
            conv5x5_rowstream<64>(sB, wq, accp, y0, x0);
            pool_store(accp, &sA[o*1024 + (2*ty)*32 + 2*tx], 32);
        }
    }
    __syncthreads();   // conv0 reads of sB done -> sB reusable for packed weights

    // prepack conv1 weights as output-pairs: sW[(op*8+c)*25+k] = (w[2op], w[2op+1])
    u64* sW = (u64*)sB;
    for (int i = t; i < 1600; i += 256) {
        int op  = i / 200;
        int rem = i - op*200;          // c*25 + k
        int c = rem / 25, k = rem - c*25;
        sW[i] = pack2(__ldg(&cw1p[((2*op    )*8 + c)*25 + k]),
                      __ldg(&cw1p[((2*op + 1)*8 + c)*25 + k]));
    }
    __syncthreads();

    // ---- conv1 (8->16, 5x5, same, o-paired) + relu + pool -> global h ----
    {
        float* hout = g_scratch + OFF_H + sim*4096 + (long)bk * 12288;
        #pragma unroll
        for (int it = 0; it < 2; ++it) {
            const int item = it*256 + t;
            const int op   = item >> 6;          // 0..7 (uniform per warp)
            const int tile = item & 63;
            const int ty = tile >> 3, tx = tile & 7;
            const int y0 = 4*ty - 2, x0 = 4*tx - 2;

            u64 binit = pack2(__ldg(&cb1p[2*op]), __ldg(&cb1p[2*op + 1]));
            u64 acc[4][4];
            #pragma unroll
            for (int u = 0; u < 4; ++u)
                #pragma unroll
                for (int v = 0; v < 4; ++v) acc[u][v] = binit;

            for (int c = 0; c < 8; ++c) {
                u64 wq[25];
                const u64* ws = &sW[(op*8 + c) * 25];
                #pragma unroll
                for (int i = 0; i < 25; ++i) wq[i] = ws[i];
                conv5x5_opair<32>(&sA[c*1024], wq, acc, y0, x0);
            }
            #pragma unroll
            for (int a = 0; a < 2; ++a)
                #pragma unroll
                for (int b = 0; b < 2; ++b) {
                    float2 p00 = unpack2(acc[2*a][2*b]);
                    float2 p01 = unpack2(acc[2*a][2*b+1]);
                    float2 p10 = unpack2(acc[2*a+1][2*b]);
                    float2 p11 = unpack2(acc[2*a+1][2*b+1]);
                    float mlo = fmaxf(fmaxf(p00.x, p01.x), fmaxf(p10.x, p11.x));
                    float mhi = fmaxf(fmaxf(p00.y, p01.y), fmaxf(p10.y, p11.y));
                    hout[((2*op    )*16 + 2*ty + a)*16 + 2*tx + b] = fmaxf(mlo, 0.f);
                    hout[((2*op + 1)*16 + 2*ty + a)*16 + 2*tx + b] = fmaxf(mhi, 0.f);
                }
        }
    }
}

// ---------------------------------------------------------------------------
// MLP layer 0 on tensor cores: y1 += h @ Wl0, tf32 mma.sync m16n8k8.
// 128x128 block tile, KSPLIT=16 -> 128 blocks = one wave. Fragment-permuted
// smem layout so fragment loads are single ld.shared.v4/v2.
// ---------------------------------------------------------------------------
__global__ void init_y1(const float* __restrict__ bl0)
{
    int i = blockIdx.x * 256 + threadIdx.x;
    if (i < 512*256) g_scratch[OFF_Y1 + i] = __ldg(&bl0[i & 255]);
}

#define KSPLIT 16
#define KC (12288 / KSPLIT)   // 768
#define KT 32                 // k per smem tile

__device__ __forceinline__ void mma_tf32(float c[4],
    unsigned a0, unsigned a1, unsigned a2, unsigned a3,
    unsigned b0, unsigned b1)
{
    asm volatile(
        "mma.sync.aligned.m16n8k8.row.col.f32.tf32.tf32.f32 "
        "{%0,%1,%2,%3}, {%4,%5,%6,%7}, {%8,%9}, {%0,%1,%2,%3};"
        : "+f"(c[0]), "+f"(c[1]), "+f"(c[2]), "+f"(c[3])
        : "r"(a0), "r"(a1), "r"(a2), "r"(a3), "r"(b0), "r"(b1));
}

__global__ void __launch_bounds__(256) gemm1_kernel(const float* __restrict__ Bw)
{
    const float* A = g_scratch + OFF_H;
    float* C = g_scratch + OFF_Y1;

    const int r0 = blockIdx.x * 128;
    const int c0 = blockIdx.y * 128;
    const int k0 = blockIdx.z * KC;

    // fragment-permuted tiles
    __shared__ __align__(16) unsigned sAf[4*8*32*4];    // [kc][mc][lane][slot]
    __shared__ __align__(16) unsigned sBf[4*16*32*2];   // [kc][nc][lane][slot]

    const int t = threadIdx.x;
    const int warp = t >> 5, lane = t & 31;
    const int warp_m = warp & 1;          // 2 x 64-row slabs
    const int warp_n = warp >> 1;         // 4 x 32-col slabs
    const int g = lane >> 2, tig = lane & 3;

    // A loader mapping: row = t>>1 (0..127), 16 cols starting at (t&1)*16
    const int a_row = t >> 1, a_cb = (t & 1) * 16;
    const int a_mc = a_row >> 4;
    const int a_r  = a_row & 15;
    const int a_g = a_r & 7, a_half = a_r >> 3;
    // B loader mapping: kk = t>>3 (0..31), 16 cols starting at (t&7)*16
    const int b_kk = t >> 3, b_cb = (t & 7) * 16;
    const int b_kc = b_kk >> 3, b_ck = b_kk & 7;
    const int b_lane_base = b_ck & 3;
    const int b_slot = b_ck >> 2;

    float c[4][4][4];
    #pragma unroll
    for (int mi = 0; mi < 4; ++mi)
        #pragma unroll
        for (int ni = 0; ni < 4; ++ni)
            #pragma unroll
            for (int r = 0; r < 4; ++r) c[mi][ni][r] = 0.f;

    for (int kt = 0; kt < KC; kt += KT) {
        // load + convert + permute A (128 x 32)
        {
            const float* Ag = A + (long)(r0 + a_row)*12288 + k0 + kt + a_cb;
            #pragma unroll
            for (int q = 0; q < 4; ++q) {
                float4 v = *(const float4*)(Ag + 4*q);
                float vv[4] = {v.x, v.y, v.z, v.w};
                #pragma unroll
                for (int j = 0; j < 4; ++j) {
                    int k = a_cb + 4*q + j;
                    int kc = k >> 3, ck = k & 7;
                    int ln = a_g*4 + (ck & 3);
                    int slot = a_half + 2*(ck >> 2);
                    sAf[((kc*8 + a_mc)*32 + ln)*4 + slot] = f2tf32(vv[j]);
                }
            }
        }
        // load + convert + permute B (32 x 128)
        {
            const float* Bg = Bw + (long)(k0 + kt + b_kk)*256 + c0 + b_cb;
            #pragma unroll
            for (int q = 0; q < 4; ++q) {
                float4 v = *(const float4*)(Bg + 4*q);
                float vv[4] = {v.x, v.y, v.z, v.w};
                #pragma unroll
                for (int j = 0; j < 4; ++j) {
                    int n = b_cb + 4*q + j;
                    int nc = n >> 3, ng = n & 7;
                    sBf[((b_kc*16 + nc)*32 + ng*4 + b_lane_base)*2 + b_slot] = f2tf32(vv[j]);
                }
            }
        }
        __syncthreads();

        #pragma unroll
        for (int kc = 0; kc < 4; ++kc) {
            unsigned af[4][4], bf[4][2];
            #pragma unroll
            for (int mi = 0; mi < 4; ++mi) {
                int mc = warp_m*4 + mi;
                uint4 va = *(const uint4*)&sAf[((kc*8 + mc)*32 + lane)*4];
                af[mi][0] = va.x; af[mi][1] = va.y; af[mi][2] = va.z; af[mi][3] = va.w;
            }
            #pragma unroll
            for (int ni = 0; ni < 4; ++ni) {
                int nc = warp_n*4 + ni;
                uint2 vb = *(const uint2*)&sBf[((kc*16 + nc)*32 + lane)*2];
                bf[ni][0] = vb.x; bf[ni][1] = vb.y;
            }
            #pragma unroll
            for (int mi = 0; mi < 4; ++mi)
                #pragma unroll
                for (int ni = 0; ni < 4; ++ni)
                    mma_tf32(c[mi][ni], af[mi][0], af[mi][1], af[mi][2], af[mi][3],
                             bf[ni][0], bf[ni][1]);
        }
        __syncthreads();
    }

    // epilogue: split-K atomic accumulation
    #pragma unroll
    for (int mi = 0; mi < 4; ++mi) {
        int Rr = r0 + warp_m*64 + mi*16 + g;
        #pragma unroll
        for (int ni = 0; ni < 4; ++ni) {
            int Cc = c0 + warp_n*32 + ni*8 + 2*tig;
            atomicAdd(&C[Rr*256 + Cc],         c[mi][ni][0]);
            atomicAdd(&C[Rr*256 + Cc + 1],     c[mi][ni][1]);
            atomicAdd(&C[(Rr+8)*256 + Cc],     c[mi][ni][2]);
            atomicAdd(&C[(Rr+8)*256 + Cc + 1], c[mi][ni][3]);
        }
    }
}

// ---------------------------------------------------------------------------
// Head: relu(y1) @ Wl1 + bl1 -> relu -> @ Wsc + bsc -> sigmoid. One block/row.
// ---------------------------------------------------------------------------
__global__ void head_kernel(const float* __restrict__ Wl1, const float* __restrict__ bl1,
                            const float* __restrict__ Wsc, const float* __restrict__ bsc,
                            float* __restrict__ out)
{
    const int r = blockIdx.x;
    const int j = threadIdx.x;   // 64 threads
    __shared__ float sy[256];
    __shared__ float red[2];

    const float* y1 = g_scratch + OFF_Y1 + (long)r * 256;
    for (int k = j; k < 256; k += 64) sy[k] = fmaxf(y1[k], 0.f);
    __syncthreads();

    float acc = __ldg(&bl1[j]);
    #pragma unroll 8
    for (int k = 0; k < 256; ++k) acc += sy[k] * __ldg(&Wl1[k*64 + j]);

    float v = fmaxf(acc, 0.f) * __ldg(&Wsc[j]);
    #pragma unroll
    for (int off = 16; off > 0; off >>= 1)
        v += __shfl_down_sync(0xffffffffu, v, off);
    if ((j & 31) == 0) red[j >> 5] = v;
    __syncthreads();
    if (j == 0) {
        float s = red[0] + red[1] + __ldg(&bsc[0]);
        out[r] = 1.f / (1.f + expf(-s));
    }
}

// ---------------------------------------------------------------------------
// Launch
// ---------------------------------------------------------------------------
extern "C" void kernel_launch(void* const* d_in, const int* in_sizes, int n_in,
                              void* d_out, int out_size)
{
    (void)in_sizes; (void)n_in; (void)out_size;
    const float* x_q  = (const float*)d_in[0];
    const float* x_c  = (const float*)d_in[1];
    const int*   src_q = (const int*)d_in[2];
    const int*   dst_q = (const int*)d_in[3];
    const int*   src_c = (const int*)d_in[4];
    const int*   dst_c = (const int*)d_in[5];
    const float* Wg0 = (const float*)d_in[6];
    const float* bg0 = (const float*)d_in[7];
    const float* Wg1 = (const float*)d_in[8];
    const float* bg1 = (const float*)d_in[9];
    const float* Wg2 = (const float*)d_in[10];
    const float* bg2 = (const float*)d_in[11];
    const float* cw0 = (const float*)d_in[12];
    const float* cb0 = (const float*)d_in[13];
    const float* cw1 = (const float*)d_in[14];
    const float* cb1 = (const float*)d_in[15];
    const float* Wl0 = (const float*)d_in[16];
    const float* bl0 = (const float*)d_in[17];
    const float* Wl1 = (const float*)d_in[18];
    const float* bl1 = (const float*)d_in[19];
    const float* Wsc = (const float*)d_in[20];
    const float* bsc = (const float*)d_in[21];
    float* out = (float*)d_out;

    // y1 bias init early (independent of everything upstream)
    init_y1<<<512, 256>>>(bl0);

    // Fused 3-layer GCN (q + c in one grid), sort+gather aggregation
    gcn_all<<<2*NB_GRAPHS, 256>>>(x_q, x_c, Wg0, bg0, Wg1, bg1, Wg2, bg2,
                                  src_q, dst_q, src_c, dst_c);

    // Fused sim + conv stacks: all 3 sims, one launch (interleaved)
    pair_all<<<3*NB_GRAPHS, 256>>>(cw0, cb0, cw1, cb1);

    // MLP layer 0 on tensor cores (tf32), then head
    gemm1_kernel<<<dim3(4, 2, KSPLIT), 256>>>(Wl0);
    head_kernel<<<512, 64>>>(Wl1, bl1, Wsc, bsc, out);
}

// round 6
// speedup vs baseline: 2.4269x; 1.2665x over previous
#include <cuda_runtime.h>
#include <math.h>

// ---------------------------------------------------------------------------
// Problem constants
// ---------------------------------------------------------------------------
#define NB_GRAPHS 512          // B
#define M_NODES   64           // nodes per graph
#define EPG       512          // edges per graph

// ---------------------------------------------------------------------------
// Scratch layout (single __device__ array, no allocations)
// ---------------------------------------------------------------------------
#define SZ_F0 (32768*64)
#define SZ_F1 (32768*32)
#define SZ_F2 (32768*16)
#define SZ_H  (512*12288)
#define SZ_Y1 (512*256)
#define SZ_WT0 (12288*256)

#define OFF_FQ0 0
#define OFF_FC0 (OFF_FQ0 + SZ_F0)
#define OFF_FQ1 (OFF_FC0 + SZ_F0)
#define OFF_FC1 (OFF_FQ1 + SZ_F1)
#define OFF_FQ2 (OFF_FC1 + SZ_F1)
#define OFF_FC2 (OFF_FQ2 + SZ_F2)
#define OFF_H   (OFF_FC2 + SZ_F2)
#define OFF_Y1  (OFF_H + SZ_H)
#define OFF_WT0 (OFF_Y1 + SZ_Y1)
#define SCRATCH_TOTAL (OFF_WT0 + SZ_WT0)

__device__ float g_scratch[SCRATCH_TOTAL];

// ---------------------------------------------------------------------------
// Helpers
// ---------------------------------------------------------------------------
typedef unsigned long long u64;

__device__ __forceinline__ u64 pack2(float lo, float hi) {
    u64 r; asm("mov.b64 %0, {%1,%2};" : "=l"(r) : "f"(lo), "f"(hi)); return r;
}
__device__ __forceinline__ u64 fma2(u64 a, u64 b, u64 c) {
    u64 d; asm("fma.rn.f32x2 %0, %1, %2, %3;" : "=l"(d) : "l"(a), "l"(b), "l"(c));
    return d;
}
__device__ __forceinline__ float2 unpack2(u64 v) {
    float lo, hi; asm("mov.b64 {%0,%1}, %2;" : "=f"(lo), "=f"(hi) : "l"(v));
    return make_float2(lo, hi);
}
__device__ __forceinline__ unsigned f2tf32(float f) {
    unsigned u; asm("cvt.rna.tf32.f32 %0, %1;" : "=r"(u) : "f"(f)); return u;
}
__device__ __forceinline__ float tf32f(float f) {     // rna-rounded tf32 as fp32
    return __uint_as_float(f2tf32(f));
}
__device__ __forceinline__ void cp_async16(float* dst, const float* src) {
    unsigned d = (unsigned)__cvta_generic_to_shared(dst);
    asm volatile("cp.async.cg.shared.global [%0], [%1], 16;" :: "r"(d), "l"(src));
}
__device__ __forceinline__ void mma_tf32(float c[4],
    unsigned a0, unsigned a1, unsigned a2, unsigned a3,
    unsigned b0, unsigned b1)
{
    asm volatile(
        "mma.sync.aligned.m16n8k8.row.col.f32.tf32.tf32.f32 "
        "{%0,%1,%2,%3}, {%4,%5,%6,%7}, {%8,%9}, {%0,%1,%2,%3};"
        : "+f"(c[0]), "+f"(c[1]), "+f"(c[2]), "+f"(c[3])
        : "r"(a0), "r"(a1), "r"(a2), "r"(a3), "r"(b0), "r"(b1));
}

// ---------------------------------------------------------------------------
// Fused 3-layer GCN with sort+gather aggregation (unchanged from R4)
// ---------------------------------------------------------------------------
template<int FIN, int FOUT>
__device__ __forceinline__ void gcn_layer_body(
    const float* __restrict__ sx, float* __restrict__ sA, float* __restrict__ sout,
    const float* __restrict__ sdinv,
    const int* __restrict__ sstart, const int* __restrict__ ssrc,
    const float* __restrict__ W, const float* __restrict__ bias,
    float* __restrict__ outg, int t)
{
    {
        const int j = t % FOUT;
        float wcol[FIN];
        #pragma unroll
        for (int k = 0; k < FIN; ++k) wcol[k] = __ldg(&W[k*FOUT + j]);
        for (int i = t; i < 64*FOUT; i += 256) {
            int n = i / FOUT;
            float acc = 0.f;
            #pragma unroll
            for (int k = 0; k < FIN; ++k) acc += sx[n*FIN + k] * wcol[k];
            sA[i] = acc * sdinv[n];
        }
    }
    __syncthreads();

    {
        const int wp = t >> 5, lane = t & 31;
        constexpr int CH = (FOUT + 31) / 32;
        for (int d = wp; d < 64; d += 8) {
            const int e0 = sstart[d], e1 = sstart[d + 1];
            const float dv = sdinv[d];
            float a[CH];
            #pragma unroll
            for (int c = 0; c < CH; ++c) {
                int j = lane + 32*c;
                a[c] = (j < FOUT) ? sA[d*FOUT + j] : 0.f;
            }
            for (int e = e0; e < e1; ++e) {
                int s = ssrc[e];
                #pragma unroll
                for (int c = 0; c < CH; ++c) {
                    int j = lane + 32*c;
                    if (j < FOUT) a[c] += sA[s*FOUT + j];
                }
            }
            #pragma unroll
            for (int c = 0; c < CH; ++c) {
                int j = lane + 32*c;
                if (j < FOUT) sout[d*FOUT + j] = dv*a[c] + __ldg(&bias[j]);
            }
        }
    }
    __syncthreads();

    for (int i = t; i < 64*FOUT; i += 256)
        outg[i] = sout[i];
}

__global__ void __launch_bounds__(256) gcn_all(
    const float* __restrict__ xq, const float* __restrict__ xc,
    const float* __restrict__ Wg0, const float* __restrict__ bg0,
    const float* __restrict__ Wg1, const float* __restrict__ bg1,
    const float* __restrict__ Wg2, const float* __restrict__ bg2,
    const int* __restrict__ srcq, const int* __restrict__ dstq,
    const int* __restrict__ srcc, const int* __restrict__ dstc)
{
    __shared__ float pool[10240];
    __shared__ int   ssrc[EPG];
    __shared__ int   sstart[65];
    __shared__ int   scnt[64];
    __shared__ float sdinv[64];

    const int g   = blockIdx.x;
    const bool isC = (g >= NB_GRAPHS);
    const int gg  = isC ? g - NB_GRAPHS : g;
    const float* x = isC ? xc : xq;
    const int* src = isC ? srcc : srcq;
    const int* dst = isC ? dstc : dstq;

    const int nb = gg * M_NODES;
    const int eb = gg * EPG;
    const int t  = threadIdx.x;

    if (t < 64) scnt[t] = 0;
    __syncthreads();

    for (int e = t; e < EPG; e += 256)
        atomicAdd(&scnt[dst[eb + e] - nb], 1);
    for (int i = t; i < 64*32; i += 256) pool[i] = x[(long)nb*32 + i];
    __syncthreads();

    if (t == 0) {
        int a = 0;
        for (int i = 0; i < 64; ++i) { sstart[i] = a; a += scnt[i]; }
        sstart[64] = a;
    }
    __syncthreads();
    if (t < 64) {
        scnt[t] = sstart[t];
        sdinv[t] = rsqrtf(1.0f + (float)(sstart[t + 1] - sstart[t]));
    }
    __syncthreads();

    for (int e = t; e < EPG; e += 256) {
        int d = dst[eb + e] - nb;
        int s = src[eb + e] - nb;
        int p = atomicAdd(&scnt[d], 1);
        ssrc[p] = s;
    }
    __syncthreads();

    gcn_layer_body<32,64>(pool, pool+2048, pool+6144, sdinv, sstart, ssrc,
                          Wg0, bg0, g_scratch + (isC?OFF_FC0:OFF_FQ0) + (long)nb*64, t);
    for (int i = t; i < 64*64; i += 256) pool[i] = fmaxf(pool[6144 + i], 0.f);
    __syncthreads();

    gcn_layer_body<64,32>(pool, pool+4096, pool+6144, sdinv, sstart, ssrc,
                          Wg1, bg1, g_scratch + (isC?OFF_FC1:OFF_FQ1) + (long)nb*32, t);
    for (int i = t; i < 64*32; i += 256) pool[i] = fmaxf(pool[6144 + i], 0.f);
    __syncthreads();

    gcn_layer_body<32,16>(pool, pool+2048, pool+3072, sdinv, sstart, ssrc,
                          Wg2, bg2, g_scratch + (isC?OFF_FC2:OFF_FQ2) + (long)nb*16, t);
}

// ---------------------------------------------------------------------------
// conv0 helper: spatial-paired f32x2 row-streaming (one input channel)
// ---------------------------------------------------------------------------
template<int Wd>
__device__ __forceinline__ void conv5x5_rowstream(
    const float* __restrict__ plane, const u64* __restrict__ wq,
    u64 accp[4][2], int y0, int x0)
{
    #pragma unroll
    for (int dy = 0; dy < 8; ++dy) {
        const int yy = y0 + dy;
        const bool rowok = ((unsigned)yy < (unsigned)Wd);
        float r[8];
        #pragma unroll
        for (int j = 0; j < 4; ++j) {
            int xx = x0 + 2*j;
            float2 v = make_float2(0.f, 0.f);
            if (rowok && (unsigned)xx < (unsigned)Wd)
                v = *(const float2*)(plane + yy*Wd + xx);
            r[2*j] = v.x; r[2*j+1] = v.y;
        }
        u64 q[7];
        #pragma unroll
        for (int j = 0; j < 7; ++j) q[j] = pack2(r[j], r[j+1]);
        #pragma unroll
        for (int u = 0; u < 4; ++u) {
            const int ky = dy - u;
            if (ky >= 0 && ky < 5) {
                #pragma unroll
                for (int kx = 0; kx < 5; ++kx) {
                    u64 w = wq[ky*5 + kx];
                    accp[u][0] = fma2(q[kx],     w, accp[u][0]);
                    accp[u][1] = fma2(q[kx + 2], w, accp[u][1]);
                }
            }
        }
    }
}

// ---------------------------------------------------------------------------
// Fused pair kernel: sim GEMM (f32x2) + conv0 (f32x2) + conv1 (tf32 mma)
// grid = 1536 (3 sims x 512 pairs).
// Dynamic smem buf (14464 floats = 57856 B):
//   sim    : buf[0..4096)        (phase 1-2; reused for sW1 in phase 3)
//   sq/scT : buf[4096..12288)    (phase 1; dead after sim)
//   planes : buf[4096..14464)    (8 ch x 36x36 halo-padded, tf32-rounded)
//   praw   : buf[4096..9216)     (pool staging, after planes dead)
// ---------------------------------------------------------------------------
__global__ void __launch_bounds__(256, 2) pair_all(
    const float* __restrict__ cw0, const float* __restrict__ cb0,
    const float* __restrict__ cw1, const float* __restrict__ cb1)
{
    extern __shared__ __align__(16) float buf[];
    __shared__ u64 sw0[200];
    __shared__ int soff[200];

    float* sim    = buf;
    float* sq     = buf + 4096;
    float* scT    = buf + 8192;
    float* planes = buf + 4096;
    float* praw   = buf + 4096;
    float* sw1    = buf;

    const int simi = blockIdx.x % 3;
    const int bk   = blockIdx.x / 3;
    const int lf   = 6 - simi;               // log2(F)
    const int F    = 1 << lf;                // 64, 32, 16
    const int offq = (simi == 0) ? OFF_FQ0 : (simi == 1) ? OFF_FQ1 : OFF_FQ2;
    const int offc = (simi == 0) ? OFF_FC0 : (simi == 1) ? OFF_FC1 : OFF_FC2;
    const float* cw0p = cw0 + simi*200;
    const float* cb0p = cb0 + simi*8;
    const float* cw1p = cw1 + simi*3200;
    const float* cb1p = cb1 + simi*16;

    const int t = threadIdx.x;
    const float* fq = g_scratch + offq + ((long)bk << (6 + lf));
    const float* fc = g_scratch + offc + ((long)bk << (6 + lf));

    // phase 0: stage features + conv0 weights + tap-offset table
    for (int i = t; i < (64 << lf); i += 256) sq[i] = fq[i];
    for (int i = t; i < (64 << lf); i += 256) {
        int n = i >> lf, k = i & (F - 1);
        scT[k*64 + (n ^ (k & 28))] = fc[i];
    }
    for (int i = t; i < 200; i += 256) {
        float w = __ldg(&cw0p[i]);
        sw0[i] = pack2(w, w);
        int c = i / 25, rem = i - c*25;
        soff[i] = c*1296 + (rem/5)*36 + (rem%5);
    }
    __syncthreads();

    // ---- phase 1: similarity GEMM (f32x2) -> sim[64][64] ----
    {
        const int m0 = (t >> 4) << 2;
        const int n0 = (t & 15) << 2;
        u64 acc[4][2] = {};
        #pragma unroll 16
        for (int k = 0; k < F; ++k) {
            const int s = k & 28;
            u64 bp[2];
            bp[0] = *(const u64*)&scT[k*64 + ((n0    ) ^ s)];
            bp[1] = *(const u64*)&scT[k*64 + ((n0 + 2) ^ s)];
            #pragma unroll
            for (int u = 0; u < 4; ++u) {
                float av = sq[((m0+u) << lf) + k];
                u64 ap = pack2(av, av);
                acc[u][0] = fma2(bp[0], ap, acc[u][0]);
                acc[u][1] = fma2(bp[1], ap, acc[u][1]);
            }
        }
        #pragma unroll
        for (int u = 0; u < 4; ++u)
            #pragma unroll
            for (int vp = 0; vp < 2; ++vp)
                *(float2*)&sim[(m0+u)*64 + n0 + 2*vp] = unpack2(acc[u][vp]);
    }
    __syncthreads();

    // ---- phase 2a: zero halo-padded planes ----
    for (int i = t; i < 10368; i += 256) planes[i] = 0.f;
    __syncthreads();

    // ---- phase 2b: conv0 (1->8) + relu + pool -> planes (tf32-rounded) ----
    {
        const int ty = t >> 4, tx = t & 15;
        const int y0 = 4*ty - 2, x0 = 4*tx - 2;
        for (int o = 0; o < 8; ++o) {
            u64 wq[25];
            #pragma unroll
            for (int i = 0; i < 25; ++i) wq[i] = sw0[o*25 + i];
            float b0 = __ldg(&cb0p[o]);
            u64 accp[4][2];
            #pragma unroll
            for (int u = 0; u < 4; ++u) { accp[u][0] = pack2(b0,b0); accp[u][1] = pack2(b0,b0); }
            conv5x5_rowstream<64>(sim, wq, accp, y0, x0);
            #pragma unroll
            for (int a = 0; a < 2; ++a)
                #pragma unroll
                for (int b = 0; b < 2; ++b) {
                    float2 p0 = unpack2(accp[2*a][b]);
                    float2 p1 = unpack2(accp[2*a+1][b]);
                    float m = fmaxf(fmaxf(p0.x, p0.y), fmaxf(p1.x, p1.y));
                    planes[o*1296 + (2 + 2*ty + a)*36 + (2 + 2*tx + b)] =
                        tf32f(fmaxf(m, 0.f));
                }
        }
    }
    __syncthreads();

    // ---- phase 3a: stage conv1 weights [k][o] stride 17, tf32-rounded ----
    for (int i = t; i < 3200; i += 256) {
        int k = i >> 4, o = i & 15;
        sw1[k*17 + o] = tf32f(__ldg(&cw1p[o*200 + k]));
    }
    __syncthreads();

    // ---- phase 3b: conv1 as implicit GEMM, tf32 mma m16n8k8 ----
    // M = 1024 spatial, N = 16 out-ch, K = 200 taps (25 k-steps)
    const int warp = t >> 5, lane = t & 31, g = lane >> 2, tig = lane & 3;
    float acc[8][2][4];
    #pragma unroll
    for (int mi = 0; mi < 8; ++mi)
        #pragma unroll
        for (int ni = 0; ni < 2; ++ni)
            #pragma unroll
            for (int r = 0; r < 4; ++r) acc[mi][ni][r] = 0.f;

    int base_m[8];
    #pragma unroll
    for (int mi = 0; mi < 8; ++mi) {
        int mt = warp*8 + mi;
        base_m[mi] = (mt >> 1)*36 + (mt & 1)*16 + g;
    }

    for (int kk = 0; kk < 25; ++kk) {
        const int klo = 8*kk + tig;
        const int offlo = soff[klo], offhi = soff[klo + 4];
        unsigned bf0[2], bf1[2];
        bf0[0] = __float_as_uint(sw1[klo*17 + g]);
        bf0[1] = __float_as_uint(sw1[(klo+4)*17 + g]);
        bf1[0] = __float_as_uint(sw1[klo*17 + 8 + g]);
        bf1[1] = __float_as_uint(sw1[(klo+4)*17 + 8 + g]);
        #pragma unroll
        for (int mi = 0; mi < 8; ++mi) {
            const float* p = planes + base_m[mi];
            unsigned a0 = __float_as_uint(p[offlo]);
            unsigned a1 = __float_as_uint(p[offlo + 8]);
            unsigned a2 = __float_as_uint(p[offhi]);
            unsigned a3 = __float_as_uint(p[offhi + 8]);
            mma_tf32(acc[mi][0], a0, a1, a2, a3, bf0[0], bf0[1]);
            mma_tf32(acc[mi][1], a0, a1, a2, a3, bf1[0], bf1[1]);
        }
    }
    __syncthreads();   // planes dead; praw region reusable

    // ---- phase 3c: pool via smem roundtrip (4 o-groups of 4) ----
    {
        float* hout = g_scratch + OFF_H + simi*4096 + (long)bk * 12288;
        for (int g2 = 0; g2 < 4; ++g2) {
            if ((tig >> 1) == (g2 & 1)) {
                const int j0 = (2*tig) & 3;   // 0 or 2
                const int ni = g2 >> 1;
                #pragma unroll
                for (int mi = 0; mi < 8; ++mi) {
                    int s0 = (warp*8 + mi)*16 + g;
                    praw[s0*5 + j0]         = acc[mi][ni][0];
                    praw[s0*5 + j0 + 1]     = acc[mi][ni][1];
                    praw[(s0+8)*5 + j0]     = acc[mi][ni][2];
                    praw[(s0+8)*5 + j0 + 1] = acc[mi][ni][3];
                }
            }
            __syncthreads();
            #pragma unroll
            for (int v = 0; v < 4; ++v) {
                int pid = v*256 + t;
                int ol = pid & 3, rest = pid >> 2;
                int X = rest & 15, Y = rest >> 4;
                int s00 = (2*Y)*32 + 2*X;
                float m = fmaxf(fmaxf(praw[s00*5 + ol], praw[(s00+1)*5 + ol]),
                                fmaxf(praw[(s00+32)*5 + ol], praw[(s00+33)*5 + ol]));
                m = fmaxf(m + __ldg(&cb1p[4*g2 + ol]), 0.f);
                hout[(4*g2 + ol)*256 + Y*16 + X] = tf32f(m);
            }
            __syncthreads();
        }
    }
}

// ---------------------------------------------------------------------------
// Pre-round Wl0 to tf32 (once per launch; raw-bit fragments in gemm1)
// ---------------------------------------------------------------------------
__global__ void cvt_wl0_kernel(const float* __restrict__ W)
{
    int i = blockIdx.x * 256 + threadIdx.x;   // float4 index
    float4 v = ((const float4*)W)[i];
    float4 o;
    o.x = tf32f(v.x); o.y = tf32f(v.y); o.z = tf32f(v.z); o.w = tf32f(v.w);
    ((float4*)(g_scratch + OFF_WT0))[i] = o;
}

// ---------------------------------------------------------------------------
// MLP layer 0: y1 += h @ Wl0. tf32 mma, cp.async double-buffered.
// 128x64 tiles, grid (4, 4, 16) = 256 blocks. Conflict-free padded strides.
// ---------------------------------------------------------------------------
__global__ void init_y1(const float* __restrict__ bl0)
{
    int i = blockIdx.x * 256 + threadIdx.x;
    if (i < 512*256) g_scratch[OFF_Y1 + i] = __ldg(&bl0[i & 255]);
}

#define G1_KC 768
#define G1_KT 32
#define G1_NT 24          // k-tiles per block
#define AS_STRIDE 36
#define BS_STRIDE 72
#define AS_SZ (128*AS_STRIDE)   // 4608
#define BS_SZ (32*BS_STRIDE)    // 2304

__global__ void __launch_bounds__(256) gemm1_kernel()
{
    extern __shared__ __align__(16) float gbuf[];
    const float* A = g_scratch + OFF_H;
    const float* B = g_scratch + OFF_WT0;
    float* C = g_scratch + OFF_Y1;

    const int r0 = blockIdx.x * 128;
    const int c0 = blockIdx.y * 64;
    const int k0 = blockIdx.z * G1_KC;

    const int t = threadIdx.x, warp = t >> 5, lane = t & 31;
    const int g = lane >> 2, tig = lane & 3;
    const int wm = warp & 3, wn = warp >> 2;   // 4 m-warps x 2 n-warps

    float acc[2][4][4];
    #pragma unroll
    for (int mi = 0; mi < 2; ++mi)
        #pragma unroll
        for (int ni = 0; ni < 4; ++ni)
            #pragma unroll
            for (int r = 0; r < 4; ++r) acc[mi][ni][r] = 0.f;

    auto issue = [&](int ibuf, int kt) {
        float* As = gbuf + ibuf*AS_SZ;
        float* Bs = gbuf + 2*AS_SZ + ibuf*BS_SZ;
        #pragma unroll
        for (int j = 0; j < 4; ++j) {
            int cid = t + 256*j;
            int row = cid >> 3, seg = cid & 7;
            cp_async16(&As[row*AS_STRIDE + seg*4],
                       A + (long)(r0 + row)*12288 + k0 + kt + seg*4);
        }
        #pragma unroll
        for (int j = 0; j < 2; ++j) {
            int cid = t + 256*j;
            int k = cid >> 4, seg = cid & 15;
            cp_async16(&Bs[k*BS_STRIDE + seg*4],
                       B + (long)(k0 + kt + k)*256 + c0 + seg*4);
        }
        asm volatile("cp.async.commit_group;");
    };

    issue(0, 0);
    issue(1, G1_KT);

    for (int i = 0; i < G1_NT; ++i) {
        if (i < G1_NT - 1) asm volatile("cp.async.wait_group 1;");
        else               asm volatile("cp.async.wait_group 0;");
        __syncthreads();

        const float* As = gbuf + (i & 1)*AS_SZ;
        const float* Bs = gbuf + 2*AS_SZ + (i & 1)*BS_SZ;
        #pragma unroll
        for (int kc = 0; kc < 4; ++kc) {
            unsigned af[2][4], bf[4][2];
            #pragma unroll
            for (int mi = 0; mi < 2; ++mi) {
                const float* ap = As + (wm*32 + mi*16 + g)*AS_STRIDE + kc*8 + tig;
                af[mi][0] = __float_as_uint(ap[0]);
                af[mi][1] = __float_as_uint(ap[8*AS_STRIDE]);
                af[mi][2] = __float_as_uint(ap[4]);
                af[mi][3] = __float_as_uint(ap[8*AS_STRIDE + 4]);
            }
            #pragma unroll
            for (int ni = 0; ni < 4; ++ni) {
                const float* bp = Bs + (kc*8 + tig)*BS_STRIDE + wn*32 + ni*8 + g;
                bf[ni][0] = __float_as_uint(bp[0]);
                bf[ni][1] = __float_as_uint(bp[4*BS_STRIDE]);
            }
            #pragma unroll
            for (int mi = 0; mi < 2; ++mi)
                #pragma unroll
                for (int ni = 0; ni < 4; ++ni)
                    mma_tf32(acc[mi][ni], af[mi][0], af[mi][1], af[mi][2], af[mi][3],
                             bf[ni][0], bf[ni][1]);
        }
        __syncthreads();
        if (i + 2 < G1_NT) issue(i & 1, (i + 2)*G1_KT);
    }

    // epilogue: split-K atomic accumulation
    #pragma unroll
    for (int mi = 0; mi < 2; ++mi) {
        int R = r0 + wm*32 + mi*16 + g;
        #pragma unroll
        for (int ni = 0; ni < 4; ++ni) {
            int Cc = c0 + wn*32 + ni*8 + 2*tig;
            atomicAdd(&C[R*256 + Cc],         acc[mi][ni][0]);
            atomicAdd(&C[R*256 + Cc + 1],     acc[mi][ni][1]);
            atomicAdd(&C[(R+8)*256 + Cc],     acc[mi][ni][2]);
            atomicAdd(&C[(R+8)*256 + Cc + 1], acc[mi][ni][3]);
        }
    }
}

// ---------------------------------------------------------------------------
// Head: relu(y1) @ Wl1 + bl1 -> relu -> @ Wsc + bsc -> sigmoid. One block/row.
// ---------------------------------------------------------------------------
__global__ void head_kernel(const float* __restrict__ Wl1, const float* __restrict__ bl1,
                            const float* __restrict__ Wsc, const float* __restrict__ bsc,
                            float* __restrict__ out)
{
    const int r = blockIdx.x;
    const int j = threadIdx.x;   // 64 threads
    __shared__ float sy[256];
    __shared__ float red[2];

    const float* y1 = g_scratch + OFF_Y1 + (long)r * 256;
    for (int k = j; k < 256; k += 64) sy[k] = fmaxf(y1[k], 0.f);
    __syncthreads();

    float acc = __ldg(&bl1[j]);
    #pragma unroll 8
    for (int k = 0; k < 256; ++k) acc += sy[k] * __ldg(&Wl1[k*64 + j]);

    float v = fmaxf(acc, 0.f) * __ldg(&Wsc[j]);
    #pragma unroll
    for (int off = 16; off > 0; off >>= 1)
        v += __shfl_down_sync(0xffffffffu, v, off);
    if ((j & 31) == 0) red[j >> 5] = v;
    __syncthreads();
    if (j == 0) {
        float s = red[0] + red[1] + __ldg(&bsc[0]);
        out[r] = 1.f / (1.f + expf(-s));
    }
}

// ---------------------------------------------------------------------------
// Launch
// ---------------------------------------------------------------------------
#define PAIR_SMEM (14464*4)
#define G1_SMEM ((2*AS_SZ + 2*BS_SZ)*4)

extern "C" void kernel_launch(void* const* d_in, const int* in_sizes, int n_in,
                              void* d_out, int out_size)
{
    (void)in_sizes; (void)n_in; (void)out_size;
    const float* x_q  = (const float*)d_in[0];
    const float* x_c  = (const float*)d_in[1];
    const int*   src_q = (const int*)d_in[2];
    const int*   dst_q = (const int*)d_in[3];
    const int*   src_c = (const int*)d_in[4];
    const int*   dst_c = (const int*)d_in[5];
    const float* Wg0 = (const float*)d_in[6];
    const float* bg0 = (const float*)d_in[7];
    const float* Wg1 = (const float*)d_in[8];
    const float* bg1 = (const float*)d_in[9];
    const float* Wg2 = (const float*)d_in[10];
    const float* bg2 = (const float*)d_in[11];
    const float* cw0 = (const float*)d_in[12];
    const float* cb0 = (const float*)d_in[13];
    const float* cw1 = (const float*)d_in[14];
    const float* cb1 = (const float*)d_in[15];
    const float* Wl0 = (const float*)d_in[16];
    const float* bl0 = (const float*)d_in[17];
    const float* Wl1 = (const float*)d_in[18];
    const float* bl1 = (const float*)d_in[19];
    const float* Wsc = (const float*)d_in[20];
    const float* bsc = (const float*)d_in[21];
    float* out = (float*)d_out;

    static int attr_done = 0;
    if (!attr_done) {
        cudaFuncSetAttribute(pair_all,  cudaFuncAttributeMaxDynamicSharedMemorySize, PAIR_SMEM);
        cudaFuncSetAttribute(gemm1_kernel, cudaFuncAttributeMaxDynamicSharedMemorySize, G1_SMEM);
        attr_done = 1;
    }

    // independent prep work first
    init_y1<<<512, 256>>>(bl0);
    cvt_wl0_kernel<<<3072, 256>>>(Wl0);

    // fused 3-layer GCN (q + c in one grid)
    gcn_all<<<2*NB_GRAPHS, 256>>>(x_q, x_c, Wg0, bg0, Wg1, bg1, Wg2, bg2,
                                  src_q, dst_q, src_c, dst_c);

    // fused sim + conv stacks (all 3 sims)
    pair_all<<<3*NB_GRAPHS, 256, PAIR_SMEM>>>(cw0, cb0, cw1, cb1);

    // MLP layer 0 on tensor cores, then head
    gemm1_kernel<<<dim3(4, 4, 16), 256, G1_SMEM>>>();
    head_kernel<<<512, 64>>>(Wl1, bl1, Wsc, bsc, out);
}

// round 8
// speedup vs baseline: 2.8286x; 1.1655x over previous
#include <cuda_runtime.h>
#include <math.h>

// ---------------------------------------------------------------------------
// Problem constants
// ---------------------------------------------------------------------------
#define NB_GRAPHS 512          // B
#define M_NODES   64           // nodes per graph
#define EPG       512          // edges per graph

// ---------------------------------------------------------------------------
// Scratch layout (single __device__ array, no allocations)
// ---------------------------------------------------------------------------
#define SZ_F0 (32768*64)
#define SZ_F1 (32768*32)
#define SZ_F2 (32768*16)
#define SZ_H  (512*12288)
#define SZ_Y1 (512*256)
#define SZ_WT0 (12288*256)

#define OFF_FQ0 0
#define OFF_FC0 (OFF_FQ0 + SZ_F0)
#define OFF_FQ1 (OFF_FC0 + SZ_F0)
#define OFF_FC1 (OFF_FQ1 + SZ_F1)
#define OFF_FQ2 (OFF_FC1 + SZ_F1)
#define OFF_FC2 (OFF_FQ2 + SZ_F2)
#define OFF_H   (OFF_FC2 + SZ_F2)
#define OFF_Y1  (OFF_H + SZ_H)
#define OFF_WT0 (OFF_Y1 + SZ_Y1)
#define SCRATCH_TOTAL (OFF_WT0 + SZ_WT0)

__device__ float g_scratch[SCRATCH_TOTAL];

// ---------------------------------------------------------------------------
// Helpers
// ---------------------------------------------------------------------------
typedef unsigned long long u64;

__device__ __forceinline__ u64 pack2(float lo, float hi) {
    u64 r; asm("mov.b64 %0, {%1,%2};" : "=l"(r) : "f"(lo), "f"(hi)); return r;
}
__device__ __forceinline__ u64 fma2(u64 a, u64 b, u64 c) {
    u64 d; asm("fma.rn.f32x2 %0, %1, %2, %3;" : "=l"(d) : "l"(a), "l"(b), "l"(c));
    return d;
}
__device__ __forceinline__ float2 unpack2(u64 v) {
    float lo, hi; asm("mov.b64 {%0,%1}, %2;" : "=f"(lo), "=f"(hi) : "l"(v));
    return make_float2(lo, hi);
}
__device__ __forceinline__ unsigned f2tf32(float f) {
    unsigned u; asm("cvt.rna.tf32.f32 %0, %1;" : "=r"(u) : "f"(f)); return u;
}
__device__ __forceinline__ float tf32f(float f) {
    return __uint_as_float(f2tf32(f));
}
__device__ __forceinline__ void cp_async16(float* dst, const float* src) {
    unsigned d = (unsigned)__cvta_generic_to_shared(dst);
    asm volatile("cp.async.cg.shared.global [%0], [%1], 16;" :: "r"(d), "l"(src));
}
__device__ __forceinline__ void mma_tf32(float c[4],
    unsigned a0, unsigned a1, unsigned a2, unsigned a3,
    unsigned b0, unsigned b1)
{
    asm volatile(
        "mma.sync.aligned.m16n8k8.row.col.f32.tf32.tf32.f32 "
        "{%0,%1,%2,%3}, {%4,%5,%6,%7}, {%8,%9}, {%0,%1,%2,%3};"
        : "+f"(c[0]), "+f"(c[1]), "+f"(c[2]), "+f"(c[3])
        : "r"(a0), "r"(a1), "r"(a2), "r"(a3), "r"(b0), "r"(b1));
}

// ---------------------------------------------------------------------------
// GCN layer body (float4-vectorized GEMM; same accumulation order as before)
// ---------------------------------------------------------------------------
template<int FIN, int FOUT>
__device__ __forceinline__ void gcn_layer_body(
    const float* __restrict__ sx, float* __restrict__ sA, float* __restrict__ sout,
    const float* __restrict__ sdinv,
    const int* __restrict__ sstart, const int* __restrict__ ssrc,
    const float* __restrict__ W, const float* __restrict__ bias,
    float* __restrict__ outg, int t)
{
    {
        const int j = t % FOUT;
        float wcol[FIN];
        #pragma unroll
        for (int k = 0; k < FIN; ++k) wcol[k] = __ldg(&W[k*FOUT + j]);
        for (int i = t; i < 64*FOUT; i += 256) {
            int n = i / FOUT;
            const float4* xr = (const float4*)(sx + n*FIN);
            float acc = 0.f;
            #pragma unroll
            for (int k4 = 0; k4 < FIN/4; ++k4) {
                float4 xv = xr[k4];
                acc += xv.x*wcol[4*k4] + xv.y*wcol[4*k4+1]
                     + xv.z*wcol[4*k4+2] + xv.w*wcol[4*k4+3];
            }
            sA[i] = acc * sdinv[n];
        }
    }
    __syncthreads();

    {
        const int wp = t >> 5, lane = t & 31;
        constexpr int CH = (FOUT + 31) / 32;
        for (int d = wp; d < 64; d += 8) {
            const int e0 = sstart[d], e1 = sstart[d + 1];
            const float dv = sdinv[d];
            float a[CH];
            #pragma unroll
            for (int c = 0; c < CH; ++c) {
                int j = lane + 32*c;
                a[c] = (j < FOUT) ? sA[d*FOUT + j] : 0.f;
            }
            for (int e = e0; e < e1; ++e) {
                int s = ssrc[e];
                #pragma unroll
                for (int c = 0; c < CH; ++c) {
                    int j = lane + 32*c;
                    if (j < FOUT) a[c] += sA[s*FOUT + j];
                }
            }
            #pragma unroll
            for (int c = 0; c < CH; ++c) {
                int j = lane + 32*c;
                if (j < FOUT) sout[d*FOUT + j] = dv*a[c] + __ldg(&bias[j]);
            }
        }
    }
    __syncthreads();

    for (int i = t; i < 64*FOUT; i += 256)
        outg[i] = sout[i];
}

// ---------------------------------------------------------------------------
// prep_all: blocks [0,1024) = fused 3-layer GCN (one block per graph);
//           blocks [1024,1536) = y1 bias init;
//           blocks [1536,4608) = Wl0 tf32 pre-round.
// ---------------------------------------------------------------------------
__global__ void __launch_bounds__(256) prep_all(
    const float* __restrict__ xq, const float* __restrict__ xc,
    const float* __restrict__ Wg0, const float* __restrict__ bg0,
    const float* __restrict__ Wg1, const float* __restrict__ bg1,
    const float* __restrict__ Wg2, const float* __restrict__ bg2,
    const int* __restrict__ srcq, const int* __restrict__ dstq,
    const int* __restrict__ srcc, const int* __restrict__ dstc,
    const float* __restrict__ bl0, const float* __restrict__ Wl0)
{
    __shared__ __align__(16) float pool[10240];
    __shared__ int   ssrc[EPG];
    __shared__ int   sstart[65];
    __shared__ int   scnt[64];
    __shared__ float sdinv[64];

    const int b = blockIdx.x;
    const int t = threadIdx.x;

    if (b >= 2*NB_GRAPHS) {
        if (b < 2*NB_GRAPHS + 512) {
            int i = (b - 2*NB_GRAPHS)*256 + t;
            g_scratch[OFF_Y1 + i] = __ldg(&bl0[i & 255]);
        } else {
            int i = (b - (2*NB_GRAPHS + 512))*256 + t;   // float4 index
            float4 v = ((const float4*)Wl0)[i];
            float4 o;
            o.x = tf32f(v.x); o.y = tf32f(v.y); o.z = tf32f(v.z); o.w = tf32f(v.w);
            ((float4*)(g_scratch + OFF_WT0))[i] = o;
        }
        return;
    }

    const bool isC = (b >= NB_GRAPHS);
    const int gg  = isC ? b - NB_GRAPHS : b;
    const float* x = isC ? xc : xq;
    const int* src = isC ? srcc : srcq;
    const int* dst = isC ? dstc : dstq;

    const int nb = gg * M_NODES;
    const int eb = gg * EPG;

    if (t < 64) scnt[t] = 0;
    __syncthreads();

    for (int e = t; e < EPG; e += 256)
        atomicAdd(&scnt[dst[eb + e] - nb], 1);
    for (int i = t; i < 64*32; i += 256) pool[i] = x[(long)nb*32 + i];
    __syncthreads();

    if (t == 0) {
        int a = 0;
        for (int i = 0; i < 64; ++i) { sstart[i] = a; a += scnt[i]; }
        sstart[64] = a;
    }
    __syncthreads();
    if (t < 64) {
        scnt[t] = sstart[t];
        sdinv[t] = rsqrtf(1.0f + (float)(sstart[t + 1] - sstart[t]));
    }
    __syncthreads();

    for (int e = t; e < EPG; e += 256) {
        int d = dst[eb + e] - nb;
        int s = src[eb + e] - nb;
        int p = atomicAdd(&scnt[d], 1);
        ssrc[p] = s;
    }
    __syncthreads();

    gcn_layer_body<32,64>(pool, pool+2048, pool+6144, sdinv, sstart, ssrc,
                          Wg0, bg0, g_scratch + (isC?OFF_FC0:OFF_FQ0) + (long)nb*64, t);
    for (int i = t; i < 64*64; i += 256) pool[i] = fmaxf(pool[6144 + i], 0.f);
    __syncthreads();

    gcn_layer_body<64,32>(pool, pool+4096, pool+6144, sdinv, sstart, ssrc,
                          Wg1, bg1, g_scratch + (isC?OFF_FC1:OFF_FQ1) + (long)nb*32, t);
    for (int i = t; i < 64*32; i += 256) pool[i] = fmaxf(pool[6144 + i], 0.f);
    __syncthreads();

    gcn_layer_body<32,16>(pool, pool+2048, pool+3072, sdinv, sstart, ssrc,
                          Wg2, bg2, g_scratch + (isC?OFF_FC2:OFF_FQ2) + (long)nb*16, t);
}

// ---------------------------------------------------------------------------
// conv0 helper: o-paired f32x2, row-streamed (verified vs R4-passing version)
// acc[u][v] : 4x4 spatial, each u64 = (o_lo, o_hi)
// ---------------------------------------------------------------------------
__device__ __forceinline__ void conv5x5_opair64(
    const float* __restrict__ plane, const u64* __restrict__ wq,
    u64 acc[4][4], int y0, int x0)
{
    #pragma unroll
    for (int dy = 0; dy < 8; ++dy) {
        const int yy = y0 + dy;
        const bool rowok = ((unsigned)yy < 64u);
        u64 sp[8];
        #pragma unroll
        for (int j = 0; j < 4; ++j) {
            int xx = x0 + 2*j;
            float2 v = make_float2(0.f, 0.f);
            if (rowok && (unsigned)xx < 64u)
                v = *(const float2*)(plane + yy*64 + xx);
            sp[2*j]   = pack2(v.x, v.x);
            sp[2*j+1] = pack2(v.y, v.y);
        }
        #pragma unroll
        for (int u = 0; u < 4; ++u) {
            const int ky = dy - u;
            if (ky >= 0 && ky < 5) {
                #pragma unroll
                for (int kx = 0; kx < 5; ++kx) {
                    u64 w = wq[ky*5 + kx];
                    #pragma unroll
                    for (int v = 0; v < 4; ++v)
                        acc[u][v] = fma2(sp[v + kx], w, acc[u][v]);
                }
            }
        }
    }
}

// ---------------------------------------------------------------------------
// Fused pair kernel: sim GEMM (f32x2, k-vectorized) + conv0 (f32x2 o-paired)
// + conv1 (tf32 mma, per-channel halo planes — R5 proven path)
//
// Dynamic smem buf (14464 floats):
//   sim    : [0,4096)        phase 1-2; reused for sw1 in phase 3
//   sq/scT : [4096,12288)    phase 0-1
//   planes : [4096,14464)    phase 2-3b (8 ch x 36x36 halo, tf32)
//   praw   : [4096,9216)     phase 3c pool staging
// ---------------------------------------------------------------------------
__global__ void __launch_bounds__(256, 2) pair_all(
    const float* __restrict__ cw0, const float* __restrict__ cb0,
    const float* __restrict__ cw1, const float* __restrict__ cb1)
{
    extern __shared__ __align__(16) float buf[];
    __shared__ u64 sw0u[100];   // conv0 weights as (o,o+1) pairs: [op*25 + tap]
    __shared__ int soff[200];

    float* sim    = buf;
    float* sq     = buf + 4096;
    float* scT    = buf + 8192;
    float* planes = buf + 4096;
    float* praw   = buf + 4096;
    float* sw1    = buf;

    const int simi = blockIdx.x % 3;
    const int bk   = blockIdx.x / 3;
    const int lf   = 6 - simi;               // log2(F)
    const int F    = 1 << lf;                // 64, 32, 16
    const int offq = (simi == 0) ? OFF_FQ0 : (simi == 1) ? OFF_FQ1 : OFF_FQ2;
    const int offc = (simi == 0) ? OFF_FC0 : (simi == 1) ? OFF_FC1 : OFF_FC2;
    const float* cw0p = cw0 + simi*200;
    const float* cb0p = cb0 + simi*8;
    const float* cw1p = cw1 + simi*3200;
    const float* cb1p = cb1 + simi*16;

    const int t = threadIdx.x;
    const float* fq = g_scratch + offq + ((long)bk << (6 + lf));
    const float* fc = g_scratch + offc + ((long)bk << (6 + lf));

    // ---- phase 0: stage features + conv0 weights (o-paired) + tap offsets ----
    for (int i = t; i < (64 << lf); i += 256) sq[i] = fq[i];
    for (int i = t; i < (64 << lf); i += 256) {
        int n = i >> lf, k = i & (F - 1);
        scT[k*64 + (n ^ (k & 28))] = fc[i];
    }
    if (t < 100) {
        int op = t / 25, tap = t % 25;
        sw0u[t] = pack2(__ldg(&cw0p[(2*op)*25 + tap]),
                        __ldg(&cw0p[(2*op + 1)*25 + tap]));
    }
    for (int i = t; i < 200; i += 256) {
        int c = i / 25, rem = i - c*25;
        soff[i] = c*1296 + (rem/5)*36 + (rem%5);
    }
    __syncthreads();

    // ---- phase 1: similarity GEMM (f32x2, float4 A loads) -> sim[64][64] ----
    {
        const int m0 = (t >> 4) << 2;
        const int n0 = (t & 15) << 2;
        u64 acc[4][2] = {};
        for (int kb = 0; kb < (F >> 2); ++kb) {
            float aa[4][4];   // [j][u]
            #pragma unroll
            for (int u = 0; u < 4; ++u) {
                float4 v = *(const float4*)&sq[((m0+u) << lf) + 4*kb];
                aa[0][u] = v.x; aa[1][u] = v.y; aa[2][u] = v.z; aa[3][u] = v.w;
            }
            #pragma unroll
            for (int j = 0; j < 4; ++j) {
                const int k = 4*kb + j;
                const int s = k & 28;
                u64 bp0 = *(const u64*)&scT[k*64 + (n0 ^ s)];
                u64 bp1 = *(const u64*)&scT[k*64 + ((n0 ^ s) + 2)];
                #pragma unroll
                for (int u = 0; u < 4; ++u) {
                    u64 ap = pack2(aa[j][u], aa[j][u]);
                    acc[u][0] = fma2(bp0, ap, acc[u][0]);
                    acc[u][1] = fma2(bp1, ap, acc[u][1]);
                }
            }
        }
        #pragma unroll
        for (int u = 0; u < 4; ++u)
            #pragma unroll
            for (int vp = 0; vp < 2; ++vp)
                *(float2*)&sim[(m0+u)*64 + n0 + 2*vp] = unpack2(acc[u][vp]);
    }
    __syncthreads();

    // ---- phase 2a: zero halo-padded planes ----
    for (int i = t; i < 10368; i += 256) planes[i] = 0.f;
    __syncthreads();

    // ---- phase 2b: conv0 (1->8, o-paired) + relu + pool -> planes (tf32) ----
    {
        const int ty = t >> 4, tx = t & 15;
        const int y0 = 4*ty - 2, x0 = 4*tx - 2;
        for (int op = 0; op < 4; ++op) {
            u64 wq[25];
            #pragma unroll
            for (int i = 0; i < 25; ++i) wq[i] = sw0u[op*25 + i];
            u64 binit = pack2(__ldg(&cb0p[2*op]), __ldg(&cb0p[2*op + 1]));
            u64 acc[4][4];
            #pragma unroll
            for (int u = 0; u < 4; ++u)
                #pragma unroll
                for (int v = 0; v < 4; ++v) acc[u][v] = binit;
            conv5x5_opair64(sim, wq, acc, y0, x0);
            #pragma unroll
            for (int a = 0; a < 2; ++a)
                #pragma unroll
                for (int b = 0; b < 2; ++b) {
                    float2 p00 = unpack2(acc[2*a][2*b]);
                    float2 p01 = unpack2(acc[2*a][2*b+1]);
                    float2 p10 = unpack2(acc[2*a+1][2*b]);
                    float2 p11 = unpack2(acc[2*a+1][2*b+1]);
                    float mlo = fmaxf(fmaxf(p00.x, p01.x), fmaxf(p10.x, p11.x));
                    float mhi = fmaxf(fmaxf(p00.y, p01.y), fmaxf(p10.y, p11.y));
                    int pix = (2 + 2*ty + a)*36 + (2 + 2*tx + b);
                    planes[(2*op)*1296 + pix]     = tf32f(fmaxf(mlo, 0.f));
                    planes[(2*op + 1)*1296 + pix] = tf32f(fmaxf(mhi, 0.f));
                }
        }
    }
    __syncthreads();

    // ---- phase 3a: stage conv1 weights [k][o] stride 17, tf32-rounded ----
    for (int i = t; i < 3200; i += 256) {
        int k = i >> 4, o = i & 15;
        sw1[k*17 + o] = tf32f(__ldg(&cw1p[o*200 + k]));
    }
    __syncthreads();

    // ---- phase 3b: conv1 as implicit GEMM, tf32 mma m16n8k8 (R5 proven) ----
    const int warp = t >> 5, lane = t & 31, g = lane >> 2, tig = lane & 3;
    float acc[8][2][4];
    #pragma unroll
    for (int mi = 0; mi < 8; ++mi)
        #pragma unroll
        for (int ni = 0; ni < 2; ++ni)
            #pragma unroll
            for (int r = 0; r < 4; ++r) acc[mi][ni][r] = 0.f;

    int base_m[8];
    #pragma unroll
    for (int mi = 0; mi < 8; ++mi) {
        int mt = warp*8 + mi;
        base_m[mi] = (mt >> 1)*36 + (mt & 1)*16 + g;
    }

    for (int kk = 0; kk < 25; ++kk) {
        const int klo = 8*kk + tig;
        const int offlo = soff[klo], offhi = soff[klo + 4];
        unsigned bf0[2], bf1[2];
        bf0[0] = __float_as_uint(sw1[klo*17 + g]);
        bf0[1] = __float_as_uint(sw1[(klo+4)*17 + g]);
        bf1[0] = __float_as_uint(sw1[klo*17 + 8 + g]);
        bf1[1] = __float_as_uint(sw1[(klo+4)*17 + 8 + g]);
        #pragma unroll
        for (int mi = 0; mi < 8; ++mi) {
            const float* p = planes + base_m[mi];
            unsigned a0 = __float_as_uint(p[offlo]);
            unsigned a1 = __float_as_uint(p[offlo + 8]);
            unsigned a2 = __float_as_uint(p[offhi]);
            unsigned a3 = __float_as_uint(p[offhi + 8]);
            mma_tf32(acc[mi][0], a0, a1, a2, a3, bf0[0], bf0[1]);
            mma_tf32(acc[mi][1], a0, a1, a2, a3, bf1[0], bf1[1]);
        }
    }
    __syncthreads();   // planes dead; praw region reusable

    // ---- phase 3c: pool via smem roundtrip (4 o-groups of 4) — R5 proven ----
    {
        float* hout = g_scratch + OFF_H + simi*4096 + (long)bk * 12288;
        for (int g2 = 0; g2 < 4; ++g2) {
            if ((tig >> 1) == (g2 & 1)) {
                const int j0 = (2*tig) & 3;   // 0 or 2
                const int ni = g2 >> 1;
                #pragma unroll
                for (int mi = 0; mi < 8; ++mi) {
                    int s0 = (warp*8 + mi)*16 + g;
                    praw[s0*5 + j0]         = acc[mi][ni][0];
                    praw[s0*5 + j0 + 1]     = acc[mi][ni][1];
                    praw[(s0+8)*5 + j0]     = acc[mi][ni][2];
                    praw[(s0+8)*5 + j0 + 1] = acc[mi][ni][3];
                }
            }
            __syncthreads();
            #pragma unroll
            for (int v = 0; v < 4; ++v) {
                int pid = v*256 + t;
                int ol = pid & 3, rest = pid >> 2;
                int X = rest & 15, Y = rest >> 4;
                int s00 = (2*Y)*32 + 2*X;
                float m = fmaxf(fmaxf(praw[s00*5 + ol], praw[(s00+1)*5 + ol]),
                                fmaxf(praw[(s00+32)*5 + ol], praw[(s00+33)*5 + ol]));
                m = fmaxf(m + __ldg(&cb1p[4*g2 + ol]), 0.f);
                hout[(4*g2 + ol)*256 + Y*16 + X] = tf32f(m);
            }
            __syncthreads();
        }
    }
}

// ---------------------------------------------------------------------------
// MLP layer 0: y1 += h @ Wl0. tf32 mma, cp.async double-buffered (R5 proven).
// ---------------------------------------------------------------------------
#define G1_KC 768
#define G1_KT 32
#define G1_NT 24
#define AS_STRIDE 36
#define BS_STRIDE 72
#define AS_SZ (128*AS_STRIDE)
#define BS_SZ (32*BS_STRIDE)

__global__ void __launch_bounds__(256) gemm1_kernel()
{
    extern __shared__ __align__(16) float gbuf[];
    const float* A = g_scratch + OFF_H;
    const float* B = g_scratch + OFF_WT0;
    float* C = g_scratch + OFF_Y1;

    const int r0 = blockIdx.x * 128;
    const int c0 = blockIdx.y * 64;
    const int k0 = blockIdx.z * G1_KC;

    const int t = threadIdx.x, warp = t >> 5, lane = t & 31;
    const int g = lane >> 2, tig = lane & 3;
    const int wm = warp & 3, wn = warp >> 2;

    float acc[2][4][4];
    #pragma unroll
    for (int mi = 0; mi < 2; ++mi)
        #pragma unroll
        for (int ni = 0; ni < 4; ++ni)
            #pragma unroll
            for (int r = 0; r < 4; ++r) acc[mi][ni][r] = 0.f;

    auto issue = [&](int ibuf, int kt) {
        float* As = gbuf + ibuf*AS_SZ;
        float* Bs = gbuf + 2*AS_SZ + ibuf*BS_SZ;
        #pragma unroll
        for (int j = 0; j < 4; ++j) {
            int cid = t + 256*j;
            int row = cid >> 3, seg = cid & 7;
            cp_async16(&As[row*AS_STRIDE + seg*4],
                       A + (long)(r0 + row)*12288 + k0 + kt + seg*4);
        }
        #pragma unroll
        for (int j = 0; j < 2; ++j) {
            int cid = t + 256*j;
            int k = cid >> 4, seg = cid & 15;
            cp_async16(&Bs[k*BS_STRIDE + seg*4],
                       B + (long)(k0 + kt + k)*256 + c0 + seg*4);
        }
        asm volatile("cp.async.commit_group;");
    };

    issue(0, 0);
    issue(1, G1_KT);

    for (int i = 0; i < G1_NT; ++i) {
        if (i < G1_NT - 1) asm volatile("cp.async.wait_group 1;");
        else               asm volatile("cp.async.wait_group 0;");
        __syncthreads();

        const float* As = gbuf + (i & 1)*AS_SZ;
        const float* Bs = gbuf + 2*AS_SZ + (i & 1)*BS_SZ;
        #pragma unroll
        for (int kc = 0; kc < 4; ++kc) {
            unsigned af[2][4], bf[4][2];
            #pragma unroll
            for (int mi = 0; mi < 2; ++mi) {
                const float* ap = As + (wm*32 + mi*16 + g)*AS_STRIDE + kc*8 + tig;
                af[mi][0] = __float_as_uint(ap[0]);
                af[mi][1] = __float_as_uint(ap[8*AS_STRIDE]);
                af[mi][2] = __float_as_uint(ap[4]);
                af[mi][3] = __float_as_uint(ap[8*AS_STRIDE + 4]);
            }
            #pragma unroll
            for (int ni = 0; ni < 4; ++ni) {
                const float* bp = Bs + (kc*8 + tig)*BS_STRIDE + wn*32 + ni*8 + g;
                bf[ni][0] = __float_as_uint(bp[0]);
                bf[ni][1] = __float_as_uint(bp[4*BS_STRIDE]);
            }
            #pragma unroll
            for (int mi = 0; mi < 2; ++mi)
                #pragma unroll
                for (int ni = 0; ni < 4; ++ni)
                    mma_tf32(acc[mi][ni], af[mi][0], af[mi][1], af[mi][2], af[mi][3],
                             bf[ni][0], bf[ni][1]);
        }
        __syncthreads();
        if (i + 2 < G1_NT) issue(i & 1, (i + 2)*G1_KT);
    }

    #pragma unroll
    for (int mi = 0; mi < 2; ++mi) {
        int R = r0 + wm*32 + mi*16 + g;
        #pragma unroll
        for (int ni = 0; ni < 4; ++ni) {
            int Cc = c0 + wn*32 + ni*8 + 2*tig;
            atomicAdd(&C[R*256 + Cc],         acc[mi][ni][0]);
            atomicAdd(&C[R*256 + Cc + 1],     acc[mi][ni][1]);
            atomicAdd(&C[(R+8)*256 + Cc],     acc[mi][ni][2]);
            atomicAdd(&C[(R+8)*256 + Cc + 1], acc[mi][ni][3]);
        }
    }
}

// ---------------------------------------------------------------------------
// Head: relu(y1) @ Wl1 + bl1 -> relu -> @ Wsc + bsc -> sigmoid. One block/row.
// ---------------------------------------------------------------------------
__global__ void head_kernel(const float* __restrict__ Wl1, const float* __restrict__ bl1,
                            const float* __restrict__ Wsc, const float* __restrict__ bsc,
                            float* __restrict__ out)
{
    const int r = blockIdx.x;
    const int j = threadIdx.x;   // 64 threads
    __shared__ float sy[256];
    __shared__ float red[2];

    const float* y1 = g_scratch + OFF_Y1 + (long)r * 256;
    for (int k = j; k < 256; k += 64) sy[k] = fmaxf(y1[k], 0.f);
    __syncthreads();

    float acc = __ldg(&bl1[j]);
    #pragma unroll 8
    for (int k = 0; k < 256; ++k) acc += sy[k] * __ldg(&Wl1[k*64 + j]);

    float v = fmaxf(acc, 0.f) * __ldg(&Wsc[j]);
    #pragma unroll
    for (int off = 16; off > 0; off >>= 1)
        v += __shfl_down_sync(0xffffffffu, v, off);
    if ((j & 31) == 0) red[j >> 5] = v;
    __syncthreads();
    if (j == 0) {
        float s = red[0] + red[1] + __ldg(&bsc[0]);
        out[r] = 1.f / (1.f + expf(-s));
    }
}

// ---------------------------------------------------------------------------
// Launch
// ---------------------------------------------------------------------------
#define PAIR_SMEM (14464*4)
#define G1_SMEM ((2*AS_SZ + 2*BS_SZ)*4)

extern "C" void kernel_launch(void* const* d_in, const int* in_sizes, int n_in,
                              void* d_out, int out_size)
{
    (void)in_sizes; (void)n_in; (void)out_size;
    const float* x_q  = (const float*)d_in[0];
    const float* x_c  = (const float*)d_in[1];
    const int*   src_q = (const int*)d_in[2];
    const int*   dst_q = (const int*)d_in[3];
    const int*   src_c = (const int*)d_in[4];
    const int*   dst_c = (const int*)d_in[5];
    const float* Wg0 = (const float*)d_in[6];
    const float* bg0 = (const float*)d_in[7];
    const float* Wg1 = (const float*)d_in[8];
    const float* bg1 = (const float*)d_in[9];
    const float* Wg2 = (const float*)d_in[10];
    const float* bg2 = (const float*)d_in[11];
    const float* cw0 = (const float*)d_in[12];
    const float* cb0 = (const float*)d_in[13];
    const float* cw1 = (const float*)d_in[14];
    const float* cb1 = (const float*)d_in[15];
    const float* Wl0 = (const float*)d_in[16];
    const float* bl0 = (const float*)d_in[17];
    const float* Wl1 = (const float*)d_in[18];
    const float* bl1 = (const float*)d_in[19];
    const float* Wsc = (const float*)d_in[20];
    const float* bsc = (const float*)d_in[21];
    float* out = (float*)d_out;

    static int attr_done = 0;
    if (!attr_done) {
        cudaFuncSetAttribute(pair_all,  cudaFuncAttributeMaxDynamicSharedMemorySize, PAIR_SMEM);
        cudaFuncSetAttribute(gemm1_kernel, cudaFuncAttributeMaxDynamicSharedMemorySize, G1_SMEM);
        attr_done = 1;
    }

    // fused: 3-layer GCN (1024 blocks) + y1 bias init (512) + Wl0 tf32 (3072)
    prep_all<<<2*NB_GRAPHS + 512 + 3072, 256>>>(
        x_q, x_c, Wg0, bg0, Wg1, bg1, Wg2, bg2,
        src_q, dst_q, src_c, dst_c, bl0, Wl0);

    // fused sim + conv stacks (all 3 sims)
    pair_all<<<3*NB_GRAPHS, 256, PAIR_SMEM>>>(cw0, cb0, cw1, cb1);

    // MLP layer 0 on tensor cores, then head
    gemm1_kernel<<<dim3(4, 4, 16), 256, G1_SMEM>>>();
    head_kernel<<<512, 64>>>(Wl1, bl1, Wsc, bsc, out);
}

// round 9
// speedup vs baseline: 2.9487x; 1.0425x over previous
#include <cuda_runtime.h>
#include <math.h>

// ---------------------------------------------------------------------------
// Problem constants
// ---------------------------------------------------------------------------
#define NB_GRAPHS 512          // B
#define M_NODES   64           // nodes per graph
#define EPG       512          // edges per graph

// ---------------------------------------------------------------------------
// Scratch layout (single __device__ array, no allocations)
// ---------------------------------------------------------------------------
#define SZ_F0 (32768*64)
#define SZ_F1 (32768*32)
#define SZ_F2 (32768*16)
#define SZ_H  (512*12288)
#define SZ_Y1 (512*256)
#define SZ_WT0 (12288*256)

#define OFF_FQ0 0
#define OFF_FC0 (OFF_FQ0 + SZ_F0)
#define OFF_FQ1 (OFF_FC0 + SZ_F0)
#define OFF_FC1 (OFF_FQ1 + SZ_F1)
#define OFF_FQ2 (OFF_FC1 + SZ_F1)
#define OFF_FC2 (OFF_FQ2 + SZ_F2)
#define OFF_H   (OFF_FC2 + SZ_F2)
#define OFF_Y1  (OFF_H + SZ_H)
#define OFF_WT0 (OFF_Y1 + SZ_Y1)
#define SCRATCH_TOTAL (OFF_WT0 + SZ_WT0)

__device__ float g_scratch[SCRATCH_TOTAL];

// ---------------------------------------------------------------------------
// Helpers
// ---------------------------------------------------------------------------
typedef unsigned long long u64;

__device__ __forceinline__ u64 pack2(float lo, float hi) {
    u64 r; asm("mov.b64 %0, {%1,%2};" : "=l"(r) : "f"(lo), "f"(hi)); return r;
}
__device__ __forceinline__ u64 fma2(u64 a, u64 b, u64 c) {
    u64 d; asm("fma.rn.f32x2 %0, %1, %2, %3;" : "=l"(d) : "l"(a), "l"(b), "l"(c));
    return d;
}
__device__ __forceinline__ float2 unpack2(u64 v) {
    float lo, hi; asm("mov.b64 {%0,%1}, %2;" : "=f"(lo), "=f"(hi) : "l"(v));
    return make_float2(lo, hi);
}
__device__ __forceinline__ unsigned f2tf32(float f) {
    unsigned u; asm("cvt.rna.tf32.f32 %0, %1;" : "=r"(u) : "f"(f)); return u;
}
__device__ __forceinline__ float tf32f(float f) {
    return __uint_as_float(f2tf32(f));
}
__device__ __forceinline__ void cp_async16(float* dst, const float* src) {
    unsigned d = (unsigned)__cvta_generic_to_shared(dst);
    asm volatile("cp.async.cg.shared.global [%0], [%1], 16;" :: "r"(d), "l"(src));
}
__device__ __forceinline__ void mma_tf32(float c[4],
    unsigned a0, unsigned a1, unsigned a2, unsigned a3,
    unsigned b0, unsigned b1)
{
    asm volatile(
        "mma.sync.aligned.m16n8k8.row.col.f32.tf32.tf32.f32 "
        "{%0,%1,%2,%3}, {%4,%5,%6,%7}, {%8,%9}, {%0,%1,%2,%3};"
        : "+f"(c[0]), "+f"(c[1]), "+f"(c[2]), "+f"(c[3])
        : "r"(a0), "r"(a1), "r"(a2), "r"(a3), "r"(b0), "r"(b1));
}
__device__ __forceinline__ void ldsm_x4(unsigned& r0, unsigned& r1,
                                        unsigned& r2, unsigned& r3, unsigned addr)
{
    asm volatile("ldmatrix.sync.aligned.m8n8.x4.shared.b16 {%0,%1,%2,%3}, [%4];"
        : "=r"(r0), "=r"(r1), "=r"(r2), "=r"(r3) : "r"(addr));
}

// ---------------------------------------------------------------------------
// GCN layer body (float4-vectorized GEMM)
// ---------------------------------------------------------------------------
template<int FIN, int FOUT>
__device__ __forceinline__ void gcn_layer_body(
    const float* __restrict__ sx, float* __restrict__ sA, float* __restrict__ sout,
    const float* __restrict__ sdinv,
    const int* __restrict__ sstart, const int* __restrict__ ssrc,
    const float* __restrict__ W, const float* __restrict__ bias,
    float* __restrict__ outg, int t)
{
    {
        const int j = t % FOUT;
        float wcol[FIN];
        #pragma unroll
        for (int k = 0; k < FIN; ++k) wcol[k] = __ldg(&W[k*FOUT + j]);
        for (int i = t; i < 64*FOUT; i += 256) {
            int n = i / FOUT;
            const float4* xr = (const float4*)(sx + n*FIN);
            float acc = 0.f;
            #pragma unroll
            for (int k4 = 0; k4 < FIN/4; ++k4) {
                float4 xv = xr[k4];
                acc += xv.x*wcol[4*k4] + xv.y*wcol[4*k4+1]
                     + xv.z*wcol[4*k4+2] + xv.w*wcol[4*k4+3];
            }
            sA[i] = acc * sdinv[n];
        }
    }
    __syncthreads();

    {
        const int wp = t >> 5, lane = t & 31;
        constexpr int CH = (FOUT + 31) / 32;
        for (int d = wp; d < 64; d += 8) {
            const int e0 = sstart[d], e1 = sstart[d + 1];
            const float dv = sdinv[d];
            float a[CH];
            #pragma unroll
            for (int c = 0; c < CH; ++c) {
                int j = lane + 32*c;
                a[c] = (j < FOUT) ? sA[d*FOUT + j] : 0.f;
            }
            for (int e = e0; e < e1; ++e) {
                int s = ssrc[e];
                #pragma unroll
                for (int c = 0; c < CH; ++c) {
                    int j = lane + 32*c;
                    if (j < FOUT) a[c] += sA[s*FOUT + j];
                }
            }
            #pragma unroll
            for (int c = 0; c < CH; ++c) {
                int j = lane + 32*c;
                if (j < FOUT) sout[d*FOUT + j] = dv*a[c] + __ldg(&bias[j]);
            }
        }
    }
    __syncthreads();

    for (int i = t; i < 64*FOUT; i += 256)
        outg[i] = sout[i];
}

// ---------------------------------------------------------------------------
// prep_all: [0,1024) GCN; [1024,1536) y1 bias init; [1536,4608) Wl0 tf32.
// ---------------------------------------------------------------------------
__global__ void __launch_bounds__(256) prep_all(
    const float* __restrict__ xq, const float* __restrict__ xc,
    const float* __restrict__ Wg0, const float* __restrict__ bg0,
    const float* __restrict__ Wg1, const float* __restrict__ bg1,
    const float* __restrict__ Wg2, const float* __restrict__ bg2,
    const int* __restrict__ srcq, const int* __restrict__ dstq,
    const int* __restrict__ srcc, const int* __restrict__ dstc,
    const float* __restrict__ bl0, const float* __restrict__ Wl0)
{
    __shared__ __align__(16) float pool[10240];
    __shared__ int   ssrc[EPG];
    __shared__ int   sstart[65];
    __shared__ int   scnt[64];
    __shared__ float sdinv[64];

    const int b = blockIdx.x;
    const int t = threadIdx.x;

    if (b >= 2*NB_GRAPHS) {
        if (b < 2*NB_GRAPHS + 512) {
            int i = (b - 2*NB_GRAPHS)*256 + t;
            g_scratch[OFF_Y1 + i] = __ldg(&bl0[i & 255]);
        } else {
            int i = (b - (2*NB_GRAPHS + 512))*256 + t;   // float4 index
            float4 v = ((const float4*)Wl0)[i];
            float4 o;
            o.x = tf32f(v.x); o.y = tf32f(v.y); o.z = tf32f(v.z); o.w = tf32f(v.w);
            ((float4*)(g_scratch + OFF_WT0))[i] = o;
        }
        return;
    }

    const bool isC = (b >= NB_GRAPHS);
    const int gg  = isC ? b - NB_GRAPHS : b;
    const float* x = isC ? xc : xq;
    const int* src = isC ? srcc : srcq;
    const int* dst = isC ? dstc : dstq;

    const int nb = gg * M_NODES;
    const int eb = gg * EPG;

    if (t < 64) scnt[t] = 0;
    __syncthreads();

    for (int e = t; e < EPG; e += 256)
        atomicAdd(&scnt[dst[eb + e] - nb], 1);
    for (int i = t; i < 64*32; i += 256) pool[i] = x[(long)nb*32 + i];
    __syncthreads();

    if (t == 0) {
        int a = 0;
        for (int i = 0; i < 64; ++i) { sstart[i] = a; a += scnt[i]; }
        sstart[64] = a;
    }
    __syncthreads();
    if (t < 64) {
        scnt[t] = sstart[t];
        sdinv[t] = rsqrtf(1.0f + (float)(sstart[t + 1] - sstart[t]));
    }
    __syncthreads();

    for (int e = t; e < EPG; e += 256) {
        int d = dst[eb + e] - nb;
        int s = src[eb + e] - nb;
        int p = atomicAdd(&scnt[d], 1);
        ssrc[p] = s;
    }
    __syncthreads();

    gcn_layer_body<32,64>(pool, pool+2048, pool+6144, sdinv, sstart, ssrc,
                          Wg0, bg0, g_scratch + (isC?OFF_FC0:OFF_FQ0) + (long)nb*64, t);
    for (int i = t; i < 64*64; i += 256) pool[i] = fmaxf(pool[6144 + i], 0.f);
    __syncthreads();

    gcn_layer_body<64,32>(pool, pool+4096, pool+6144, sdinv, sstart, ssrc,
                          Wg1, bg1, g_scratch + (isC?OFF_FC1:OFF_FQ1) + (long)nb*32, t);
    for (int i = t; i < 64*32; i += 256) pool[i] = fmaxf(pool[6144 + i], 0.f);
    __syncthreads();

    gcn_layer_body<32,16>(pool, pool+2048, pool+3072, sdinv, sstart, ssrc,
                          Wg2, bg2, g_scratch + (isC?OFF_FC2:OFF_FQ2) + (long)nb*16, t);
}

// ---------------------------------------------------------------------------
// conv0 helper: o-paired f32x2, row-streamed (R7 proven)
// ---------------------------------------------------------------------------
__device__ __forceinline__ void conv5x5_opair64(
    const float* __restrict__ plane, const u64* __restrict__ wq,
    u64 acc[4][4], int y0, int x0)
{
    #pragma unroll
    for (int dy = 0; dy < 8; ++dy) {
        const int yy = y0 + dy;
        const bool rowok = ((unsigned)yy < 64u);
        u64 sp[8];
        #pragma unroll
        for (int j = 0; j < 4; ++j) {
            int xx = x0 + 2*j;
            float2 v = make_float2(0.f, 0.f);
            if (rowok && (unsigned)xx < 64u)
                v = *(const float2*)(plane + yy*64 + xx);
            sp[2*j]   = pack2(v.x, v.x);
            sp[2*j+1] = pack2(v.y, v.y);
        }
        #pragma unroll
        for (int u = 0; u < 4; ++u) {
            const int ky = dy - u;
            if (ky >= 0 && ky < 5) {
                #pragma unroll
                for (int kx = 0; kx < 5; ++kx) {
                    u64 w = wq[ky*5 + kx];
                    #pragma unroll
                    for (int v = 0; v < 4; ++v)
                        acc[u][v] = fma2(sp[v + kx], w, acc[u][v]);
                }
            }
        }
    }
}

// ---------------------------------------------------------------------------
// Fused pair kernel: sim GEMM (f32x2) + conv0 (f32x2 o-paired, interleaved
// write) + conv1 (tf32 mma, channel-interleaved planes, ldmatrix A feed)
//
// Dynamic smem buf (19648 floats = 78592 B):
//   sim    : [0,4096)        phase 1-2; reused for sw1 in phase 3
//   sq/scT : [4096,12288)    phase 0-1
//   planes : [4096,19648)    phase 2-3b (1296 pixels x stride 12, tf32,
//                            channels 0-7 interleaved per pixel)
//   praw   : [4096,9216)     phase 3c pool staging
// ---------------------------------------------------------------------------
__global__ void __launch_bounds__(256, 2) pair_all(
    const float* __restrict__ cw0, const float* __restrict__ cb0,
    const float* __restrict__ cw1, const float* __restrict__ cb1)
{
    extern __shared__ __align__(16) float buf[];
    __shared__ u64 sw0u[100];   // conv0 weights as (o,o+1) pairs: [op*25 + tap]

    float* sim    = buf;
    float* sq     = buf + 4096;
    float* scT    = buf + 8192;
    float* planes = buf + 4096;
    float* praw   = buf + 4096;
    float* sw1    = buf;        // [tap*136 + c*17 + o], 3398 floats

    const int simi = blockIdx.x % 3;
    const int bk   = blockIdx.x / 3;
    const int lf   = 6 - simi;               // log2(F)
    const int F    = 1 << lf;                // 64, 32, 16
    const int offq = (simi == 0) ? OFF_FQ0 : (simi == 1) ? OFF_FQ1 : OFF_FQ2;
    const int offc = (simi == 0) ? OFF_FC0 : (simi == 1) ? OFF_FC1 : OFF_FC2;
    const float* cw0p = cw0 + simi*200;
    const float* cb0p = cb0 + simi*8;
    const float* cw1p = cw1 + simi*3200;
    const float* cb1p = cb1 + simi*16;

    const int t = threadIdx.x;
    const float* fq = g_scratch + offq + ((long)bk << (6 + lf));
    const float* fc = g_scratch + offc + ((long)bk << (6 + lf));

    // ---- phase 0: stage features + conv0 weights (o-paired) ----
    for (int i = t; i < (64 << lf); i += 256) sq[i] = fq[i];
    for (int i = t; i < (64 << lf); i += 256) {
        int n = i >> lf, k = i & (F - 1);
        scT[k*64 + (n ^ (k & 28))] = fc[i];
    }
    if (t < 100) {
        int op = t / 25, tap = t % 25;
        sw0u[t] = pack2(__ldg(&cw0p[(2*op)*25 + tap]),
                        __ldg(&cw0p[(2*op + 1)*25 + tap]));
    }
    __syncthreads();

    // ---- phase 1: similarity GEMM (f32x2, float4 A loads) -> sim[64][64] ----
    {
        const int m0 = (t >> 4) << 2;
        const int n0 = (t & 15) << 2;
        u64 acc[4][2] = {};
        for (int kb = 0; kb < (F >> 2); ++kb) {
            float aa[4][4];   // [j][u]
            #pragma unroll
            for (int u = 0; u < 4; ++u) {
                float4 v = *(const float4*)&sq[((m0+u) << lf) + 4*kb];
                aa[0][u] = v.x; aa[1][u] = v.y; aa[2][u] = v.z; aa[3][u] = v.w;
            }
            #pragma unroll
            for (int j = 0; j < 4; ++j) {
                const int k = 4*kb + j;
                const int s = k & 28;
                u64 bp0 = *(const u64*)&scT[k*64 + (n0 ^ s)];
                u64 bp1 = *(const u64*)&scT[k*64 + ((n0 ^ s) + 2)];
                #pragma unroll
                for (int u = 0; u < 4; ++u) {
                    u64 ap = pack2(aa[j][u], aa[j][u]);
                    acc[u][0] = fma2(bp0, ap, acc[u][0]);
                    acc[u][1] = fma2(bp1, ap, acc[u][1]);
                }
            }
        }
        #pragma unroll
        for (int u = 0; u < 4; ++u)
            #pragma unroll
            for (int vp = 0; vp < 2; ++vp)
                *(float2*)&sim[(m0+u)*64 + n0 + 2*vp] = unpack2(acc[u][vp]);
    }
    __syncthreads();

    // ---- phase 2a: zero halo pixels (interior fully overwritten by conv0) ----
    // halo: rows {0,1,34,35} full + cols {0,1,34,35} of rows 2..33 = 272 pixels
    for (int i = t; i < 272; i += 256) {
        int pix;
        if (i < 72)       pix = i;                       // rows 0-1
        else if (i < 144) pix = 34*36 + (i - 72);        // rows 34-35
        else {
            int j = i - 144;                             // 0..127
            int row = 2 + (j >> 2);
            int col = (j & 3); col = (col < 2) ? col : col + 32;
            pix = row*36 + col;
        }
        float4* p4 = (float4*)(planes + pix*12);
        p4[0] = make_float4(0.f,0.f,0.f,0.f);
        p4[1] = make_float4(0.f,0.f,0.f,0.f);
    }
    __syncthreads();

    // ---- phase 2b: conv0 (1->8, o-paired) + relu + pool -> interleaved planes ----
    {
        const int ty = t >> 4, tx = t & 15;
        const int y0 = 4*ty - 2, x0 = 4*tx - 2;
        for (int op = 0; op < 4; ++op) {
            u64 wq[25];
            #pragma unroll
            for (int i = 0; i < 25; ++i) wq[i] = sw0u[op*25 + i];
            u64 binit = pack2(__ldg(&cb0p[2*op]), __ldg(&cb0p[2*op + 1]));
            u64 acc[4][4];
            #pragma unroll
            for (int u = 0; u < 4; ++u)
                #pragma unroll
                for (int v = 0; v < 4; ++v) acc[u][v] = binit;
            conv5x5_opair64(sim, wq, acc, y0, x0);
            #pragma unroll
            for (int a = 0; a < 2; ++a)
                #pragma unroll
                for (int b = 0; b < 2; ++b) {
                    float2 p00 = unpack2(acc[2*a][2*b]);
                    float2 p01 = unpack2(acc[2*a][2*b+1]);
                    float2 p10 = unpack2(acc[2*a+1][2*b]);
                    float2 p11 = unpack2(acc[2*a+1][2*b+1]);
                    float mlo = fmaxf(fmaxf(p00.x, p01.x), fmaxf(p10.x, p11.x));
                    float mhi = fmaxf(fmaxf(p00.y, p01.y), fmaxf(p10.y, p11.y));
                    int pix = (2 + 2*ty + a)*36 + (2 + 2*tx + b);
                    *(float2*)&planes[pix*12 + 2*op] =
                        make_float2(tf32f(fmaxf(mlo, 0.f)), tf32f(fmaxf(mhi, 0.f)));
                }
        }
    }
    __syncthreads();

    // ---- phase 3a: stage conv1 weights [tap][ch][o], tf32-rounded ----
    for (int i = t; i < 3200; i += 256) {
        int o = i & 15, j = i >> 4;          // j = c*25 + tap
        int c = j / 25, tap = j - c*25;
        sw1[tap*136 + c*17 + o] = tf32f(__ldg(&cw1p[o*200 + j]));
    }
    __syncthreads();

    // ---- phase 3b: conv1 as per-tap K=8 mma over channels, A via ldmatrix ----
    const int warp = t >> 5, lane = t & 31, g = lane >> 2, tig = lane & 3;
    const unsigned planes_s = (unsigned)__cvta_generic_to_shared(planes);
    const int rowl = (lane & 7) + ((lane >> 3) & 1) * 8;   // pixel-in-tile per lane
    const unsigned lane_off = (unsigned)(rowl*48 + (lane >> 4)*16);  // 16B = ch 4-7

    float acc[8][2][4];
    #pragma unroll
    for (int mi = 0; mi < 8; ++mi)
        #pragma unroll
        for (int ni = 0; ni < 2; ++ni)
            #pragma unroll
            for (int r = 0; r < 4; ++r) acc[mi][ni][r] = 0.f;

    unsigned addr_mi[8];
    #pragma unroll
    for (int mi = 0; mi < 8; ++mi) {
        int mt = warp*8 + mi;
        int pix0 = (mt >> 1)*36 + (mt & 1)*16;
        addr_mi[mi] = planes_s + (unsigned)(pix0*48) + lane_off;
    }

    #pragma unroll
    for (int ky = 0; ky < 5; ++ky) {
        #pragma unroll
        for (int kx = 0; kx < 5; ++kx) {
            const float* wt = sw1 + (ky*5 + kx)*136;
            const unsigned tapoff = (unsigned)((ky*36 + kx)*48);
            unsigned b00 = __float_as_uint(wt[tig*17 + g]);
            unsigned b01 = __float_as_uint(wt[(tig+4)*17 + g]);
            unsigned b10 = __float_as_uint(wt[tig*17 + 8 + g]);
            unsigned b11 = __float_as_uint(wt[(tig+4)*17 + 8 + g]);
            #pragma unroll
            for (int mi = 0; mi < 8; ++mi) {
                unsigned a0, a1, a2, a3;
                ldsm_x4(a0, a1, a2, a3, addr_mi[mi] + tapoff);
                mma_tf32(acc[mi][0], a0, a1, a2, a3, b00, b01);
                mma_tf32(acc[mi][1], a0, a1, a2, a3, b10, b11);
            }
        }
    }
    __syncthreads();   // planes dead; praw region reusable

    // ---- phase 3c: pool via smem roundtrip (R7 verbatim) ----
    {
        float* hout = g_scratch + OFF_H + simi*4096 + (long)bk * 12288;
        for (int g2 = 0; g2 < 4; ++g2) {
            if ((tig >> 1) == (g2 & 1)) {
                const int j0 = (2*tig) & 3;   // 0 or 2
                const int ni = g2 >> 1;
                #pragma unroll
                for (int mi = 0; mi < 8; ++mi) {
                    int s0 = (warp*8 + mi)*16 + g;
                    praw[s0*5 + j0]         = acc[mi][ni][0];
                    praw[s0*5 + j0 + 1]     = acc[mi][ni][1];
                    praw[(s0+8)*5 + j0]     = acc[mi][ni][2];
                    praw[(s0+8)*5 + j0 + 1] = acc[mi][ni][3];
                }
            }
            __syncthreads();
            #pragma unroll
            for (int v = 0; v < 4; ++v) {
                int pid = v*256 + t;
                int ol = pid & 3, rest = pid >> 2;
                int X = rest & 15, Y = rest >> 4;
                int s00 = (2*Y)*32 + 2*X;
                float m = fmaxf(fmaxf(praw[s00*5 + ol], praw[(s00+1)*5 + ol]),
                                fmaxf(praw[(s00+32)*5 + ol], praw[(s00+33)*5 + ol]));
                m = fmaxf(m + __ldg(&cb1p[4*g2 + ol]), 0.f);
                hout[(4*g2 + ol)*256 + Y*16 + X] = tf32f(m);
            }
            __syncthreads();
        }
    }
}

// ---------------------------------------------------------------------------
// MLP layer 0: y1 += h @ Wl0. tf32 mma, cp.async double-buffered (proven).
// ---------------------------------------------------------------------------
#define G1_KC 768
#define G1_KT 32
#define G1_NT 24
#define AS_STRIDE 36
#define BS_STRIDE 72
#define AS_SZ (128*AS_STRIDE)
#define BS_SZ (32*BS_STRIDE)

__global__ void __launch_bounds__(256) gemm1_kernel()
{
    extern __shared__ __align__(16) float gbuf[];
    const float* A = g_scratch + OFF_H;
    const float* B = g_scratch + OFF_WT0;
    float* C = g_scratch + OFF_Y1;

    const int r0 = blockIdx.x * 128;
    const int c0 = blockIdx.y * 64;
    const int k0 = blockIdx.z * G1_KC;

    const int t = threadIdx.x, warp = t >> 5, lane = t & 31;
    const int g = lane >> 2, tig = lane & 3;
    const int wm = warp & 3, wn = warp >> 2;

    float acc[2][4][4];
    #pragma unroll
    for (int mi = 0; mi < 2; ++mi)
        #pragma unroll
        for (int ni = 0; ni < 4; ++ni)
            #pragma unroll
            for (int r = 0; r < 4; ++r) acc[mi][ni][r] = 0.f;

    auto issue = [&](int ibuf, int kt) {
        float* As = gbuf + ibuf*AS_SZ;
        float* Bs = gbuf + 2*AS_SZ + ibuf*BS_SZ;
        #pragma unroll
        for (int j = 0; j < 4; ++j) {
            int cid = t + 256*j;
            int row = cid >> 3, seg = cid & 7;
            cp_async16(&As[row*AS_STRIDE + seg*4],
                       A + (long)(r0 + row)*12288 + k0 + kt + seg*4);
        }
        #pragma unroll
        for (int j = 0; j < 2; ++j) {
            int cid = t + 256*j;
            int k = cid >> 4, seg = cid & 15;
            cp_async16(&Bs[k*BS_STRIDE + seg*4],
                       B + (long)(k0 + kt + k)*256 + c0 + seg*4);
        }
        asm volatile("cp.async.commit_group;");
    };

    issue(0, 0);
    issue(1, G1_KT);

    for (int i = 0; i < G1_NT; ++i) {
        if (i < G1_NT - 1) asm volatile("cp.async.wait_group 1;");
        else               asm volatile("cp.async.wait_group 0;");
        __syncthreads();

        const float* As = gbuf + (i & 1)*AS_SZ;
        const float* Bs = gbuf + 2*AS_SZ + (i & 1)*BS_SZ;
        #pragma unroll
        for (int kc = 0; kc < 4; ++kc) {
            unsigned af[2][4], bf[4][2];
            #pragma unroll
            for (int mi = 0; mi < 2; ++mi) {
                const float* ap = As + (wm*32 + mi*16 + g)*AS_STRIDE + kc*8 + tig;
                af[mi][0] = __float_as_uint(ap[0]);
                af[mi][1] = __float_as_uint(ap[8*AS_STRIDE]);
                af[mi][2] = __float_as_uint(ap[4]);
                af[mi][3] = __float_as_uint(ap[8*AS_STRIDE + 4]);
            }
            #pragma unroll
            for (int ni = 0; ni < 4; ++ni) {
                const float* bp = Bs + (kc*8 + tig)*BS_STRIDE + wn*32 + ni*8 + g;
                bf[ni][0] = __float_as_uint(bp[0]);
                bf[ni][1] = __float_as_uint(bp[4*BS_STRIDE]);
            }
            #pragma unroll
            for (int mi = 0; mi < 2; ++mi)
                #pragma unroll
                for (int ni = 0; ni < 4; ++ni)
                    mma_tf32(acc[mi][ni], af[mi][0], af[mi][1], af[mi][2], af[mi][3],
                             bf[ni][0], bf[ni][1]);
        }
        __syncthreads();
        if (i + 2 < G1_NT) issue(i & 1, (i + 2)*G1_KT);
    }

    #pragma unroll
    for (int mi = 0; mi < 2; ++mi) {
        int R = r0 + wm*32 + mi*16 + g;
        #pragma unroll
        for (int ni = 0; ni < 4; ++ni) {
            int Cc = c0 + wn*32 + ni*8 + 2*tig;
            atomicAdd(&C[R*256 + Cc],         acc[mi][ni][0]);
            atomicAdd(&C[R*256 + Cc + 1],     acc[mi][ni][1]);
            atomicAdd(&C[(R+8)*256 + Cc],     acc[mi][ni][2]);
            atomicAdd(&C[(R+8)*256 + Cc + 1], acc[mi][ni][3]);
        }
    }
}

// ---------------------------------------------------------------------------
// Head: split-K (4 slices of 64), 256 threads/block, one block per row.
// ---------------------------------------------------------------------------
__global__ void __launch_bounds__(256) head_kernel(
    const float* __restrict__ Wl1, const float* __restrict__ bl1,
    const float* __restrict__ Wsc, const float* __restrict__ bsc,
    float* __restrict__ out)
{
    const int r = blockIdx.x;
    const int t = threadIdx.x;
    __shared__ float sy[256];
    __shared__ float part[4][64];
    __shared__ float red[2];

    sy[t] = fmaxf(g_scratch[OFF_Y1 + (long)r*256 + t], 0.f);
    __syncthreads();

    const int j = t & 63, ks = t >> 6;
    float acc = 0.f;
    #pragma unroll 16
    for (int k = 64*ks; k < 64*ks + 64; ++k)
        acc += sy[k] * __ldg(&Wl1[k*64 + j]);
    part[ks][j] = acc;
    __syncthreads();

    if (t < 64) {
        float a = part[0][t] + part[1][t] + part[2][t] + part[3][t] + __ldg(&bl1[t]);
        float v = fmaxf(a, 0.f) * __ldg(&Wsc[t]);
        #pragma unroll
        for (int off = 16; off > 0; off >>= 1)
            v += __shfl_down_sync(0xffffffffu, v, off);
        if ((t & 31) == 0) red[t >> 5] = v;
    }
    __syncthreads();
    if (t == 0) {
        float s = red[0] + red[1] + __ldg(&bsc[0]);
        out[r] = 1.f / (1.f + expf(-s));
    }
}

// ---------------------------------------------------------------------------
// Launch
// ---------------------------------------------------------------------------
#define PAIR_SMEM (19648*4)
#define G1_SMEM ((2*AS_SZ + 2*BS_SZ)*4)

extern "C" void kernel_launch(void* const* d_in, const int* in_sizes, int n_in,
                              void* d_out, int out_size)
{
    (void)in_sizes; (void)n_in; (void)out_size;
    const float* x_q  = (const float*)d_in[0];
    const float* x_c  = (const float*)d_in[1];
    const int*   src_q = (const int*)d_in[2];
    const int*   dst_q = (const int*)d_in[3];
    const int*   src_c = (const int*)d_in[4];
    const int*   dst_c = (const int*)d_in[5];
    const float* Wg0 = (const float*)d_in[6];
    const float* bg0 = (const float*)d_in[7];
    const float* Wg1 = (const float*)d_in[8];
    const float* bg1 = (const float*)d_in[9];
    const float* Wg2 = (const float*)d_in[10];
    const float* bg2 = (const float*)d_in[11];
    const float* cw0 = (const float*)d_in[12];
    const float* cb0 = (const float*)d_in[13];
    const float* cw1 = (const float*)d_in[14];
    const float* cb1 = (const float*)d_in[15];
    const float* Wl0 = (const float*)d_in[16];
    const float* bl0 = (const float*)d_in[17];
    const float* Wl1 = (const float*)d_in[18];
    const float* bl1 = (const float*)d_in[19];
    const float* Wsc = (const float*)d_in[20];
    const float* bsc = (const float*)d_in[21];
    float* out = (float*)d_out;

    static int attr_done = 0;
    if (!attr_done) {
        cudaFuncSetAttribute(pair_all,  cudaFuncAttributeMaxDynamicSharedMemorySize, PAIR_SMEM);
        cudaFuncSetAttribute(gemm1_kernel, cudaFuncAttributeMaxDynamicSharedMemorySize, G1_SMEM);
        attr_done = 1;
    }

    // fused: 3-layer GCN (1024 blocks) + y1 bias init (512) + Wl0 tf32 (3072)
    prep_all<<<2*NB_GRAPHS + 512 + 3072, 256>>>(
        x_q, x_c, Wg0, bg0, Wg1, bg1, Wg2, bg2,
        src_q, dst_q, src_c, dst_c, bl0, Wl0);

    // fused sim + conv stacks (all 3 sims)
    pair_all<<<3*NB_GRAPHS, 256, PAIR_SMEM>>>(cw0, cb0, cw1, cb1);

    // MLP layer 0 on tensor cores, then head
    gemm1_kernel<<<dim3(4, 4, 16), 256, G1_SMEM>>>();
    head_kernel<<<512, 256>>>(Wl1, bl1, Wsc, bsc, out);
}

// round 10
// speedup vs baseline: 2.9864x; 1.0128x over previous
#include <cuda_runtime.h>
#include <math.h>

// ---------------------------------------------------------------------------
// Problem constants
// ---------------------------------------------------------------------------
#define NB_GRAPHS 512          // B
#define M_NODES   64           // nodes per graph
#define EPG       512          // edges per graph

// ---------------------------------------------------------------------------
// Scratch layout (single __device__ array, no allocations)
// ---------------------------------------------------------------------------
#define SZ_F0 (32768*64)
#define SZ_F1 (32768*32)
#define SZ_F2 (32768*16)
#define SZ_H  (512*12288)
#define SZ_Y1 (512*256)
#define SZ_WT0 (12288*256)

#define OFF_FQ0 0
#define OFF_FC0 (OFF_FQ0 + SZ_F0)
#define OFF_FQ1 (OFF_FC0 + SZ_F0)
#define OFF_FC1 (OFF_FQ1 + SZ_F1)
#define OFF_FQ2 (OFF_FC1 + SZ_F1)
#define OFF_FC2 (OFF_FQ2 + SZ_F2)
#define OFF_H   (OFF_FC2 + SZ_F2)
#define OFF_Y1  (OFF_H + SZ_H)
#define OFF_WT0 (OFF_Y1 + SZ_Y1)
#define SCRATCH_TOTAL (OFF_WT0 + SZ_WT0)

__device__ float g_scratch[SCRATCH_TOTAL];

// ---------------------------------------------------------------------------
// Helpers
// ---------------------------------------------------------------------------
typedef unsigned long long u64;

__device__ __forceinline__ u64 pack2(float lo, float hi) {
    u64 r; asm("mov.b64 %0, {%1,%2};" : "=l"(r) : "f"(lo), "f"(hi)); return r;
}
__device__ __forceinline__ u64 fma2(u64 a, u64 b, u64 c) {
    u64 d; asm("fma.rn.f32x2 %0, %1, %2, %3;" : "=l"(d) : "l"(a), "l"(b), "l"(c));
    return d;
}
__device__ __forceinline__ float2 unpack2(u64 v) {
    float lo, hi; asm("mov.b64 {%0,%1}, %2;" : "=f"(lo), "=f"(hi) : "l"(v));
    return make_float2(lo, hi);
}
__device__ __forceinline__ unsigned f2tf32(float f) {
    unsigned u; asm("cvt.rna.tf32.f32 %0, %1;" : "=r"(u) : "f"(f)); return u;
}
__device__ __forceinline__ float tf32f(float f) {
    return __uint_as_float(f2tf32(f));
}
__device__ __forceinline__ void cp_async16(float* dst, const float* src) {
    unsigned d = (unsigned)__cvta_generic_to_shared(dst);
    asm volatile("cp.async.cg.shared.global [%0], [%1], 16;" :: "r"(d), "l"(src));
}
__device__ __forceinline__ void mma_tf32(float c[4],
    unsigned a0, unsigned a1, unsigned a2, unsigned a3,
    unsigned b0, unsigned b1)
{
    asm volatile(
        "mma.sync.aligned.m16n8k8.row.col.f32.tf32.tf32.f32 "
        "{%0,%1,%2,%3}, {%4,%5,%6,%7}, {%8,%9}, {%0,%1,%2,%3};"
        : "+f"(c[0]), "+f"(c[1]), "+f"(c[2]), "+f"(c[3])
        : "r"(a0), "r"(a1), "r"(a2), "r"(a3), "r"(b0), "r"(b1));
}
__device__ __forceinline__ void ldsm_x4(unsigned& r0, unsigned& r1,
                                        unsigned& r2, unsigned& r3, unsigned addr)
{
    asm volatile("ldmatrix.sync.aligned.m8n8.x4.shared.b16 {%0,%1,%2,%3}, [%4];"
        : "=r"(r0), "=r"(r1), "=r"(r2), "=r"(r3) : "r"(addr));
}

// ---------------------------------------------------------------------------
// GCN layer body (float4-vectorized GEMM). Feature outputs tf32-rounded so
// the sim GEMM can consume them as raw tensor-core fragments.
// ---------------------------------------------------------------------------
template<int FIN, int FOUT>
__device__ __forceinline__ void gcn_layer_body(
    const float* __restrict__ sx, float* __restrict__ sA, float* __restrict__ sout,
    const float* __restrict__ sdinv,
    const int* __restrict__ sstart, const int* __restrict__ ssrc,
    const float* __restrict__ W, const float* __restrict__ bias,
    float* __restrict__ outg, int t)
{
    {
        const int j = t % FOUT;
        float wcol[FIN];
        #pragma unroll
        for (int k = 0; k < FIN; ++k) wcol[k] = __ldg(&W[k*FOUT + j]);
        for (int i = t; i < 64*FOUT; i += 256) {
            int n = i / FOUT;
            const float4* xr = (const float4*)(sx + n*FIN);
            float acc = 0.f;
            #pragma unroll
            for (int k4 = 0; k4 < FIN/4; ++k4) {
                float4 xv = xr[k4];
                acc += xv.x*wcol[4*k4] + xv.y*wcol[4*k4+1]
                     + xv.z*wcol[4*k4+2] + xv.w*wcol[4*k4+3];
            }
            sA[i] = acc * sdinv[n];
        }
    }
    __syncthreads();

    {
        const int wp = t >> 5, lane = t & 31;
        constexpr int CH = (FOUT + 31) / 32;
        for (int d = wp; d < 64; d += 8) {
            const int e0 = sstart[d], e1 = sstart[d + 1];
            const float dv = sdinv[d];
            float a[CH];
            #pragma unroll
            for (int c = 0; c < CH; ++c) {
                int j = lane + 32*c;
                a[c] = (j < FOUT) ? sA[d*FOUT + j] : 0.f;
            }
            for (int e = e0; e < e1; ++e) {
                int s = ssrc[e];
                #pragma unroll
                for (int c = 0; c < CH; ++c) {
                    int j = lane + 32*c;
                    if (j < FOUT) a[c] += sA[s*FOUT + j];
                }
            }
            #pragma unroll
            for (int c = 0; c < CH; ++c) {
                int j = lane + 32*c;
                if (j < FOUT) sout[d*FOUT + j] = dv*a[c] + __ldg(&bias[j]);
            }
        }
    }
    __syncthreads();

    for (int i = t; i < 64*FOUT; i += 256)
        outg[i] = tf32f(sout[i]);           // tf32-rounded feature copies
}

// ---------------------------------------------------------------------------
// prep_all: [0,1024) GCN; [1024,1536) y1 bias init; [1536,4608) Wl0 tf32.
// ---------------------------------------------------------------------------
__global__ void __launch_bounds__(256) prep_all(
    const float* __restrict__ xq, const float* __restrict__ xc,
    const float* __restrict__ Wg0, const float* __restrict__ bg0,
    const float* __restrict__ Wg1, const float* __restrict__ bg1,
    const float* __restrict__ Wg2, const float* __restrict__ bg2,
    const int* __restrict__ srcq, const int* __restrict__ dstq,
    const int* __restrict__ srcc, const int* __restrict__ dstc,
    const float* __restrict__ bl0, const float* __restrict__ Wl0)
{
    __shared__ __align__(16) float pool[10240];
    __shared__ int   ssrc[EPG];
    __shared__ int   sstart[65];
    __shared__ int   scnt[64];
    __shared__ float sdinv[64];

    const int b = blockIdx.x;
    const int t = threadIdx.x;

    if (b >= 2*NB_GRAPHS) {
        if (b < 2*NB_GRAPHS + 512) {
            int i = (b - 2*NB_GRAPHS)*256 + t;
            g_scratch[OFF_Y1 + i] = __ldg(&bl0[i & 255]);
        } else {
            int i = (b - (2*NB_GRAPHS + 512))*256 + t;   // float4 index
            float4 v = ((const float4*)Wl0)[i];
            float4 o;
            o.x = tf32f(v.x); o.y = tf32f(v.y); o.z = tf32f(v.z); o.w = tf32f(v.w);
            ((float4*)(g_scratch + OFF_WT0))[i] = o;
        }
        return;
    }

    const bool isC = (b >= NB_GRAPHS);
    const int gg  = isC ? b - NB_GRAPHS : b;
    const float* x = isC ? xc : xq;
    const int* src = isC ? srcc : srcq;
    const int* dst = isC ? dstc : dstq;

    const int nb = gg * M_NODES;
    const int eb = gg * EPG;

    if (t < 64) scnt[t] = 0;
    __syncthreads();

    for (int e = t; e < EPG; e += 256)
        atomicAdd(&scnt[dst[eb + e] - nb], 1);
    for (int i = t; i < 64*32; i += 256) pool[i] = x[(long)nb*32 + i];
    __syncthreads();

    if (t == 0) {
        int a = 0;
        for (int i = 0; i < 64; ++i) { sstart[i] = a; a += scnt[i]; }
        sstart[64] = a;
    }
    __syncthreads();
    if (t < 64) {
        scnt[t] = sstart[t];
        sdinv[t] = rsqrtf(1.0f + (float)(sstart[t + 1] - sstart[t]));
    }
    __syncthreads();

    for (int e = t; e < EPG; e += 256) {
        int d = dst[eb + e] - nb;
        int s = src[eb + e] - nb;
        int p = atomicAdd(&scnt[d], 1);
        ssrc[p] = s;
    }
    __syncthreads();

    gcn_layer_body<32,64>(pool, pool+2048, pool+6144, sdinv, sstart, ssrc,
                          Wg0, bg0, g_scratch + (isC?OFF_FC0:OFF_FQ0) + (long)nb*64, t);
    for (int i = t; i < 64*64; i += 256) pool[i] = fmaxf(pool[6144 + i], 0.f);
    __syncthreads();

    gcn_layer_body<64,32>(pool, pool+4096, pool+6144, sdinv, sstart, ssrc,
                          Wg1, bg1, g_scratch + (isC?OFF_FC1:OFF_FQ1) + (long)nb*32, t);
    for (int i = t; i < 64*32; i += 256) pool[i] = fmaxf(pool[6144 + i], 0.f);
    __syncthreads();

    gcn_layer_body<32,16>(pool, pool+2048, pool+3072, sdinv, sstart, ssrc,
                          Wg2, bg2, g_scratch + (isC?OFF_FC2:OFF_FQ2) + (long)nb*16, t);
}

// ---------------------------------------------------------------------------
// conv0 helper: o-paired f32x2, row-streamed (R7/R8 proven)
// ---------------------------------------------------------------------------
__device__ __forceinline__ void conv5x5_opair64(
    const float* __restrict__ plane, const u64* __restrict__ wq,
    u64 acc[4][4], int y0, int x0)
{
    #pragma unroll
    for (int dy = 0; dy < 8; ++dy) {
        const int yy = y0 + dy;
        const bool rowok = ((unsigned)yy < 64u);
        u64 sp[8];
        #pragma unroll
        for (int j = 0; j < 4; ++j) {
            int xx = x0 + 2*j;
            float2 v = make_float2(0.f, 0.f);
            if (rowok && (unsigned)xx < 64u)
                v = *(const float2*)(plane + yy*64 + xx);
            sp[2*j]   = pack2(v.x, v.x);
            sp[2*j+1] = pack2(v.y, v.y);
        }
        #pragma unroll
        for (int u = 0; u < 4; ++u) {
            const int ky = dy - u;
            if (ky >= 0 && ky < 5) {
                #pragma unroll
                for (int kx = 0; kx < 5; ++kx) {
                    u64 w = wq[ky*5 + kx];
                    #pragma unroll
                    for (int v = 0; v < 4; ++v)
                        acc[u][v] = fma2(sp[v + kx], w, acc[u][v]);
                }
            }
        }
    }
}

// ---------------------------------------------------------------------------
// Fused pair kernel: sim GEMM (tf32 mma) + conv0 (f32x2 o-paired) +
// conv1 (tf32 mma, channel-interleaved planes, ldmatrix A feed)
//
// Dynamic smem buf (19648 floats):
//   sim    : [0,4096)        phase 1-2; reused for sw1 in phase 3
//   sq     : [4096,8448)     phase 0-1 ([m][F+4] padded)
//   scB    : [8448,13056)    phase 0-1 ([k][72] — gemm1-proven stride)
//   planes : [4096,19648)    phase 2-3b (1296 px x stride 12, tf32, ch-interleaved)
//   praw   : [4096,9216)     phase 3c pool staging
// ---------------------------------------------------------------------------
__global__ void __launch_bounds__(256, 2) pair_all(
    const float* __restrict__ cw0, const float* __restrict__ cb0,
    const float* __restrict__ cw1, const float* __restrict__ cb1)
{
    extern __shared__ __align__(16) float buf[];
    __shared__ u64 sw0u[100];   // conv0 weights as (o,o+1) pairs: [op*25 + tap]

    float* sim    = buf;
    float* sq     = buf + 4096;
    float* scB    = buf + 8448;
    float* planes = buf + 4096;
    float* praw   = buf + 4096;
    float* sw1    = buf;        // [tap*136 + c*17 + o]

    const int simi = blockIdx.x % 3;
    const int bk   = blockIdx.x / 3;
    const int lf   = 6 - simi;               // log2(F)
    const int F    = 1 << lf;                // 64, 32, 16
    const int SP   = F + 4;                  // padded sq stride (68/36/20)
    const int offq = (simi == 0) ? OFF_FQ0 : (simi == 1) ? OFF_FQ1 : OFF_FQ2;
    const int offc = (simi == 0) ? OFF_FC0 : (simi == 1) ? OFF_FC1 : OFF_FC2;
    const float* cw0p = cw0 + simi*200;
    const float* cb0p = cb0 + simi*8;
    const float* cw1p = cw1 + simi*3200;
    const float* cb1p = cb1 + simi*16;

    const int t = threadIdx.x;
    const int warp = t >> 5, lane = t & 31, g = lane >> 2, tig = lane & 3;
    const float* fq = g_scratch + offq + ((long)bk << (6 + lf));
    const float* fc = g_scratch + offc + ((long)bk << (6 + lf));

    // ---- phase 0: stage features (tf32-valued) + conv0 weights ----
    for (int i = t; i < (64 << lf); i += 256) {
        int n = i >> lf, k = i & (F - 1);
        sq[n*SP + k] = fq[i];
    }
    for (int i = t; i < (64 << lf); i += 256) {
        int n = i >> lf, k = i & (F - 1);
        scB[k*72 + n] = fc[i];
    }
    if (t < 100) {
        int op = t / 25, tap = t % 25;
        sw0u[t] = pack2(__ldg(&cw0p[(2*op)*25 + tap]),
                        __ldg(&cw0p[(2*op + 1)*25 + tap]));
    }
    __syncthreads();

    // ---- phase 1: similarity GEMM on tensor cores -> sim[64][64] (fp32) ----
    // warp w: m-tile (w&3) (16 rows), n-range (w>>2)*32 (4 n-tiles of 8)
    {
        const int wm = warp & 3;
        const int n0base = (warp >> 2) * 32;
        float c[4][4];
        #pragma unroll
        for (int ni = 0; ni < 4; ++ni)
            #pragma unroll
            for (int r = 0; r < 4; ++r) c[ni][r] = 0.f;

        const int nk = F >> 3;
        for (int kk = 0; kk < nk; ++kk) {
            const float* ap = sq + (wm*16 + g)*SP + kk*8 + tig;
            unsigned a0 = __float_as_uint(ap[0]);
            unsigned a1 = __float_as_uint(ap[8*SP]);
            unsigned a2 = __float_as_uint(ap[4]);
            unsigned a3 = __float_as_uint(ap[8*SP + 4]);
            const float* bp = scB + (kk*8 + tig)*72 + n0base + g;
            #pragma unroll
            for (int ni = 0; ni < 4; ++ni) {
                unsigned b0 = __float_as_uint(bp[ni*8]);
                unsigned b1 = __float_as_uint(bp[4*72 + ni*8]);
                mma_tf32(c[ni], a0, a1, a2, a3, b0, b1);
            }
        }
        // sim region [0,4096) disjoint from sq/scB — safe to write directly
        #pragma unroll
        for (int ni = 0; ni < 4; ++ni) {
            int col = n0base + ni*8 + 2*tig;
            int row = wm*16 + g;
            *(float2*)&sim[row*64 + col]     = make_float2(c[ni][0], c[ni][1]);
            *(float2*)&sim[(row+8)*64 + col] = make_float2(c[ni][2], c[ni][3]);
        }
    }
    __syncthreads();

    // ---- phase 2a: zero halo pixels (interior fully overwritten by conv0) ----
    for (int i = t; i < 272; i += 256) {
        int pix;
        if (i < 72)       pix = i;                       // rows 0-1
        else if (i < 144) pix = 34*36 + (i - 72);        // rows 34-35
        else {
            int j = i - 144;                             // 0..127
            int row = 2 + (j >> 2);
            int col = (j & 3); col = (col < 2) ? col : col + 32;
            pix = row*36 + col;
        }
        float4* p4 = (float4*)(planes + pix*12);
        p4[0] = make_float4(0.f,0.f,0.f,0.f);
        p4[1] = make_float4(0.f,0.f,0.f,0.f);
    }
    __syncthreads();

    // ---- phase 2b: conv0 (1->8, o-paired) + relu + pool -> interleaved planes ----
    {
        const int ty = t >> 4, tx = t & 15;
        const int y0 = 4*ty - 2, x0 = 4*tx - 2;
        for (int op = 0; op < 4; ++op) {
            u64 wq[25];
            #pragma unroll
            for (int i = 0; i < 25; ++i) wq[i] = sw0u[op*25 + i];
            u64 binit = pack2(__ldg(&cb0p[2*op]), __ldg(&cb0p[2*op + 1]));
            u64 acc[4][4];
            #pragma unroll
            for (int u = 0; u < 4; ++u)
                #pragma unroll
                for (int v = 0; v < 4; ++v) acc[u][v] = binit;
            conv5x5_opair64(sim, wq, acc, y0, x0);
            #pragma unroll
            for (int a = 0; a < 2; ++a)
                #pragma unroll
                for (int b = 0; b < 2; ++b) {
                    float2 p00 = unpack2(acc[2*a][2*b]);
                    float2 p01 = unpack2(acc[2*a][2*b+1]);
                    float2 p10 = unpack2(acc[2*a+1][2*b]);
                    float2 p11 = unpack2(acc[2*a+1][2*b+1]);
                    float mlo = fmaxf(fmaxf(p00.x, p01.x), fmaxf(p10.x, p11.x));
                    float mhi = fmaxf(fmaxf(p00.y, p01.y), fmaxf(p10.y, p11.y));
                    int pix = (2 + 2*ty + a)*36 + (2 + 2*tx + b);
                    *(float2*)&planes[pix*12 + 2*op] =
                        make_float2(tf32f(fmaxf(mlo, 0.f)), tf32f(fmaxf(mhi, 0.f)));
                }
        }
    }
    __syncthreads();

    // ---- phase 3a: stage conv1 weights [tap][ch][o], tf32-rounded ----
    for (int i = t; i < 3200; i += 256) {
        int o = i & 15, j = i >> 4;          // j = c*25 + tap
        int c = j / 25, tap = j - c*25;
        sw1[tap*136 + c*17 + o] = tf32f(__ldg(&cw1p[o*200 + j]));
    }
    __syncthreads();

    // ---- phase 3b: conv1 as per-tap K=8 mma over channels, A via ldmatrix ----
    const unsigned planes_s = (unsigned)__cvta_generic_to_shared(planes);
    const int rowl = (lane & 7) + ((lane >> 3) & 1) * 8;
    const unsigned lane_off = (unsigned)(rowl*48 + (lane >> 4)*16);

    float acc[8][2][4];
    #pragma unroll
    for (int mi = 0; mi < 8; ++mi)
        #pragma unroll
        for (int ni = 0; ni < 2; ++ni)
            #pragma unroll
            for (int r = 0; r < 4; ++r) acc[mi][ni][r] = 0.f;

    unsigned addr_mi[8];
    #pragma unroll
    for (int mi = 0; mi < 8; ++mi) {
        int mt = warp*8 + mi;
        int pix0 = (mt >> 1)*36 + (mt & 1)*16;
        addr_mi[mi] = planes_s + (unsigned)(pix0*48) + lane_off;
    }

    #pragma unroll
    for (int ky = 0; ky < 5; ++ky) {
        #pragma unroll
        for (int kx = 0; kx < 5; ++kx) {
            const float* wt = sw1 + (ky*5 + kx)*136;
            const unsigned tapoff = (unsigned)((ky*36 + kx)*48);
            unsigned b00 = __float_as_uint(wt[tig*17 + g]);
            unsigned b01 = __float_as_uint(wt[(tig+4)*17 + g]);
            unsigned b10 = __float_as_uint(wt[tig*17 + 8 + g]);
            unsigned b11 = __float_as_uint(wt[(tig+4)*17 + 8 + g]);
            #pragma unroll
            for (int mi = 0; mi < 8; ++mi) {
                unsigned a0, a1, a2, a3;
                ldsm_x4(a0, a1, a2, a3, addr_mi[mi] + tapoff);
                mma_tf32(acc[mi][0], a0, a1, a2, a3, b00, b01);
                mma_tf32(acc[mi][1], a0, a1, a2, a3, b10, b11);
            }
        }
    }
    __syncthreads();   // planes dead; praw region reusable

    // ---- phase 3c: pool via smem roundtrip (proven) ----
    {
        float* hout = g_scratch + OFF_H + simi*4096 + (long)bk * 12288;
        for (int g2 = 0; g2 < 4; ++g2) {
            if ((tig >> 1) == (g2 & 1)) {
                const int j0 = (2*tig) & 3;   // 0 or 2
                const int ni = g2 >> 1;
                #pragma unroll
                for (int mi = 0; mi < 8; ++mi) {
                    int s0 = (warp*8 + mi)*16 + g;
                    praw[s0*5 + j0]         = acc[mi][ni][0];
                    praw[s0*5 + j0 + 1]     = acc[mi][ni][1];
                    praw[(s0+8)*5 + j0]     = acc[mi][ni][2];
                    praw[(s0+8)*5 + j0 + 1] = acc[mi][ni][3];
                }
            }
            __syncthreads();
            #pragma unroll
            for (int v = 0; v < 4; ++v) {
                int pid = v*256 + t;
                int ol = pid & 3, rest = pid >> 2;
                int X = rest & 15, Y = rest >> 4;
                int s00 = (2*Y)*32 + 2*X;
                float m = fmaxf(fmaxf(praw[s00*5 + ol], praw[(s00+1)*5 + ol]),
                                fmaxf(praw[(s00+32)*5 + ol], praw[(s00+33)*5 + ol]));
                m = fmaxf(m + __ldg(&cb1p[4*g2 + ol]), 0.f);
                hout[(4*g2 + ol)*256 + Y*16 + X] = tf32f(m);
            }
            __syncthreads();
        }
    }
}

// ---------------------------------------------------------------------------
// MLP layer 0: y1 += h @ Wl0. tf32 mma, cp.async double-buffered (proven).
// ---------------------------------------------------------------------------
#define G1_KC 768
#define G1_KT 32
#define G1_NT 24
#define AS_STRIDE 36
#define BS_STRIDE 72
#define AS_SZ (128*AS_STRIDE)
#define BS_SZ (32*BS_STRIDE)

__global__ void __launch_bounds__(256) gemm1_kernel()
{
    extern __shared__ __align__(16) float gbuf[];
    const float* A = g_scratch + OFF_H;
    const float* B = g_scratch + OFF_WT0;
    float* C = g_scratch + OFF_Y1;

    const int r0 = blockIdx.x * 128;
    const int c0 = blockIdx.y * 64;
    const int k0 = blockIdx.z * G1_KC;

    const int t = threadIdx.x, warp = t >> 5, lane = t & 31;
    const int g = lane >> 2, tig = lane & 3;
    const int wm = warp & 3, wn = warp >> 2;

    float acc[2][4][4];
    #pragma unroll
    for (int mi = 0; mi < 2; ++mi)
        #pragma unroll
        for (int ni = 0; ni < 4; ++ni)
            #pragma unroll
            for (int r = 0; r < 4; ++r) acc[mi][ni][r] = 0.f;

    auto issue = [&](int ibuf, int kt) {
        float* As = gbuf + ibuf*AS_SZ;
        float* Bs = gbuf + 2*AS_SZ + ibuf*BS_SZ;
        #pragma unroll
        for (int j = 0; j < 4; ++j) {
            int cid = t + 256*j;
            int row = cid >> 3, seg = cid & 7;
            cp_async16(&As[row*AS_STRIDE + seg*4],
                       A + (long)(r0 + row)*12288 + k0 + kt + seg*4);
        }
        #pragma unroll
        for (int j = 0; j < 2; ++j) {
            int cid = t + 256*j;
            int k = cid >> 4, seg = cid & 15;
            cp_async16(&Bs[k*BS_STRIDE + seg*4],
                       B + (long)(k0 + kt + k)*256 + c0 + seg*4);
        }
        asm volatile("cp.async.commit_group;");
    };

    issue(0, 0);
    issue(1, G1_KT);

    for (int i = 0; i < G1_NT; ++i) {
        if (i < G1_NT - 1) asm volatile("cp.async.wait_group 1;");
        else               asm volatile("cp.async.wait_group 0;");
        __syncthreads();

        const float* As = gbuf + (i & 1)*AS_SZ;
        const float* Bs = gbuf + 2*AS_SZ + (i & 1)*BS_SZ;
        #pragma unroll
        for (int kc = 0; kc < 4; ++kc) {
            unsigned af[2][4], bf[4][2];
            #pragma unroll
            for (int mi = 0; mi < 2; ++mi) {
                const float* ap = As + (wm*32 + mi*16 + g)*AS_STRIDE + kc*8 + tig;
                af[mi][0] = __float_as_uint(ap[0]);
                af[mi][1] = __float_as_uint(ap[8*AS_STRIDE]);
                af[mi][2] = __float_as_uint(ap[4]);
                af[mi][3] = __float_as_uint(ap[8*AS_STRIDE + 4]);
            }
            #pragma unroll
            for (int ni = 0; ni < 4; ++ni) {
                const float* bp = Bs + (kc*8 + tig)*BS_STRIDE + wn*32 + ni*8 + g;
                bf[ni][0] = __float_as_uint(bp[0]);
                bf[ni][1] = __float_as_uint(bp[4*BS_STRIDE]);
            }
            #pragma unroll
            for (int mi = 0; mi < 2; ++mi)
                #pragma unroll
                for (int ni = 0; ni < 4; ++ni)
                    mma_tf32(acc[mi][ni], af[mi][0], af[mi][1], af[mi][2], af[mi][3],
                             bf[ni][0], bf[ni][1]);
        }
        __syncthreads();
        if (i + 2 < G1_NT) issue(i & 1, (i + 2)*G1_KT);
    }

    #pragma unroll
    for (int mi = 0; mi < 2; ++mi) {
        int R = r0 + wm*32 + mi*16 + g;
        #pragma unroll
        for (int ni = 0; ni < 4; ++ni) {
            int Cc = c0 + wn*32 + ni*8 + 2*tig;
            atomicAdd(&C[R*256 + Cc],         acc[mi][ni][0]);
            atomicAdd(&C[R*256 + Cc + 1],     acc[mi][ni][1]);
            atomicAdd(&C[(R+8)*256 + Cc],     acc[mi][ni][2]);
            atomicAdd(&C[(R+8)*256 + Cc + 1], acc[mi][ni][3]);
        }
    }
}

// ---------------------------------------------------------------------------
// Head: 8 rows per block, Wl1 loaded once and reused across rows in regs.
// ---------------------------------------------------------------------------
__global__ void __launch_bounds__(256) head_kernel(
    const float* __restrict__ Wl1, const float* __restrict__ bl1,
    const float* __restrict__ Wsc, const float* __restrict__ bsc,
    float* __restrict__ out)
{
    const int r0 = blockIdx.x * 8;
    const int t = threadIdx.x;
    __shared__ float sy[8][256];
    __shared__ float part[4][8][64];

    for (int i = t; i < 2048; i += 256) {
        int row = i >> 8, k = i & 255;
        sy[row][k] = fmaxf(g_scratch[OFF_Y1 + (long)(r0 + row)*256 + k], 0.f);
    }
    __syncthreads();

    const int j = t & 63, ks = t >> 6;
    float acc[8];
    #pragma unroll
    for (int row = 0; row < 8; ++row) acc[row] = 0.f;
    for (int k = 64*ks; k < 64*ks + 64; ++k) {
        float w = __ldg(&Wl1[k*64 + j]);
        #pragma unroll
        for (int row = 0; row < 8; ++row) acc[row] += sy[row][k] * w;
    }
    #pragma unroll
    for (int row = 0; row < 8; ++row) part[ks][row][j] = acc[row];
    __syncthreads();

    // one warp per row
    const int wp = t >> 5, lane = t & 31;
    float v = 0.f;
    #pragma unroll
    for (int h = 0; h < 2; ++h) {
        int jj = lane + 32*h;
        float a = part[0][wp][jj] + part[1][wp][jj] + part[2][wp][jj]
                + part[3][wp][jj] + __ldg(&bl1[jj]);
        v += fmaxf(a, 0.f) * __ldg(&Wsc[jj]);
    }
    #pragma unroll
    for (int off = 16; off > 0; off >>= 1)
        v += __shfl_down_sync(0xffffffffu, v, off);
    if (lane == 0) {
        float s = v + __ldg(&bsc[0]);
        out[r0 + wp] = 1.f / (1.f + expf(-s));
    }
}

// ---------------------------------------------------------------------------
// Launch
// ---------------------------------------------------------------------------
#define PAIR_SMEM (19648*4)
#define G1_SMEM ((2*AS_SZ + 2*BS_SZ)*4)

extern "C" void kernel_launch(void* const* d_in, const int* in_sizes, int n_in,
                              void* d_out, int out_size)
{
    (void)in_sizes; (void)n_in; (void)out_size;
    const float* x_q  = (const float*)d_in[0];
    const float* x_c  = (const float*)d_in[1];
    const int*   src_q = (const int*)d_in[2];
    const int*   dst_q = (const int*)d_in[3];
    const int*   src_c = (const int*)d_in[4];
    const int*   dst_c = (const int*)d_in[5];
    const float* Wg0 = (const float*)d_in[6];
    const float* bg0 = (const float*)d_in[7];
    const float* Wg1 = (const float*)d_in[8];
    const float* bg1 = (const float*)d_in[9];
    const float* Wg2 = (const float*)d_in[10];
    const float* bg2 = (const float*)d_in[11];
    const float* cw0 = (const float*)d_in[12];
    const float* cb0 = (const float*)d_in[13];
    const float* cw1 = (const float*)d_in[14];
    const float* cb1 = (const float*)d_in[15];
    const float* Wl0 = (const float*)d_in[16];
    const float* bl0 = (const float*)d_in[17];
    const float* Wl1 = (const float*)d_in[18];
    const float* bl1 = (const float*)d_in[19];
    const float* Wsc = (const float*)d_in[20];
    const float* bsc = (const float*)d_in[21];
    float* out = (float*)d_out;

    static int attr_done = 0;
    if (!attr_done) {
        cudaFuncSetAttribute(pair_all,  cudaFuncAttributeMaxDynamicSharedMemorySize, PAIR_SMEM);
        cudaFuncSetAttribute(gemm1_kernel, cudaFuncAttributeMaxDynamicSharedMemorySize, G1_SMEM);
        attr_done = 1;
    }

    // fused: 3-layer GCN (1024 blocks) + y1 bias init (512) + Wl0 tf32 (3072)
    prep_all<<<2*NB_GRAPHS + 512 + 3072, 256>>>(
        x_q, x_c, Wg0, bg0, Wg1, bg1, Wg2, bg2,
        src_q, dst_q, src_c, dst_c, bl0, Wl0);

    // fused sim + conv stacks (all 3 sims)
    pair_all<<<3*NB_GRAPHS, 256, PAIR_SMEM>>>(cw0, cb0, cw1, cb1);

    // MLP layer 0 on tensor cores, then head (8 rows/block)
    gemm1_kernel<<<dim3(4, 4, 16), 256, G1_SMEM>>>();
    head_kernel<<<64, 256>>>(Wl1, bl1, Wsc, bsc, out);
}

// round 11
// speedup vs baseline: 3.0868x; 1.0336x over previous
#include <cuda_runtime.h>
#include <math.h>

// ---------------------------------------------------------------------------
// Problem constants
// ---------------------------------------------------------------------------
#define NB_GRAPHS 512          // B
#define M_NODES   64           // nodes per graph
#define EPG       512          // edges per graph

// ---------------------------------------------------------------------------
// Scratch layout (single __device__ array, no allocations)
// ---------------------------------------------------------------------------
#define SZ_F0 (32768*64)
#define SZ_F1 (32768*32)
#define SZ_F2 (32768*16)
#define SZ_H  (512*12288)
#define SZ_Y1 (512*256)
#define SZ_WT0 (12288*256)

#define OFF_FQ0 0
#define OFF_FC0 (OFF_FQ0 + SZ_F0)
#define OFF_FQ1 (OFF_FC0 + SZ_F0)
#define OFF_FC1 (OFF_FQ1 + SZ_F1)
#define OFF_FQ2 (OFF_FC1 + SZ_F1)
#define OFF_FC2 (OFF_FQ2 + SZ_F2)
#define OFF_H   (OFF_FC2 + SZ_F2)
#define OFF_Y1  (OFF_H + SZ_H)
#define OFF_WT0 (OFF_Y1 + SZ_Y1)
#define SCRATCH_TOTAL (OFF_WT0 + SZ_WT0)

__device__ float g_scratch[SCRATCH_TOTAL];

// ---------------------------------------------------------------------------
// Helpers
// ---------------------------------------------------------------------------
typedef unsigned long long u64;

__device__ __forceinline__ u64 pack2(float lo, float hi) {
    u64 r; asm("mov.b64 %0, {%1,%2};" : "=l"(r) : "f"(lo), "f"(hi)); return r;
}
__device__ __forceinline__ u64 fma2(u64 a, u64 b, u64 c) {
    u64 d; asm("fma.rn.f32x2 %0, %1, %2, %3;" : "=l"(d) : "l"(a), "l"(b), "l"(c));
    return d;
}
__device__ __forceinline__ float2 unpack2(u64 v) {
    float lo, hi; asm("mov.b64 {%0,%1}, %2;" : "=f"(lo), "=f"(hi) : "l"(v));
    return make_float2(lo, hi);
}
__device__ __forceinline__ unsigned f2tf32(float f) {
    unsigned u; asm("cvt.rna.tf32.f32 %0, %1;" : "=r"(u) : "f"(f)); return u;
}
__device__ __forceinline__ float tf32f(float f) {
    return __uint_as_float(f2tf32(f));
}
__device__ __forceinline__ void cp_async16(float* dst, const float* src) {
    unsigned d = (unsigned)__cvta_generic_to_shared(dst);
    asm volatile("cp.async.cg.shared.global [%0], [%1], 16;" :: "r"(d), "l"(src));
}
__device__ __forceinline__ void mma_tf32(float c[4],
    unsigned a0, unsigned a1, unsigned a2, unsigned a3,
    unsigned b0, unsigned b1)
{
    asm volatile(
        "mma.sync.aligned.m16n8k8.row.col.f32.tf32.tf32.f32 "
        "{%0,%1,%2,%3}, {%4,%5,%6,%7}, {%8,%9}, {%0,%1,%2,%3};"
        : "+f"(c[0]), "+f"(c[1]), "+f"(c[2]), "+f"(c[3])
        : "r"(a0), "r"(a1), "r"(a2), "r"(a3), "r"(b0), "r"(b1));
}
__device__ __forceinline__ void ldsm_x4(unsigned& r0, unsigned& r1,
                                        unsigned& r2, unsigned& r3, unsigned addr)
{
    asm volatile("ldmatrix.sync.aligned.m8n8.x4.shared.b16 {%0,%1,%2,%3}, [%4];"
        : "=r"(r0), "=r"(r1), "=r"(r2), "=r"(r3) : "r"(addr));
}

// ---------------------------------------------------------------------------
// GCN layer body (float4-vectorized GEMM). Feature outputs tf32-rounded so
// the sim GEMM can consume them as raw tensor-core fragments.
// ---------------------------------------------------------------------------
template<int FIN, int FOUT>
__device__ __forceinline__ void gcn_layer_body(
    const float* __restrict__ sx, float* __restrict__ sA, float* __restrict__ sout,
    const float* __restrict__ sdinv,
    const int* __restrict__ sstart, const int* __restrict__ ssrc,
    const float* __restrict__ W, const float* __restrict__ bias,
    float* __restrict__ outg, int t)
{
    {
        const int j = t % FOUT;
        float wcol[FIN];
        #pragma unroll
        for (int k = 0; k < FIN; ++k) wcol[k] = __ldg(&W[k*FOUT + j]);
        for (int i = t; i < 64*FOUT; i += 256) {
            int n = i / FOUT;
            const float4* xr = (const float4*)(sx + n*FIN);
            float acc = 0.f;
            #pragma unroll
            for (int k4 = 0; k4 < FIN/4; ++k4) {
                float4 xv = xr[k4];
                acc += xv.x*wcol[4*k4] + xv.y*wcol[4*k4+1]
                     + xv.z*wcol[4*k4+2] + xv.w*wcol[4*k4+3];
            }
            sA[i] = acc * sdinv[n];
        }
    }
    __syncthreads();

    {
        const int wp = t >> 5, lane = t & 31;
        constexpr int CH = (FOUT + 31) / 32;
        for (int d = wp; d < 64; d += 8) {
            const int e0 = sstart[d], e1 = sstart[d + 1];
            const float dv = sdinv[d];
            float a[CH];
            #pragma unroll
            for (int c = 0; c < CH; ++c) {
                int j = lane + 32*c;
                a[c] = (j < FOUT) ? sA[d*FOUT + j] : 0.f;
            }
            for (int e = e0; e < e1; ++e) {
                int s = ssrc[e];
                #pragma unroll
                for (int c = 0; c < CH; ++c) {
                    int j = lane + 32*c;
                    if (j < FOUT) a[c] += sA[s*FOUT + j];
                }
            }
            #pragma unroll
            for (int c = 0; c < CH; ++c) {
                int j = lane + 32*c;
                if (j < FOUT) sout[d*FOUT + j] = dv*a[c] + __ldg(&bias[j]);
            }
        }
    }
    __syncthreads();

    for (int i = t; i < 64*FOUT; i += 256)
        outg[i] = tf32f(sout[i]);           // tf32-rounded feature copies
}

// ---------------------------------------------------------------------------
// prep_all: [0,1024) GCN; [1024,1536) y1 bias init; [1536,4608) Wl0 tf32.
// ---------------------------------------------------------------------------
__global__ void __launch_bounds__(256) prep_all(
    const float* __restrict__ xq, const float* __restrict__ xc,
    const float* __restrict__ Wg0, const float* __restrict__ bg0,
    const float* __restrict__ Wg1, const float* __restrict__ bg1,
    const float* __restrict__ Wg2, const float* __restrict__ bg2,
    const int* __restrict__ srcq, const int* __restrict__ dstq,
    const int* __restrict__ srcc, const int* __restrict__ dstc,
    const float* __restrict__ bl0, const float* __restrict__ Wl0)
{
    __shared__ __align__(16) float pool[10240];
    __shared__ int   ssrc[EPG];
    __shared__ int   sstart[65];
    __shared__ int   scnt[64];
    __shared__ float sdinv[64];

    const int b = blockIdx.x;
    const int t = threadIdx.x;

    if (b >= 2*NB_GRAPHS) {
        if (b < 2*NB_GRAPHS + 512) {
            int i = (b - 2*NB_GRAPHS)*256 + t;
            g_scratch[OFF_Y1 + i] = __ldg(&bl0[i & 255]);
        } else {
            int i = (b - (2*NB_GRAPHS + 512))*256 + t;   // float4 index
            float4 v = ((const float4*)Wl0)[i];
            float4 o;
            o.x = tf32f(v.x); o.y = tf32f(v.y); o.z = tf32f(v.z); o.w = tf32f(v.w);
            ((float4*)(g_scratch + OFF_WT0))[i] = o;
        }
        return;
    }

    const bool isC = (b >= NB_GRAPHS);
    const int gg  = isC ? b - NB_GRAPHS : b;
    const float* x = isC ? xc : xq;
    const int* src = isC ? srcc : srcq;
    const int* dst = isC ? dstc : dstq;

    const int nb = gg * M_NODES;
    const int eb = gg * EPG;

    if (t < 64) scnt[t] = 0;
    __syncthreads();

    for (int e = t; e < EPG; e += 256)
        atomicAdd(&scnt[dst[eb + e] - nb], 1);
    for (int i = t; i < 64*32; i += 256) pool[i] = x[(long)nb*32 + i];
    __syncthreads();

    if (t == 0) {
        int a = 0;
        for (int i = 0; i < 64; ++i) { sstart[i] = a; a += scnt[i]; }
        sstart[64] = a;
    }
    __syncthreads();
    if (t < 64) {
        scnt[t] = sstart[t];
        sdinv[t] = rsqrtf(1.0f + (float)(sstart[t + 1] - sstart[t]));
    }
    __syncthreads();

    for (int e = t; e < EPG; e += 256) {
        int d = dst[eb + e] - nb;
        int s = src[eb + e] - nb;
        int p = atomicAdd(&scnt[d], 1);
        ssrc[p] = s;
    }
    __syncthreads();

    gcn_layer_body<32,64>(pool, pool+2048, pool+6144, sdinv, sstart, ssrc,
                          Wg0, bg0, g_scratch + (isC?OFF_FC0:OFF_FQ0) + (long)nb*64, t);
    for (int i = t; i < 64*64; i += 256) pool[i] = fmaxf(pool[6144 + i], 0.f);
    __syncthreads();

    gcn_layer_body<64,32>(pool, pool+4096, pool+6144, sdinv, sstart, ssrc,
                          Wg1, bg1, g_scratch + (isC?OFF_FC1:OFF_FQ1) + (long)nb*32, t);
    for (int i = t; i < 64*32; i += 256) pool[i] = fmaxf(pool[6144 + i], 0.f);
    __syncthreads();

    gcn_layer_body<32,16>(pool, pool+2048, pool+3072, sdinv, sstart, ssrc,
                          Wg2, bg2, g_scratch + (isC?OFF_FC2:OFF_FQ2) + (long)nb*16, t);
}

// ---------------------------------------------------------------------------
// conv0 helper: o-paired f32x2, row-streamed (R7/R8 proven)
// ---------------------------------------------------------------------------
__device__ __forceinline__ void conv5x5_opair64(
    const float* __restrict__ plane, const u64* __restrict__ wq,
    u64 acc[4][4], int y0, int x0)
{
    #pragma unroll
    for (int dy = 0; dy < 8; ++dy) {
        const int yy = y0 + dy;
        const bool rowok = ((unsigned)yy < 64u);
        u64 sp[8];
        #pragma unroll
        for (int j = 0; j < 4; ++j) {
            int xx = x0 + 2*j;
            float2 v = make_float2(0.f, 0.f);
            if (rowok && (unsigned)xx < 64u)
                v = *(const float2*)(plane + yy*64 + xx);
            sp[2*j]   = pack2(v.x, v.x);
            sp[2*j+1] = pack2(v.y, v.y);
        }
        #pragma unroll
        for (int u = 0; u < 4; ++u) {
            const int ky = dy - u;
            if (ky >= 0 && ky < 5) {
                #pragma unroll
                for (int kx = 0; kx < 5; ++kx) {
                    u64 w = wq[ky*5 + kx];
                    #pragma unroll
                    for (int v = 0; v < 4; ++v)
                        acc[u][v] = fma2(sp[v + kx], w, acc[u][v]);
                }
            }
        }
    }
}

// ---------------------------------------------------------------------------
// Fused pair kernel: sim GEMM (tf32 mma) + conv0 (f32x2 o-paired) +
// conv1 (tf32 mma, channel-interleaved planes, ldmatrix A feed) +
// warp-shuffle pooling epilogue (no smem roundtrip, no extra syncs)
//
// Dynamic smem buf (19648 floats):
//   sim    : [0,4096)        phase 1-2; reused for sw1 in phase 3
//   sq     : [4096,8448)     phase 0-1 ([m][F+4] padded)
//   scB    : [8448,13056)    phase 0-1 ([k][72])
//   planes : [4096,19648)    phase 2-3b (1296 px x stride 12, tf32, ch-interleaved)
// ---------------------------------------------------------------------------
__global__ void __launch_bounds__(256, 2) pair_all(
    const float* __restrict__ cw0, const float* __restrict__ cb0,
    const float* __restrict__ cw1, const float* __restrict__ cb1)
{
    extern __shared__ __align__(16) float buf[];
    __shared__ u64 sw0u[100];   // conv0 weights as (o,o+1) pairs: [op*25 + tap]

    float* sim    = buf;
    float* sq     = buf + 4096;
    float* scB    = buf + 8448;
    float* planes = buf + 4096;
    float* sw1    = buf;        // [tap*136 + c*17 + o]

    const int simi = blockIdx.x % 3;
    const int bk   = blockIdx.x / 3;
    const int lf   = 6 - simi;               // log2(F)
    const int F    = 1 << lf;                // 64, 32, 16
    const int SP   = F + 4;                  // padded sq stride
    const int offq = (simi == 0) ? OFF_FQ0 : (simi == 1) ? OFF_FQ1 : OFF_FQ2;
    const int offc = (simi == 0) ? OFF_FC0 : (simi == 1) ? OFF_FC1 : OFF_FC2;
    const float* cw0p = cw0 + simi*200;
    const float* cb0p = cb0 + simi*8;
    const float* cw1p = cw1 + simi*3200;
    const float* cb1p = cb1 + simi*16;

    const int t = threadIdx.x;
    const int warp = t >> 5, lane = t & 31, g = lane >> 2, tig = lane & 3;
    const float* fq = g_scratch + offq + ((long)bk << (6 + lf));
    const float* fc = g_scratch + offc + ((long)bk << (6 + lf));

    // ---- phase 0: stage features (tf32-valued) + conv0 weights ----
    for (int i = t; i < (64 << lf); i += 256) {
        int n = i >> lf, k = i & (F - 1);
        sq[n*SP + k] = fq[i];
    }
    for (int i = t; i < (64 << lf); i += 256) {
        int n = i >> lf, k = i & (F - 1);
        scB[k*72 + n] = fc[i];
    }
    if (t < 100) {
        int op = t / 25, tap = t % 25;
        sw0u[t] = pack2(__ldg(&cw0p[(2*op)*25 + tap]),
                        __ldg(&cw0p[(2*op + 1)*25 + tap]));
    }
    __syncthreads();

    // ---- phase 1: similarity GEMM on tensor cores -> sim[64][64] (fp32) ----
    {
        const int wm = warp & 3;
        const int n0base = (warp >> 2) * 32;
        float c[4][4];
        #pragma unroll
        for (int ni = 0; ni < 4; ++ni)
            #pragma unroll
            for (int r = 0; r < 4; ++r) c[ni][r] = 0.f;

        const int nk = F >> 3;
        for (int kk = 0; kk < nk; ++kk) {
            const float* ap = sq + (wm*16 + g)*SP + kk*8 + tig;
            unsigned a0 = __float_as_uint(ap[0]);
            unsigned a1 = __float_as_uint(ap[8*SP]);
            unsigned a2 = __float_as_uint(ap[4]);
            unsigned a3 = __float_as_uint(ap[8*SP + 4]);
            const float* bp = scB + (kk*8 + tig)*72 + n0base + g;
            #pragma unroll
            for (int ni = 0; ni < 4; ++ni) {
                unsigned b0 = __float_as_uint(bp[ni*8]);
                unsigned b1 = __float_as_uint(bp[4*72 + ni*8]);
                mma_tf32(c[ni], a0, a1, a2, a3, b0, b1);
            }
        }
        #pragma unroll
        for (int ni = 0; ni < 4; ++ni) {
            int col = n0base + ni*8 + 2*tig;
            int row = wm*16 + g;
            *(float2*)&sim[row*64 + col]     = make_float2(c[ni][0], c[ni][1]);
            *(float2*)&sim[(row+8)*64 + col] = make_float2(c[ni][2], c[ni][3]);
        }
    }
    __syncthreads();

    // ---- phase 2a: zero halo pixels (interior fully overwritten by conv0) ----
    for (int i = t; i < 272; i += 256) {
        int pix;
        if (i < 72)       pix = i;                       // rows 0-1
        else if (i < 144) pix = 34*36 + (i - 72);        // rows 34-35
        else {
            int j = i - 144;                             // 0..127
            int row = 2 + (j >> 2);
            int col = (j & 3); col = (col < 2) ? col : col + 32;
            pix = row*36 + col;
        }
        float4* p4 = (float4*)(planes + pix*12);
        p4[0] = make_float4(0.f,0.f,0.f,0.f);
        p4[1] = make_float4(0.f,0.f,0.f,0.f);
    }
    __syncthreads();

    // ---- phase 2b: conv0 (1->8, o-paired) + relu + pool -> interleaved planes ----
    {
        const int ty = t >> 4, tx = t & 15;
        const int y0 = 4*ty - 2, x0 = 4*tx - 2;
        for (int op = 0; op < 4; ++op) {
            u64 wq[25];
            #pragma unroll
            for (int i = 0; i < 25; ++i) wq[i] = sw0u[op*25 + i];
            u64 binit = pack2(__ldg(&cb0p[2*op]), __ldg(&cb0p[2*op + 1]));
            u64 acc[4][4];
            #pragma unroll
            for (int u = 0; u < 4; ++u)
                #pragma unroll
                for (int v = 0; v < 4; ++v) acc[u][v] = binit;
            conv5x5_opair64(sim, wq, acc, y0, x0);
            #pragma unroll
            for (int a = 0; a < 2; ++a)
                #pragma unroll
                for (int b = 0; b < 2; ++b) {
                    float2 p00 = unpack2(acc[2*a][2*b]);
                    float2 p01 = unpack2(acc[2*a][2*b+1]);
                    float2 p10 = unpack2(acc[2*a+1][2*b]);
                    float2 p11 = unpack2(acc[2*a+1][2*b+1]);
                    float mlo = fmaxf(fmaxf(p00.x, p01.x), fmaxf(p10.x, p11.x));
                    float mhi = fmaxf(fmaxf(p00.y, p01.y), fmaxf(p10.y, p11.y));
                    int pix = (2 + 2*ty + a)*36 + (2 + 2*tx + b);
                    *(float2*)&planes[pix*12 + 2*op] =
                        make_float2(tf32f(fmaxf(mlo, 0.f)), tf32f(fmaxf(mhi, 0.f)));
                }
        }
    }
    __syncthreads();

    // ---- phase 3a: stage conv1 weights [tap][ch][o], tf32-rounded ----
    for (int i = t; i < 3200; i += 256) {
        int o = i & 15, j = i >> 4;          // j = c*25 + tap
        int c = j / 25, tap = j - c*25;
        sw1[tap*136 + c*17 + o] = tf32f(__ldg(&cw1p[o*200 + j]));
    }
    __syncthreads();

    // ---- phase 3b: conv1 as per-tap K=8 mma over channels, A via ldmatrix ----
    const unsigned planes_s = (unsigned)__cvta_generic_to_shared(planes);
    const int rowl = (lane & 7) + ((lane >> 3) & 1) * 8;
    const unsigned lane_off = (unsigned)(rowl*48 + (lane >> 4)*16);

    float acc[8][2][4];
    #pragma unroll
    for (int mi = 0; mi < 8; ++mi)
        #pragma unroll
        for (int ni = 0; ni < 2; ++ni)
            #pragma unroll
            for (int r = 0; r < 4; ++r) acc[mi][ni][r] = 0.f;

    unsigned addr_mi[8];
    #pragma unroll
    for (int mi = 0; mi < 8; ++mi) {
        int mt = warp*8 + mi;
        int pix0 = (mt >> 1)*36 + (mt & 1)*16;
        addr_mi[mi] = planes_s + (unsigned)(pix0*48) + lane_off;
    }

    #pragma unroll
    for (int ky = 0; ky < 5; ++ky) {
        #pragma unroll
        for (int kx = 0; kx < 5; ++kx) {
            const float* wt = sw1 + (ky*5 + kx)*136;
            const unsigned tapoff = (unsigned)((ky*36 + kx)*48);
            unsigned b00 = __float_as_uint(wt[tig*17 + g]);
            unsigned b01 = __float_as_uint(wt[(tig+4)*17 + g]);
            unsigned b10 = __float_as_uint(wt[tig*17 + 8 + g]);
            unsigned b11 = __float_as_uint(wt[(tig+4)*17 + 8 + g]);
            #pragma unroll
            for (int mi = 0; mi < 8; ++mi) {
                unsigned a0, a1, a2, a3;
                ldsm_x4(a0, a1, a2, a3, addr_mi[mi] + tapoff);
                mma_tf32(acc[mi][0], a0, a1, a2, a3, b00, b01);
                mma_tf32(acc[mi][1], a0, a1, a2, a3, b10, b11);
            }
        }
    }

    // ---- phase 3c: warp-shuffle pooling, direct global write ----
    // Fragment map: mt = warp*8+mi covers conv row y = w*4 + (mi>>1),
    //   x half (mi&1); fragment row g -> x = 16*(mi&1)+g (c[0],c[1]),
    //   row g+8 -> x+8 (c[2],c[3]); cols = channels ni*8 + 2*tig (+1).
    // y-pool partners: (mi, mi+2) same thread. x-pool partners: shfl_down 4.
    {
        float* hout = g_scratch + OFF_H + simi*4096 + (long)bk * 12288;
        #pragma unroll
        for (int h = 0; h < 2; ++h)
            #pragma unroll
            for (int xh = 0; xh < 2; ++xh) {
                const int miA = 4*h + xh, miB = miA + 2;
                #pragma unroll
                for (int ni = 0; ni < 2; ++ni) {
                    float ym[4], nb[4];
                    #pragma unroll
                    for (int r = 0; r < 4; ++r)
                        ym[r] = fmaxf(acc[miA][ni][r], acc[miB][ni][r]);
                    #pragma unroll
                    for (int r = 0; r < 4; ++r)
                        nb[r] = __shfl_down_sync(0xffffffffu, ym[r], 4);
                    if ((g & 1) == 0) {
                        const int Y   = 2*warp + h;
                        const int XpL = 8*xh + (g >> 1);
                        const int XpH = XpL + 4;
                        #pragma unroll
                        for (int cc = 0; cc < 2; ++cc) {
                            const int o = ni*8 + 2*tig + cc;
                            const float b = __ldg(&cb1p[o]);
                            float vL = fmaxf(fmaxf(ym[cc],   nb[cc])   + b, 0.f);
                            float vH = fmaxf(fmaxf(ym[2+cc], nb[2+cc]) + b, 0.f);
                            hout[o*256 + Y*16 + XpL] = tf32f(vL);
                            hout[o*256 + Y*16 + XpH] = tf32f(vH);
                        }
                    }
                }
            }
    }
}

// ---------------------------------------------------------------------------
// MLP layer 0: y1 += h @ Wl0. tf32 mma, cp.async double-buffered (proven).
// ---------------------------------------------------------------------------
#define G1_KC 768
#define G1_KT 32
#define G1_NT 24
#define AS_STRIDE 36
#define BS_STRIDE 72
#define AS_SZ (128*AS_STRIDE)
#define BS_SZ (32*BS_STRIDE)

__global__ void __launch_bounds__(256) gemm1_kernel()
{
    extern __shared__ __align__(16) float gbuf[];
    const float* A = g_scratch + OFF_H;
    const float* B = g_scratch + OFF_WT0;
    float* C = g_scratch + OFF_Y1;

    const int r0 = blockIdx.x * 128;
    const int c0 = blockIdx.y * 64;
    const int k0 = blockIdx.z * G1_KC;

    const int t = threadIdx.x, warp = t >> 5, lane = t & 31;
    const int g = lane >> 2, tig = lane & 3;
    const int wm = warp & 3, wn = warp >> 2;

    float acc[2][4][4];
    #pragma unroll
    for (int mi = 0; mi < 2; ++mi)
        #pragma unroll
        for (int ni = 0; ni < 4; ++ni)
            #pragma unroll
            for (int r = 0; r < 4; ++r) acc[mi][ni][r] = 0.f;

    auto issue = [&](int ibuf, int kt) {
        float* As = gbuf + ibuf*AS_SZ;
        float* Bs = gbuf + 2*AS_SZ + ibuf*BS_SZ;
        #pragma unroll
        for (int j = 0; j < 4; ++j) {
            int cid = t + 256*j;
            int row = cid >> 3, seg = cid & 7;
            cp_async16(&As[row*AS_STRIDE + seg*4],
                       A + (long)(r0 + row)*12288 + k0 + kt + seg*4);
        }
        #pragma unroll
        for (int j = 0; j < 2; ++j) {
            int cid = t + 256*j;
            int k = cid >> 4, seg = cid & 15;
            cp_async16(&Bs[k*BS_STRIDE + seg*4],
                       B + (long)(k0 + kt + k)*256 + c0 + seg*4);
        }
        asm volatile("cp.async.commit_group;");
    };

    issue(0, 0);
    issue(1, G1_KT);

    for (int i = 0; i < G1_NT; ++i) {
        if (i < G1_NT - 1) asm volatile("cp.async.wait_group 1;");
        else               asm volatile("cp.async.wait_group 0;");
        __syncthreads();

        const float* As = gbuf + (i & 1)*AS_SZ;
        const float* Bs = gbuf + 2*AS_SZ + (i & 1)*BS_SZ;
        #pragma unroll
        for (int kc = 0; kc < 4; ++kc) {
            unsigned af[2][4], bf[4][2];
            #pragma unroll
            for (int mi = 0; mi < 2; ++mi) {
                const float* ap = As + (wm*32 + mi*16 + g)*AS_STRIDE + kc*8 + tig;
                af[mi][0] = __float_as_uint(ap[0]);
                af[mi][1] = __float_as_uint(ap[8*AS_STRIDE]);
                af[mi][2] = __float_as_uint(ap[4]);
                af[mi][3] = __float_as_uint(ap[8*AS_STRIDE + 4]);
            }
            #pragma unroll
            for (int ni = 0; ni < 4; ++ni) {
                const float* bp = Bs + (kc*8 + tig)*BS_STRIDE + wn*32 + ni*8 + g;
                bf[ni][0] = __float_as_uint(bp[0]);
                bf[ni][1] = __float_as_uint(bp[4*BS_STRIDE]);
            }
            #pragma unroll
            for (int mi = 0; mi < 2; ++mi)
                #pragma unroll
                for (int ni = 0; ni < 4; ++ni)
                    mma_tf32(acc[mi][ni], af[mi][0], af[mi][1], af[mi][2], af[mi][3],
                             bf[ni][0], bf[ni][1]);
        }
        __syncthreads();
        if (i + 2 < G1_NT) issue(i & 1, (i + 2)*G1_KT);
    }

    #pragma unroll
    for (int mi = 0; mi < 2; ++mi) {
        int R = r0 + wm*32 + mi*16 + g;
        #pragma unroll
        for (int ni = 0; ni < 4; ++ni) {
            int Cc = c0 + wn*32 + ni*8 + 2*tig;
            atomicAdd(&C[R*256 + Cc],         acc[mi][ni][0]);
            atomicAdd(&C[R*256 + Cc + 1],     acc[mi][ni][1]);
            atomicAdd(&C[(R+8)*256 + Cc],     acc[mi][ni][2]);
            atomicAdd(&C[(R+8)*256 + Cc + 1], acc[mi][ni][3]);
        }
    }
}

// ---------------------------------------------------------------------------
// Head: split-K (4 slices of 64), 256 threads/block, one block per row.
// (R8-proven version: 15.4us)
// ---------------------------------------------------------------------------
__global__ void __launch_bounds__(256) head_kernel(
    const float* __restrict__ Wl1, const float* __restrict__ bl1,
    const float* __restrict__ Wsc, const float* __restrict__ bsc,
    float* __restrict__ out)
{
    const int r = blockIdx.x;
    const int t = threadIdx.x;
    __shared__ float sy[256];
    __shared__ float part[4][64];
    __shared__ float red[2];

    sy[t] = fmaxf(g_scratch[OFF_Y1 + (long)r*256 + t], 0.f);
    __syncthreads();

    const int j = t & 63, ks = t >> 6;
    float acc = 0.f;
    #pragma unroll 16
    for (int k = 64*ks; k < 64*ks + 64; ++k)
        acc += sy[k] * __ldg(&Wl1[k*64 + j]);
    part[ks][j] = acc;
    __syncthreads();

    if (t < 64) {
        float a = part[0][t] + part[1][t] + part[2][t] + part[3][t] + __ldg(&bl1[t]);
        float v = fmaxf(a, 0.f) * __ldg(&Wsc[t]);
        #pragma unroll
        for (int off = 16; off > 0; off >>= 1)
            v += __shfl_down_sync(0xffffffffu, v, off);
        if ((t & 31) == 0) red[t >> 5] = v;
    }
    __syncthreads();
    if (t == 0) {
        float s = red[0] + red[1] + __ldg(&bsc[0]);
        out[r] = 1.f / (1.f + expf(-s));
    }
}

// ---------------------------------------------------------------------------
// Launch
// ---------------------------------------------------------------------------
#define PAIR_SMEM (19648*4)
#define G1_SMEM ((2*AS_SZ + 2*BS_SZ)*4)

extern "C" void kernel_launch(void* const* d_in, const int* in_sizes, int n_in,
                              void* d_out, int out_size)
{
    (void)in_sizes; (void)n_in; (void)out_size;
    const float* x_q  = (const float*)d_in[0];
    const float* x_c  = (const float*)d_in[1];
    const int*   src_q = (const int*)d_in[2];
    const int*   dst_q = (const int*)d_in[3];
    const int*   src_c = (const int*)d_in[4];
    const int*   dst_c = (const int*)d_in[5];
    const float* Wg0 = (const float*)d_in[6];
    const float* bg0 = (const float*)d_in[7];
    const float* Wg1 = (const float*)d_in[8];
    const float* bg1 = (const float*)d_in[9];
    const float* Wg2 = (const float*)d_in[10];
    const float* bg2 = (const float*)d_in[11];
    const float* cw0 = (const float*)d_in[12];
    const float* cb0 = (const float*)d_in[13];
    const float* cw1 = (const float*)d_in[14];
    const float* cb1 = (const float*)d_in[15];
    const float* Wl0 = (const float*)d_in[16];
    const float* bl0 = (const float*)d_in[17];
    const float* Wl1 = (const float*)d_in[18];
    const float* bl1 = (const float*)d_in[19];
    const float* Wsc = (const float*)d_in[20];
    const float* bsc = (const float*)d_in[21];
    float* out = (float*)d_out;

    static int attr_done = 0;
    if (!attr_done) {
        cudaFuncSetAttribute(pair_all,  cudaFuncAttributeMaxDynamicSharedMemorySize, PAIR_SMEM);
        cudaFuncSetAttribute(gemm1_kernel, cudaFuncAttributeMaxDynamicSharedMemorySize, G1_SMEM);
        attr_done = 1;
    }

    // fused: 3-layer GCN (1024 blocks) + y1 bias init (512) + Wl0 tf32 (3072)
    prep_all<<<2*NB_GRAPHS + 512 + 3072, 256>>>(
        x_q, x_c, Wg0, bg0, Wg1, bg1, Wg2, bg2,
        src_q, dst_q, src_c, dst_c, bl0, Wl0);

    // fused sim + conv stacks (all 3 sims)
    pair_all<<<3*NB_GRAPHS, 256, PAIR_SMEM>>>(cw0, cb0, cw1, cb1);

    // MLP layer 0 on tensor cores, then head
    gemm1_kernel<<<dim3(4, 4, 16), 256, G1_SMEM>>>();
    head_kernel<<<512, 256>>>(Wl1, bl1, Wsc, bsc, out);
}

// round 12
// speedup vs baseline: 3.0932x; 1.0021x over previous
#include <cuda_runtime.h>
#include <math.h>

// ---------------------------------------------------------------------------
// Problem constants
// ---------------------------------------------------------------------------
#define NB_GRAPHS 512          // B
#define M_NODES   64           // nodes per graph
#define EPG       512          // edges per graph

// ---------------------------------------------------------------------------
// Scratch layout (single __device__ array, no allocations)
// ---------------------------------------------------------------------------
#define SZ_F0 (32768*64)
#define SZ_F1 (32768*32)
#define SZ_F2 (32768*16)
#define SZ_H  (512*12288)
#define SZ_Y1 (512*256)
#define SZ_WT0 (12288*256)

#define OFF_FQ0 0
#define OFF_FC0 (OFF_FQ0 + SZ_F0)
#define OFF_FQ1 (OFF_FC0 + SZ_F0)
#define OFF_FC1 (OFF_FQ1 + SZ_F1)
#define OFF_FQ2 (OFF_FC1 + SZ_F1)
#define OFF_FC2 (OFF_FQ2 + SZ_F2)
#define OFF_H   (OFF_FC2 + SZ_F2)
#define OFF_Y1  (OFF_H + SZ_H)
#define OFF_WT0 (OFF_Y1 + SZ_Y1)
#define SCRATCH_TOTAL (OFF_WT0 + SZ_WT0)

__device__ float g_scratch[SCRATCH_TOTAL];

// ---------------------------------------------------------------------------
// Helpers
// ---------------------------------------------------------------------------
typedef unsigned long long u64;

__device__ __forceinline__ unsigned f2tf32(float f) {
    unsigned u; asm("cvt.rna.tf32.f32 %0, %1;" : "=r"(u) : "f"(f)); return u;
}
__device__ __forceinline__ float tf32f(float f) {
    return __uint_as_float(f2tf32(f));
}
__device__ __forceinline__ void cp_async16(float* dst, const float* src) {
    unsigned d = (unsigned)__cvta_generic_to_shared(dst);
    asm volatile("cp.async.cg.shared.global [%0], [%1], 16;" :: "r"(d), "l"(src));
}
__device__ __forceinline__ void mma_tf32(float c[4],
    unsigned a0, unsigned a1, unsigned a2, unsigned a3,
    unsigned b0, unsigned b1)
{
    asm volatile(
        "mma.sync.aligned.m16n8k8.row.col.f32.tf32.tf32.f32 "
        "{%0,%1,%2,%3}, {%4,%5,%6,%7}, {%8,%9}, {%0,%1,%2,%3};"
        : "+f"(c[0]), "+f"(c[1]), "+f"(c[2]), "+f"(c[3])
        : "r"(a0), "r"(a1), "r"(a2), "r"(a3), "r"(b0), "r"(b1));
}
__device__ __forceinline__ void ldsm_x4(unsigned& r0, unsigned& r1,
                                        unsigned& r2, unsigned& r3, unsigned addr)
{
    asm volatile("ldmatrix.sync.aligned.m8n8.x4.shared.b16 {%0,%1,%2,%3}, [%4];"
        : "=r"(r0), "=r"(r1), "=r"(r2), "=r"(r3) : "r"(addr));
}

// ---------------------------------------------------------------------------
// GCN layer body (float4-vectorized GEMM). Feature outputs tf32-rounded so
// the sim GEMM can consume them as raw tensor-core fragments.
// ---------------------------------------------------------------------------
template<int FIN, int FOUT>
__device__ __forceinline__ void gcn_layer_body(
    const float* __restrict__ sx, float* __restrict__ sA, float* __restrict__ sout,
    const float* __restrict__ sdinv,
    const int* __restrict__ sstart, const int* __restrict__ ssrc,
    const float* __restrict__ W, const float* __restrict__ bias,
    float* __restrict__ outg, int t)
{
    {
        const int j = t % FOUT;
        float wcol[FIN];
        #pragma unroll
        for (int k = 0; k < FIN; ++k) wcol[k] = __ldg(&W[k*FOUT + j]);
        for (int i = t; i < 64*FOUT; i += 256) {
            int n = i / FOUT;
            const float4* xr = (const float4*)(sx + n*FIN);
            float acc = 0.f;
            #pragma unroll
            for (int k4 = 0; k4 < FIN/4; ++k4) {
                float4 xv = xr[k4];
                acc += xv.x*wcol[4*k4] + xv.y*wcol[4*k4+1]
                     + xv.z*wcol[4*k4+2] + xv.w*wcol[4*k4+3];
            }
            sA[i] = acc * sdinv[n];
        }
    }
    __syncthreads();

    {
        const int wp = t >> 5, lane = t & 31;
        constexpr int CH = (FOUT + 31) / 32;
        for (int d = wp; d < 64; d += 8) {
            const int e0 = sstart[d], e1 = sstart[d + 1];
            const float dv = sdinv[d];
            float a[CH];
            #pragma unroll
            for (int c = 0; c < CH; ++c) {
                int j = lane + 32*c;
                a[c] = (j < FOUT) ? sA[d*FOUT + j] : 0.f;
            }
            for (int e = e0; e < e1; ++e) {
                int s = ssrc[e];
                #pragma unroll
                for (int c = 0; c < CH; ++c) {
                    int j = lane + 32*c;
                    if (j < FOUT) a[c] += sA[s*FOUT + j];
                }
            }
            #pragma unroll
            for (int c = 0; c < CH; ++c) {
                int j = lane + 32*c;
                if (j < FOUT) sout[d*FOUT + j] = dv*a[c] + __ldg(&bias[j]);
            }
        }
    }
    __syncthreads();

    for (int i = t; i < 64*FOUT; i += 256)
        outg[i] = tf32f(sout[i]);           // tf32-rounded feature copies
}

// ---------------------------------------------------------------------------
// prep_all: [0,1024) GCN; [1024,1536) y1 bias init; [1536,4608) Wl0 tf32.
// ---------------------------------------------------------------------------
__global__ void __launch_bounds__(256) prep_all(
    const float* __restrict__ xq, const float* __restrict__ xc,
    const float* __restrict__ Wg0, const float* __restrict__ bg0,
    const float* __restrict__ Wg1, const float* __restrict__ bg1,
    const float* __restrict__ Wg2, const float* __restrict__ bg2,
    const int* __restrict__ srcq, const int* __restrict__ dstq,
    const int* __restrict__ srcc, const int* __restrict__ dstc,
    const float* __restrict__ bl0, const float* __restrict__ Wl0)
{
    __shared__ __align__(16) float pool[10240];
    __shared__ int   ssrc[EPG];
    __shared__ int   sstart[65];
    __shared__ int   scnt[64];
    __shared__ float sdinv[64];

    const int b = blockIdx.x;
    const int t = threadIdx.x;

    if (b >= 2*NB_GRAPHS) {
        if (b < 2*NB_GRAPHS + 512) {
            int i = (b - 2*NB_GRAPHS)*256 + t;
            g_scratch[OFF_Y1 + i] = __ldg(&bl0[i & 255]);
        } else {
            int i = (b - (2*NB_GRAPHS + 512))*256 + t;   // float4 index
            float4 v = ((const float4*)Wl0)[i];
            float4 o;
            o.x = tf32f(v.x); o.y = tf32f(v.y); o.z = tf32f(v.z); o.w = tf32f(v.w);
            ((float4*)(g_scratch + OFF_WT0))[i] = o;
        }
        return;
    }

    const bool isC = (b >= NB_GRAPHS);
    const int gg  = isC ? b - NB_GRAPHS : b;
    const float* x = isC ? xc : xq;
    const int* src = isC ? srcc : srcq;
    const int* dst = isC ? dstc : dstq;

    const int nb = gg * M_NODES;
    const int eb = gg * EPG;

    if (t < 64) scnt[t] = 0;
    __syncthreads();

    for (int e = t; e < EPG; e += 256)
        atomicAdd(&scnt[dst[eb + e] - nb], 1);
    for (int i = t; i < 64*32; i += 256) pool[i] = x[(long)nb*32 + i];
    __syncthreads();

    if (t == 0) {
        int a = 0;
        for (int i = 0; i < 64; ++i) { sstart[i] = a; a += scnt[i]; }
        sstart[64] = a;
    }
    __syncthreads();
    if (t < 64) {
        scnt[t] = sstart[t];
        sdinv[t] = rsqrtf(1.0f + (float)(sstart[t + 1] - sstart[t]));
    }
    __syncthreads();

    for (int e = t; e < EPG; e += 256) {
        int d = dst[eb + e] - nb;
        int s = src[eb + e] - nb;
        int p = atomicAdd(&scnt[d], 1);
        ssrc[p] = s;
    }
    __syncthreads();

    gcn_layer_body<32,64>(pool, pool+2048, pool+6144, sdinv, sstart, ssrc,
                          Wg0, bg0, g_scratch + (isC?OFF_FC0:OFF_FQ0) + (long)nb*64, t);
    for (int i = t; i < 64*64; i += 256) pool[i] = fmaxf(pool[6144 + i], 0.f);
    __syncthreads();

    gcn_layer_body<64,32>(pool, pool+4096, pool+6144, sdinv, sstart, ssrc,
                          Wg1, bg1, g_scratch + (isC?OFF_FC1:OFF_FQ1) + (long)nb*32, t);
    for (int i = t; i < 64*32; i += 256) pool[i] = fmaxf(pool[6144 + i], 0.f);
    __syncthreads();

    gcn_layer_body<32,16>(pool, pool+2048, pool+3072, sdinv, sstart, ssrc,
                          Wg2, bg2, g_scratch + (isC?OFF_FC2:OFF_FQ2) + (long)nb*16, t);
}

// ---------------------------------------------------------------------------
// Fused pair kernel: sim GEMM (tf32 mma, halo-padded output) +
// conv0 (tf32 mma implicit GEMM, M=4096 N=8 K=32-padded, shuffle pool) +
// conv1 (tf32 mma, channel-interleaved planes, ldmatrix A feed, shuffle pool)
//
// Dynamic smem buf (20176 floats = 80704 B):
//   simh   : [0,4624)        68x68 halo sim (tf32); reused for sw1 in phase 3
//   sq     : [4624,8976)     phase 0-1 ([m][F+4] padded)
//   scB    : [8976,13584)    phase 0-1 ([k][72])
//   planes : [4624,20176)    phase 2-3b (1296 px x stride 12, tf32, ch-interleaved)
// ---------------------------------------------------------------------------
__global__ void __launch_bounds__(256, 2) pair_all(
    const float* __restrict__ cw0, const float* __restrict__ cb0,
    const float* __restrict__ cw1, const float* __restrict__ cb1)
{
    extern __shared__ __align__(16) float buf[];
    __shared__ float sw0t[32*12];   // conv0 weights [k][o] stride 12, taps 25-31 zero
    __shared__ int   soff0[32];     // conv0 tap offsets in simh (68-stride)

    float* simh   = buf;            // [0,4624)
    float* sq     = buf + 4624;
    float* scB    = buf + 8976;
    float* planes = buf + 4624;
    float* sw1    = buf;            // [tap*136 + c*17 + o] (phase 3; simh dead)

    const int simi = blockIdx.x % 3;
    const int bk   = blockIdx.x / 3;
    const int lf   = 6 - simi;               // log2(F)
    const int F    = 1 << lf;                // 64, 32, 16
    const int SP   = F + 4;                  // padded sq stride
    const int offq = (simi == 0) ? OFF_FQ0 : (simi == 1) ? OFF_FQ1 : OFF_FQ2;
    const int offc = (simi == 0) ? OFF_FC0 : (simi == 1) ? OFF_FC1 : OFF_FC2;
    const float* cw0p = cw0 + simi*200;
    const float* cb0p = cb0 + simi*8;
    const float* cw1p = cw1 + simi*3200;
    const float* cb1p = cb1 + simi*16;

    const int t = threadIdx.x;
    const int warp = t >> 5, lane = t & 31, g = lane >> 2, tig = lane & 3;
    const float* fq = g_scratch + offq + ((long)bk << (6 + lf));
    const float* fc = g_scratch + offc + ((long)bk << (6 + lf));

    // ---- phase 0: stage features + conv0 weights + zero simh halo ----
    for (int i = t; i < (64 << lf); i += 256) {
        int n = i >> lf, k = i & (F - 1);
        sq[n*SP + k] = fq[i];
    }
    for (int i = t; i < (64 << lf); i += 256) {
        int n = i >> lf, k = i & (F - 1);
        scB[k*72 + n] = fc[i];
    }
    {   // conv0 weights: [k][o] stride 12 (banks conflict-free), zero-pad k>=25
        int k = t >> 3, o = t & 7;           // 256 threads = 32 x 8 exactly
        float w = (k < 25) ? __ldg(&cw0p[o*25 + k]) : 0.f;
        sw0t[k*12 + o] = tf32f(w);
        if (t < 32) soff0[t] = (t < 25) ? (t/5)*68 + (t%5) : 0;
    }
    // simh halo: rows {0,1,66,67} full (272) + cols {0,1,66,67} of rows 2..65 (256)
    for (int i = t; i < 528; i += 256) {
        int idx;
        if (i < 272) {
            int r = (i < 136) ? (i/68) : 66 + (i-136)/68;
            idx = r*68 + (i % 68);
        } else {
            int j = i - 272;
            int r = 2 + (j >> 2);
            int cm = j & 3;
            int c = (cm < 2) ? cm : 64 + cm;
            idx = r*68 + c;
        }
        simh[idx] = 0.f;
    }
    __syncthreads();

    // ---- phase 1: similarity GEMM on tensor cores -> simh (halo, tf32) ----
    {
        const int wm = warp & 3;
        const int n0base = (warp >> 2) * 32;
        float c[4][4];
        #pragma unroll
        for (int ni = 0; ni < 4; ++ni)
            #pragma unroll
            for (int r = 0; r < 4; ++r) c[ni][r] = 0.f;

        const int nk = F >> 3;
        for (int kk = 0; kk < nk; ++kk) {
            const float* ap = sq + (wm*16 + g)*SP + kk*8 + tig;
            unsigned a0 = __float_as_uint(ap[0]);
            unsigned a1 = __float_as_uint(ap[8*SP]);
            unsigned a2 = __float_as_uint(ap[4]);
            unsigned a3 = __float_as_uint(ap[8*SP + 4]);
            const float* bp = scB + (kk*8 + tig)*72 + n0base + g;
            #pragma unroll
            for (int ni = 0; ni < 4; ++ni) {
                unsigned b0 = __float_as_uint(bp[ni*8]);
                unsigned b1 = __float_as_uint(bp[4*72 + ni*8]);
                mma_tf32(c[ni], a0, a1, a2, a3, b0, b1);
            }
        }
        // write interior at (row+2, col+2), tf32-rounded (conv0 A operand)
        #pragma unroll
        for (int ni = 0; ni < 4; ++ni) {
            int col = n0base + ni*8 + 2*tig;
            int row = wm*16 + g;
            *(float2*)&simh[(row+2)*68 + col+2] =
                make_float2(tf32f(c[ni][0]), tf32f(c[ni][1]));
            *(float2*)&simh[(row+10)*68 + col+2] =
                make_float2(tf32f(c[ni][2]), tf32f(c[ni][3]));
        }
    }
    __syncthreads();

    // ---- phase 2a: zero planes halo pixels ----
    for (int i = t; i < 272; i += 256) {
        int pix;
        if (i < 72)       pix = i;                       // rows 0-1
        else if (i < 144) pix = 34*36 + (i - 72);        // rows 34-35
        else {
            int j = i - 144;                             // 0..127
            int row = 2 + (j >> 2);
            int col = (j & 3); col = (col < 2) ? col : col + 32;
            pix = row*36 + col;
        }
        float4* p4 = (float4*)(planes + pix*12);
        p4[0] = make_float4(0.f,0.f,0.f,0.f);
        p4[1] = make_float4(0.f,0.f,0.f,0.f);
    }

    // ---- phase 2b: conv0 as tf32 implicit GEMM + shuffle pool -> planes ----
    // tile mt: y = mt>>2, x-quarter = mt&3; warp covers mt in [warp*32, warp*32+32)
    // A[m=x0+r][k=tap] = simh[y*68 + x0 + r + soff0[tap]]
    // C frag: c[0],c[1] = x0+g, ch 2tig,2tig+1; c[2],c[3] = x0+g+8.
    {
        // hoist B fragments (same for every tile)
        unsigned bw[4][2];
        #pragma unroll
        for (int kk = 0; kk < 4; ++kk) {
            bw[kk][0] = __float_as_uint(sw0t[(kk*8 + tig)*12 + g]);
            bw[kk][1] = __float_as_uint(sw0t[(kk*8 + tig + 4)*12 + g]);
        }
        const float bias01[2] = { __ldg(&cb0p[2*tig]), __ldg(&cb0p[2*tig + 1]) };

        #pragma unroll
        for (int yb = 0; yb < 4; ++yb) {
            #pragma unroll
            for (int xq = 0; xq < 4; ++xq) {
                const int y0 = warp*8 + 2*yb;          // even conv row
                const int x0 = xq*16;
                const float* pA = simh + y0*68 + x0;
                const float* pB = pA + 68;              // odd row

                float accA[4] = {0.f,0.f,0.f,0.f};
                float accB[4] = {0.f,0.f,0.f,0.f};
                #pragma unroll
                for (int kk = 0; kk < 4; ++kk) {
                    const int klo = kk*8 + tig;
                    const int o1 = soff0[klo], o2 = soff0[klo + 4];
                    {
                        unsigned a0 = __float_as_uint(pA[o1 + g]);
                        unsigned a1 = __float_as_uint(pA[o1 + g + 8]);
                        unsigned a2 = __float_as_uint(pA[o2 + g]);
                        unsigned a3 = __float_as_uint(pA[o2 + g + 8]);
                        mma_tf32(accA, a0, a1, a2, a3, bw[kk][0], bw[kk][1]);
                    }
                    {
                        unsigned a0 = __float_as_uint(pB[o1 + g]);
                        unsigned a1 = __float_as_uint(pB[o1 + g + 8]);
                        unsigned a2 = __float_as_uint(pB[o2 + g]);
                        unsigned a3 = __float_as_uint(pB[o2 + g + 8]);
                        mma_tf32(accB, a0, a1, a2, a3, bw[kk][0], bw[kk][1]);
                    }
                }
                // pool: y-pair in-thread, x-pair via shfl_down 4 (R10 pattern)
                float ym[4], nb[4];
                #pragma unroll
                for (int r = 0; r < 4; ++r)
                    ym[r] = fmaxf(accA[r], accB[r]);
                #pragma unroll
                for (int r = 0; r < 4; ++r)
                    nb[r] = __shfl_down_sync(0xffffffffu, ym[r], 4);
                if ((g & 1) == 0) {
                    const int Y   = warp*4 + yb;            // pooled row 0..31
                    const int XpL = xq*8 + (g >> 1);        // from c[0],c[1]
                    const int XpH = XpL + 4;                // from c[2],c[3]
                    float v0L = tf32f(fmaxf(fmaxf(ym[0], nb[0]) + bias01[0], 0.f));
                    float v1L = tf32f(fmaxf(fmaxf(ym[1], nb[1]) + bias01[1], 0.f));
                    float v0H = tf32f(fmaxf(fmaxf(ym[2], nb[2]) + bias01[0], 0.f));
                    float v1H = tf32f(fmaxf(fmaxf(ym[3], nb[3]) + bias01[1], 0.f));
                    int pixL = (2 + Y)*36 + 2 + XpL;
                    int pixH = (2 + Y)*36 + 2 + XpH;
                    *(float2*)&planes[pixL*12 + 2*tig] = make_float2(v0L, v1L);
                    *(float2*)&planes[pixH*12 + 2*tig] = make_float2(v0H, v1H);
                }
            }
        }
    }
    __syncthreads();

    // ---- phase 3a: stage conv1 weights [tap][ch][o], tf32-rounded ----
    for (int i = t; i < 3200; i += 256) {
        int o = i & 15, j = i >> 4;          // j = c*25 + tap
        int c = j / 25, tap = j - c*25;
        sw1[tap*136 + c*17 + o] = tf32f(__ldg(&cw1p[o*200 + j]));
    }
    __syncthreads();

    // ---- phase 3b: conv1 as per-tap K=8 mma over channels, A via ldmatrix ----
    const unsigned planes_s = (unsigned)__cvta_generic_to_shared(planes);
    const int rowl = (lane & 7) + ((lane >> 3) & 1) * 8;
    const unsigned lane_off = (unsigned)(rowl*48 + (lane >> 4)*16);

    float acc[8][2][4];
    #pragma unroll
    for (int mi = 0; mi < 8; ++mi)
        #pragma unroll
        for (int ni = 0; ni < 2; ++ni)
            #pragma unroll
            for (int r = 0; r < 4; ++r) acc[mi][ni][r] = 0.f;

    unsigned addr_mi[8];
    #pragma unroll
    for (int mi = 0; mi < 8; ++mi) {
        int mt = warp*8 + mi;
        int pix0 = (mt >> 1)*36 + (mt & 1)*16;
        addr_mi[mi] = planes_s + (unsigned)(pix0*48) + lane_off;
    }

    #pragma unroll
    for (int ky = 0; ky < 5; ++ky) {
        #pragma unroll
        for (int kx = 0; kx < 5; ++kx) {
            const float* wt = sw1 + (ky*5 + kx)*136;
            const unsigned tapoff = (unsigned)((ky*36 + kx)*48);
            unsigned b00 = __float_as_uint(wt[tig*17 + g]);
            unsigned b01 = __float_as_uint(wt[(tig+4)*17 + g]);
            unsigned b10 = __float_as_uint(wt[tig*17 + 8 + g]);
            unsigned b11 = __float_as_uint(wt[(tig+4)*17 + 8 + g]);
            #pragma unroll
            for (int mi = 0; mi < 8; ++mi) {
                unsigned a0, a1, a2, a3;
                ldsm_x4(a0, a1, a2, a3, addr_mi[mi] + tapoff);
                mma_tf32(acc[mi][0], a0, a1, a2, a3, b00, b01);
                mma_tf32(acc[mi][1], a0, a1, a2, a3, b10, b11);
            }
        }
    }

    // ---- phase 3c: warp-shuffle pooling, direct global write (R10 proven) ----
    {
        float* hout = g_scratch + OFF_H + simi*4096 + (long)bk * 12288;
        #pragma unroll
        for (int h = 0; h < 2; ++h)
            #pragma unroll
            for (int xh = 0; xh < 2; ++xh) {
                const int miA = 4*h + xh, miB = miA + 2;
                #pragma unroll
                for (int ni = 0; ni < 2; ++ni) {
                    float ym[4], nb[4];
                    #pragma unroll
                    for (int r = 0; r < 4; ++r)
                        ym[r] = fmaxf(acc[miA][ni][r], acc[miB][ni][r]);
                    #pragma unroll
                    for (int r = 0; r < 4; ++r)
                        nb[r] = __shfl_down_sync(0xffffffffu, ym[r], 4);
                    if ((g & 1) == 0) {
                        const int Y   = 2*warp + h;
                        const int XpL = 8*xh + (g >> 1);
                        const int XpH = XpL + 4;
                        #pragma unroll
                        for (int cc = 0; cc < 2; ++cc) {
                            const int o = ni*8 + 2*tig + cc;
                            const float b = __ldg(&cb1p[o]);
                            float vL = fmaxf(fmaxf(ym[cc],   nb[cc])   + b, 0.f);
                            float vH = fmaxf(fmaxf(ym[2+cc], nb[2+cc]) + b, 0.f);
                            hout[o*256 + Y*16 + XpL] = tf32f(vL);
                            hout[o*256 + Y*16 + XpH] = tf32f(vH);
                        }
                    }
                }
            }
    }
}

// ---------------------------------------------------------------------------
// MLP layer 0: y1 += h @ Wl0. tf32 mma, cp.async double-buffered (proven).
// ---------------------------------------------------------------------------
#define G1_KC 768
#define G1_KT 32
#define G1_NT 24
#define AS_STRIDE 36
#define BS_STRIDE 72
#define AS_SZ (128*AS_STRIDE)
#define BS_SZ (32*BS_STRIDE)

__global__ void __launch_bounds__(256) gemm1_kernel()
{
    extern __shared__ __align__(16) float gbuf[];
    const float* A = g_scratch + OFF_H;
    const float* B = g_scratch + OFF_WT0;
    float* C = g_scratch + OFF_Y1;

    const int r0 = blockIdx.x * 128;
    const int c0 = blockIdx.y * 64;
    const int k0 = blockIdx.z * G1_KC;

    const int t = threadIdx.x, warp = t >> 5, lane = t & 31;
    const int g = lane >> 2, tig = lane & 3;
    const int wm = warp & 3, wn = warp >> 2;

    float acc[2][4][4];
    #pragma unroll
    for (int mi = 0; mi < 2; ++mi)
        #pragma unroll
        for (int ni = 0; ni < 4; ++ni)
            #pragma unroll
            for (int r = 0; r < 4; ++r) acc[mi][ni][r] = 0.f;

    auto issue = [&](int ibuf, int kt) {
        float* As = gbuf + ibuf*AS_SZ;
        float* Bs = gbuf + 2*AS_SZ + ibuf*BS_SZ;
        #pragma unroll
        for (int j = 0; j < 4; ++j) {
            int cid = t + 256*j;
            int row = cid >> 3, seg = cid & 7;
            cp_async16(&As[row*AS_STRIDE + seg*4],
                       A + (long)(r0 + row)*12288 + k0 + kt + seg*4);
        }
        #pragma unroll
        for (int j = 0; j < 2; ++j) {
            int cid = t + 256*j;
            int k = cid >> 4, seg = cid & 15;
            cp_async16(&Bs[k*BS_STRIDE + seg*4],
                       B + (long)(k0 + kt + k)*256 + c0 + seg*4);
        }
        asm volatile("cp.async.commit_group;");
    };

    issue(0, 0);
    issue(1, G1_KT);

    for (int i = 0; i < G1_NT; ++i) {
        if (i < G1_NT - 1) asm volatile("cp.async.wait_group 1;");
        else               asm volatile("cp.async.wait_group 0;");
        __syncthreads();

        const float* As = gbuf + (i & 1)*AS_SZ;
        const float* Bs = gbuf + 2*AS_SZ + (i & 1)*BS_SZ;
        #pragma unroll
        for (int kc = 0; kc < 4; ++kc) {
            unsigned af[2][4], bf[4][2];
            #pragma unroll
            for (int mi = 0; mi < 2; ++mi) {
                const float* ap = As + (wm*32 + mi*16 + g)*AS_STRIDE + kc*8 + tig;
                af[mi][0] = __float_as_uint(ap[0]);
                af[mi][1] = __float_as_uint(ap[8*AS_STRIDE]);
                af[mi][2] = __float_as_uint(ap[4]);
                af[mi][3] = __float_as_uint(ap[8*AS_STRIDE + 4]);
            }
            #pragma unroll
            for (int ni = 0; ni < 4; ++ni) {
                const float* bp = Bs + (kc*8 + tig)*BS_STRIDE + wn*32 + ni*8 + g;
                bf[ni][0] = __float_as_uint(bp[0]);
                bf[ni][1] = __float_as_uint(bp[4*BS_STRIDE]);
            }
            #pragma unroll
            for (int mi = 0; mi < 2; ++mi)
                #pragma unroll
                for (int ni = 0; ni < 4; ++ni)
                    mma_tf32(acc[mi][ni], af[mi][0], af[mi][1], af[mi][2], af[mi][3],
                             bf[ni][0], bf[ni][1]);
        }
        __syncthreads();
        if (i + 2 < G1_NT) issue(i & 1, (i + 2)*G1_KT);
    }

    #pragma unroll
    for (int mi = 0; mi < 2; ++mi) {
        int R = r0 + wm*32 + mi*16 + g;
        #pragma unroll
        for (int ni = 0; ni < 4; ++ni) {
            int Cc = c0 + wn*32 + ni*8 + 2*tig;
            atomicAdd(&C[R*256 + Cc],         acc[mi][ni][0]);
            atomicAdd(&C[R*256 + Cc + 1],     acc[mi][ni][1]);
            atomicAdd(&C[(R+8)*256 + Cc],     acc[mi][ni][2]);
            atomicAdd(&C[(R+8)*256 + Cc + 1], acc[mi][ni][3]);
        }
    }
}

// ---------------------------------------------------------------------------
// Head: split-K (4 slices of 64), 256 threads/block, one block per row.
// (R8-proven version: 15.4us)
// ---------------------------------------------------------------------------
__global__ void __launch_bounds__(256) head_kernel(
    const float* __restrict__ Wl1, const float* __restrict__ bl1,
    const float* __restrict__ Wsc, const float* __restrict__ bsc,
    float* __restrict__ out)
{
    const int r = blockIdx.x;
    const int t = threadIdx.x;
    __shared__ float sy[256];
    __shared__ float part[4][64];
    __shared__ float red[2];

    sy[t] = fmaxf(g_scratch[OFF_Y1 + (long)r*256 + t], 0.f);
    __syncthreads();

    const int j = t & 63, ks = t >> 6;
    float acc = 0.f;
    #pragma unroll 16
    for (int k = 64*ks; k < 64*ks + 64; ++k)
        acc += sy[k] * __ldg(&Wl1[k*64 + j]);
    part[ks][j] = acc;
    __syncthreads();

    if (t < 64) {
        float a = part[0][t] + part[1][t] + part[2][t] + part[3][t] + __ldg(&bl1[t]);
        float v = fmaxf(a, 0.f) * __ldg(&Wsc[t]);
        #pragma unroll
        for (int off = 16; off > 0; off >>= 1)
            v += __shfl_down_sync(0xffffffffu, v, off);
        if ((t & 31) == 0) red[t >> 5] = v;
    }
    __syncthreads();
    if (t == 0) {
        float s = red[0] + red[1] + __ldg(&bsc[0]);
        out[r] = 1.f / (1.f + expf(-s));
    }
}

// ---------------------------------------------------------------------------
// Launch
// ---------------------------------------------------------------------------
#define PAIR_SMEM (20176*4)
#define G1_SMEM ((2*AS_SZ + 2*BS_SZ)*4)

extern "C" void kernel_launch(void* const* d_in, const int* in_sizes, int n_in,
                              void* d_out, int out_size)
{
    (void)in_sizes; (void)n_in; (void)out_size;
    const float* x_q  = (const float*)d_in[0];
    const float* x_c  = (const float*)d_in[1];
    const int*   src_q = (const int*)d_in[2];
    const int*   dst_q = (const int*)d_in[3];
    const int*   src_c = (const int*)d_in[4];
    const int*   dst_c = (const int*)d_in[5];
    const float* Wg0 = (const float*)d_in[6];
    const float* bg0 = (const float*)d_in[7];
    const float* Wg1 = (const float*)d_in[8];
    const float* bg1 = (const float*)d_in[9];
    const float* Wg2 = (const float*)d_in[10];
    const float* bg2 = (const float*)d_in[11];
    const float* cw0 = (const float*)d_in[12];
    const float* cb0 = (const float*)d_in[13];
    const float* cw1 = (const float*)d_in[14];
    const float* cb1 = (const float*)d_in[15];
    const float* Wl0 = (const float*)d_in[16];
    const float* bl0 = (const float*)d_in[17];
    const float* Wl1 = (const float*)d_in[18];
    const float* bl1 = (const float*)d_in[19];
    const float* Wsc = (const float*)d_in[20];
    const float* bsc = (const float*)d_in[21];
    float* out = (float*)d_out;

    static int attr_done = 0;
    if (!attr_done) {
        cudaFuncSetAttribute(pair_all,  cudaFuncAttributeMaxDynamicSharedMemorySize, PAIR_SMEM);
        cudaFuncSetAttribute(gemm1_kernel, cudaFuncAttributeMaxDynamicSharedMemorySize, G1_SMEM);
        attr_done = 1;
    }

    // fused: 3-layer GCN (1024 blocks) + y1 bias init (512) + Wl0 tf32 (3072)
    prep_all<<<2*NB_GRAPHS + 512 + 3072, 256>>>(
        x_q, x_c, Wg0, bg0, Wg1, bg1, Wg2, bg2,
        src_q, dst_q, src_c, dst_c, bl0, Wl0);

    // fused sim + conv stacks (all 3 sims)
    pair_all<<<3*NB_GRAPHS, 256, PAIR_SMEM>>>(cw0, cb0, cw1, cb1);

    // MLP layer 0 on tensor cores, then head
    gemm1_kernel<<<dim3(4, 4, 16), 256, G1_SMEM>>>();
    head_kernel<<<512, 256>>>(Wl1, bl1, Wsc, bsc, out);
}